// round 4
// baseline (speedup 1.0000x reference)
#include <cuda_runtime.h>
#include <cuda_bf16.h>

// Problem constants
#define NHEAD 16
#define DQ    1024
#define DKEY  64
#define BATCH 4
#define SEQ   2048
#define MROWS (BATCH * SEQ)          // 8192
#define OUT_ELEMS  (8192L * 1024L)           // 8,388,608
#define ATTN_ELEMS (64L * 2048L * 2048L)     // 268,435,456

// ---------------- scratch ---------------------------------------------------
__device__ float g_qh[MROWS * DQ];     // [B,H,S,64]  (z-major: z = b*16+h)
__device__ float g_kh[MROWS * DQ];
__device__ float g_vh[MROWS * DQ];
__device__ float g_ctx[MROWS * DQ];    // [B,S,H*64]
__device__ float g_fc[MROWS * DQ];
__device__ float g_rowm[64 * SEQ];     // per-row softmax max
__device__ float g_rowl[64 * SEQ];     // per-row 1/sum
__device__ float g_attn_fb[ATTN_ELEMS];

// ---------------- tf32 helpers ---------------------------------------------
__device__ __forceinline__ unsigned f2tf32(float x) {
    unsigned r;
    asm("cvt.rna.tf32.f32 %0, %1;" : "=r"(r) : "f"(x));
    return r;
}

__device__ __forceinline__ void mma_tf32(float c[4],
                                         unsigned a0, unsigned a1, unsigned a2, unsigned a3,
                                         unsigned b0, unsigned b1) {
    asm volatile(
        "mma.sync.aligned.m16n8k8.row.col.f32.tf32.tf32.f32 "
        "{%0,%1,%2,%3}, {%4,%5,%6,%7}, {%8,%9}, {%0,%1,%2,%3};"
        : "+f"(c[0]), "+f"(c[1]), "+f"(c[2]), "+f"(c[3])
        : "r"(a0), "r"(a1), "r"(a2), "r"(a3), "r"(b0), "r"(b1));
}

#define TSTR 68     // smem stride for 64-wide tf32 tiles (conflict-free frags)
#define PSTR 132    // smem stride for 128-wide P tile

// cooperative load of a 128x64 fp32 tile -> tf32 smem tile (stride TSTR)
__device__ __forceinline__ void load_tile64(unsigned* dst, const float* src, int tid)
{
    const int lr = tid >> 4;          // 0..15
    const int lc = (tid & 15) * 4;    // 0..60
#pragma unroll
    for (int i = 0; i < 8; i++) {
        const int r = lr + i * 16;
        float4 v = *(const float4*)(src + (long)r * 64 + lc);
        uint4 u;
        u.x = f2tf32(v.x); u.y = f2tf32(v.y);
        u.z = f2tf32(v.z); u.w = f2tf32(v.w);
        *(uint4*)&dst[r * TSTR + lc] = u;
    }
}

// ---------------- pass 1: row stats (max, 1/sumexp) of softmax(QK^T*scale) --
__global__ __launch_bounds__(256)
void attn_stats(const float* __restrict__ qh, const float* __restrict__ kh)
{
    extern __shared__ unsigned smem[];
    unsigned* Qs = smem;                  // [128][TSTR]
    unsigned* Ks = smem + 128 * TSTR;     // [128][TSTR]

    const int z  = blockIdx.y;
    const int qb = blockIdx.x * 128;
    const float* Qz = qh + (long)z * SEQ * 64 + (long)qb * 64;
    const float* Kz = kh + (long)z * SEQ * 64;

    const int tid  = threadIdx.x;
    const int warp = tid >> 5, lane = tid & 31;
    const int wm = warp * 16;
    const int g = lane >> 2, t = lane & 3;

    load_tile64(Qs, Qz, tid);

    float m0 = -1e30f, m1 = -1e30f, l0 = 0.f, l1 = 0.f;
    const float scale = 0.125f;

    for (int k0 = 0; k0 < SEQ; k0 += 128) {
        __syncthreads();
        load_tile64(Ks, Kz + (long)k0 * 64, tid);
        __syncthreads();

        float sacc[16][4];
#pragma unroll
        for (int j = 0; j < 16; j++)
#pragma unroll
            for (int r = 0; r < 4; r++) sacc[j][r] = 0.f;

#pragma unroll
        for (int kk = 0; kk < 64; kk += 8) {
            unsigned a0 = Qs[(wm + g) * TSTR + kk + t];
            unsigned a1 = Qs[(wm + g + 8) * TSTR + kk + t];
            unsigned a2 = Qs[(wm + g) * TSTR + kk + t + 4];
            unsigned a3 = Qs[(wm + g + 8) * TSTR + kk + t + 4];
#pragma unroll
            for (int j = 0; j < 16; j++) {
                unsigned b0 = Ks[(j * 8 + g) * TSTR + kk + t];
                unsigned b1 = Ks[(j * 8 + g) * TSTR + kk + t + 4];
                mma_tf32(sacc[j], a0, a1, a2, a3, b0, b1);
            }
        }

        // row-wise max over this 128-col tile
        float t0 = -1e30f, t1 = -1e30f;
#pragma unroll
        for (int j = 0; j < 16; j++) {
            t0 = fmaxf(t0, fmaxf(sacc[j][0], sacc[j][1]));
            t1 = fmaxf(t1, fmaxf(sacc[j][2], sacc[j][3]));
        }
        t0 *= scale; t1 *= scale;
        t0 = fmaxf(t0, __shfl_xor_sync(0xffffffffu, t0, 1));
        t0 = fmaxf(t0, __shfl_xor_sync(0xffffffffu, t0, 2));
        t1 = fmaxf(t1, __shfl_xor_sync(0xffffffffu, t1, 1));
        t1 = fmaxf(t1, __shfl_xor_sync(0xffffffffu, t1, 2));

        float m0n = fmaxf(m0, t0), m1n = fmaxf(m1, t1);
        float s0 = 0.f, s1 = 0.f;
#pragma unroll
        for (int j = 0; j < 16; j++) {
            s0 += __expf(sacc[j][0] * scale - m0n) + __expf(sacc[j][1] * scale - m0n);
            s1 += __expf(sacc[j][2] * scale - m1n) + __expf(sacc[j][3] * scale - m1n);
        }
        s0 += __shfl_xor_sync(0xffffffffu, s0, 1);
        s0 += __shfl_xor_sync(0xffffffffu, s0, 2);
        s1 += __shfl_xor_sync(0xffffffffu, s1, 1);
        s1 += __shfl_xor_sync(0xffffffffu, s1, 2);

        l0 = l0 * __expf(m0 - m0n) + s0;
        l1 = l1 * __expf(m1 - m1n) + s1;
        m0 = m0n; m1 = m1n;
    }

    if (t == 0) {
        const long base = (long)z * SEQ + qb + wm;
        g_rowm[base + g]     = m0;
        g_rowm[base + g + 8] = m1;
        g_rowl[base + g]     = 1.0f / l0;
        g_rowl[base + g + 8] = 1.0f / l1;
    }
}

// ---------------- pass 2: fused P write + P·V ------------------------------
__global__ __launch_bounds__(256)
void attn_fused(const float* __restrict__ qh, const float* __restrict__ kh,
                const float* __restrict__ vh, float* __restrict__ attn,
                float* __restrict__ ctx)
{
    extern __shared__ unsigned smem[];
    unsigned* Qs = smem;                       // [128][TSTR]
    unsigned* Ks = smem + 128 * TSTR;          // [128][TSTR]
    unsigned* Vs = smem + 2 * 128 * TSTR;      // [128][TSTR]  layout [k][d]
    unsigned* Ps = smem + 3 * 128 * TSTR;      // [128][PSTR]

    const int z  = blockIdx.y;
    const int b  = z >> 4, h = z & 15;
    const int qb = blockIdx.x * 128;
    const float* Qz = qh + (long)z * SEQ * 64 + (long)qb * 64;
    const float* Kz = kh + (long)z * SEQ * 64;
    const float* Vz = vh + (long)z * SEQ * 64;
    float* attnZ = attn + (long)z * SEQ * SEQ;

    const int tid  = threadIdx.x;
    const int warp = tid >> 5, lane = tid & 31;
    const int wm = warp * 16;
    const int g = lane >> 2, t = lane & 3;
    const int row0 = qb + wm + g, row1 = row0 + 8;

    load_tile64(Qs, Qz, tid);

    const long sbase = (long)z * SEQ;
    const float m0  = g_rowm[sbase + row0];
    const float m1  = g_rowm[sbase + row1];
    const float iv0 = g_rowl[sbase + row0];
    const float iv1 = g_rowl[sbase + row1];
    const float scale = 0.125f;

    float oacc[8][4];
#pragma unroll
    for (int j = 0; j < 8; j++)
#pragma unroll
        for (int r = 0; r < 4; r++) oacc[j][r] = 0.f;

    for (int k0 = 0; k0 < SEQ; k0 += 128) {
        __syncthreads();
        load_tile64(Ks, Kz + (long)k0 * 64, tid);
        load_tile64(Vs, Vz + (long)k0 * 64, tid);
        __syncthreads();

        // ---- S = Q K^T for this 128x128 tile ----
        float sacc[16][4];
#pragma unroll
        for (int j = 0; j < 16; j++)
#pragma unroll
            for (int r = 0; r < 4; r++) sacc[j][r] = 0.f;

#pragma unroll
        for (int kk = 0; kk < 64; kk += 8) {
            unsigned a0 = Qs[(wm + g) * TSTR + kk + t];
            unsigned a1 = Qs[(wm + g + 8) * TSTR + kk + t];
            unsigned a2 = Qs[(wm + g) * TSTR + kk + t + 4];
            unsigned a3 = Qs[(wm + g + 8) * TSTR + kk + t + 4];
#pragma unroll
            for (int j = 0; j < 16; j++) {
                unsigned b0 = Ks[(j * 8 + g) * TSTR + kk + t];
                unsigned b1 = Ks[(j * 8 + g) * TSTR + kk + t + 4];
                mma_tf32(sacc[j], a0, a1, a2, a3, b0, b1);
            }
        }

        // ---- p = exp(s*scale - m) * inv_l; write attn + stash tf32 in smem --
#pragma unroll
        for (int j = 0; j < 16; j++) {
            float p0 = __expf(sacc[j][0] * scale - m0) * iv0;
            float p1 = __expf(sacc[j][1] * scale - m0) * iv0;
            float p2 = __expf(sacc[j][2] * scale - m1) * iv1;
            float p3 = __expf(sacc[j][3] * scale - m1) * iv1;
            const int c = j * 8 + 2 * t;
            float2 lo; lo.x = p0; lo.y = p1;
            float2 hi; hi.x = p2; hi.y = p3;
            *(float2*)(attnZ + (long)row0 * SEQ + k0 + c) = lo;
            *(float2*)(attnZ + (long)row1 * SEQ + k0 + c) = hi;
            uint2 ulo; ulo.x = f2tf32(p0); ulo.y = f2tf32(p1);
            uint2 uhi; uhi.x = f2tf32(p2); uhi.y = f2tf32(p3);
            *(uint2*)&Ps[(wm + g) * PSTR + c]     = ulo;
            *(uint2*)&Ps[(wm + g + 8) * PSTR + c] = uhi;
        }
        __syncwarp();   // P rows are warp-private; order smem writes vs reads

        // ---- O += P · V (contraction over the 128 cols of this tile) ----
#pragma unroll
        for (int kk = 0; kk < 128; kk += 8) {
            unsigned a0 = Ps[(wm + g) * PSTR + kk + t];
            unsigned a1 = Ps[(wm + g + 8) * PSTR + kk + t];
            unsigned a2 = Ps[(wm + g) * PSTR + kk + t + 4];
            unsigned a3 = Ps[(wm + g + 8) * PSTR + kk + t + 4];
#pragma unroll
            for (int j = 0; j < 8; j++) {
                unsigned b0 = Vs[(kk + t) * TSTR + j * 8 + g];
                unsigned b1 = Vs[(kk + t + 4) * TSTR + j * 8 + g];
                mma_tf32(oacc[j], a0, a1, a2, a3, b0, b1);
            }
        }
    }

    // ---- write O to ctx[b, s, h*64+d] ----
#pragma unroll
    for (int j = 0; j < 8; j++) {
        const int d = j * 8 + 2 * t;
        float2 lo; lo.x = oacc[j][0]; lo.y = oacc[j][1];
        float2 hi; hi.x = oacc[j][2]; hi.y = oacc[j][3];
        *(float2*)(ctx + ((long)(b * SEQ + row0)) * DQ + h * 64 + d) = lo;
        *(float2*)(ctx + ((long)(b * SEQ + row1)) * DQ + h * 64 + d) = hi;
    }
}

// ---------------- tensor-core GEMM-NT (projections / FC) --------------------
// MODE 0: C row-major [M,N].  MODE 1: projection scatter [B,H,S,64].
template <int MODE>
__global__ __launch_bounds__(256)
void gemm_nt_tc(const float* __restrict__ A, const float* __restrict__ Bm,
                float* __restrict__ C, int M, int N, int K, float alpha)
{
    constexpr int BM = 128, BN = 128, BK = 32;
    __shared__ unsigned As[BM][BK + 4];
    __shared__ unsigned Bs[BN][BK + 4];

    const int bm = blockIdx.y * BM;
    const int bn = blockIdx.x * BN;
    const int tid  = threadIdx.x;
    const int warp = tid >> 5, lane = tid & 31;
    const int wm = (warp >> 2) * 64;
    const int wn = (warp & 3) * 32;
    const int g = lane >> 2, t = lane & 3;

    float acc[4][4][4];
#pragma unroll
    for (int i = 0; i < 4; i++)
#pragma unroll
        for (int j = 0; j < 4; j++)
#pragma unroll
            for (int r = 0; r < 4; r++) acc[i][j][r] = 0.f;

    const int lr = tid >> 3;
    const int lc = (tid & 7) * 4;

    for (int k0 = 0; k0 < K; k0 += BK) {
#pragma unroll
        for (int i = 0; i < 4; i++) {
            float4 va = *(const float4*)(A + (long)(bm + lr + i * 32) * K + k0 + lc);
            uint4 ua;
            ua.x = f2tf32(va.x); ua.y = f2tf32(va.y);
            ua.z = f2tf32(va.z); ua.w = f2tf32(va.w);
            *(uint4*)&As[lr + i * 32][lc] = ua;
            float4 vb = *(const float4*)(Bm + (long)(bn + lr + i * 32) * K + k0 + lc);
            uint4 ub;
            ub.x = f2tf32(vb.x); ub.y = f2tf32(vb.y);
            ub.z = f2tf32(vb.z); ub.w = f2tf32(vb.w);
            *(uint4*)&Bs[lr + i * 32][lc] = ub;
        }
        __syncthreads();

#pragma unroll
        for (int kk = 0; kk < BK; kk += 8) {
            unsigned af[4][4], bf[4][2];
#pragma unroll
            for (int i = 0; i < 4; i++) {
                int r = wm + i * 16;
                af[i][0] = As[r + g][kk + t];
                af[i][1] = As[r + g + 8][kk + t];
                af[i][2] = As[r + g][kk + t + 4];
                af[i][3] = As[r + g + 8][kk + t + 4];
            }
#pragma unroll
            for (int j = 0; j < 4; j++) {
                int c = wn + j * 8;
                bf[j][0] = Bs[c + g][kk + t];
                bf[j][1] = Bs[c + g][kk + t + 4];
            }
#pragma unroll
            for (int i = 0; i < 4; i++)
#pragma unroll
                for (int j = 0; j < 4; j++)
                    mma_tf32(acc[i][j], af[i][0], af[i][1], af[i][2], af[i][3],
                             bf[j][0], bf[j][1]);
        }
        __syncthreads();
    }

#pragma unroll
    for (int i = 0; i < 4; i++) {
#pragma unroll
        for (int j = 0; j < 4; j++) {
            const int mrow = bm + wm + i * 16 + g;
            const int ncol = bn + wn + j * 8 + 2 * t;
            float2 lo, hi;
            lo.x = alpha * acc[i][j][0]; lo.y = alpha * acc[i][j][1];
            hi.x = alpha * acc[i][j][2]; hi.y = alpha * acc[i][j][3];
            if (MODE == 0) {
                *(float2*)(C + (long)mrow * N + ncol)       = lo;
                *(float2*)(C + (long)(mrow + 8) * N + ncol) = hi;
            } else {
                const int h = ncol >> 6, d = ncol & 63;
                int b0 = mrow >> 11, s0 = mrow & 2047;
                *(float2*)(C + ((long)((b0 * NHEAD + h) * SEQ + s0)) * 64 + d) = lo;
                int m2 = mrow + 8;
                int b1 = m2 >> 11, s1 = m2 & 2047;
                *(float2*)(C + ((long)((b1 * NHEAD + h) * SEQ + s1)) * 64 + d) = hi;
            }
        }
    }
}

// ---------------- residual add + LayerNorm ----------------------------------
__global__ __launch_bounds__(256)
void add_ln_kernel(const float* __restrict__ fc, const float* __restrict__ res,
                   const float* __restrict__ gamma, const float* __restrict__ beta,
                   float* __restrict__ out)
{
    const long row = blockIdx.x;
    const int tid = threadIdx.x;
    float4 f = ((const float4*)(fc  + row * DQ))[tid];
    float4 r = ((const float4*)(res + row * DQ))[tid];
    float x0 = f.x + r.x, x1 = f.y + r.y, x2 = f.z + r.z, x3 = f.w + r.w;

    float s  = x0 + x1 + x2 + x3;
    float sq = x0 * x0 + x1 * x1 + x2 * x2 + x3 * x3;
#pragma unroll
    for (int off = 16; off > 0; off >>= 1) {
        s  += __shfl_xor_sync(0xffffffffu, s,  off);
        sq += __shfl_xor_sync(0xffffffffu, sq, off);
    }
    __shared__ float rs[8], rq[8];
    const int wid = tid >> 5, lane = tid & 31;
    if (lane == 0) { rs[wid] = s; rq[wid] = sq; }
    __syncthreads();
    float S = 0.f, SQ = 0.f;
#pragma unroll
    for (int w = 0; w < 8; w++) { S += rs[w]; SQ += rq[w]; }

    const float mu  = S * (1.0f / DQ);
    const float var = SQ * (1.0f / DQ) - mu * mu;
    const float rstd = rsqrtf(var + 1e-6f);

    float4 g  = ((const float4*)gamma)[tid];
    float4 be = ((const float4*)beta)[tid];
    float4 o;
    o.x = (x0 - mu) * rstd * g.x + be.x;
    o.y = (x1 - mu) * rstd * g.y + be.y;
    o.z = (x2 - mu) * rstd * g.z + be.z;
    o.w = (x3 - mu) * rstd * g.w + be.w;
    ((float4*)(out + row * DQ))[tid] = o;
}

// ---------------- launcher --------------------------------------------------
extern "C" void kernel_launch(void* const* d_in, const int* in_sizes, int n_in,
                              void* d_out, int out_size)
{
    const float* q    = (const float*)d_in[0];
    const float* k    = (const float*)d_in[1];
    const float* v    = (const float*)d_in[2];
    const float* w_q  = (const float*)d_in[3];
    const float* w_k  = (const float*)d_in[4];
    const float* w_v  = (const float*)d_in[5];
    const float* w_fc = (const float*)d_in[6];
    const float* ga   = (const float*)d_in[7];
    const float* be   = (const float*)d_in[8];
    float* out = (float*)d_out;

    float *qh, *kh, *vh, *ctx, *fc, *attn_fb;
    cudaGetSymbolAddress((void**)&qh,      g_qh);
    cudaGetSymbolAddress((void**)&kh,      g_kh);
    cudaGetSymbolAddress((void**)&vh,      g_vh);
    cudaGetSymbolAddress((void**)&ctx,     g_ctx);
    cudaGetSymbolAddress((void**)&fc,      g_fc);
    cudaGetSymbolAddress((void**)&attn_fb, g_attn_fb);

    float* attn;
    bool write_out = true;
    if ((long)out_size >= OUT_ELEMS + ATTN_ELEMS) {
        attn = out + OUT_ELEMS;
    } else if ((long)out_size == ATTN_ELEMS) {
        attn = out;
        write_out = false;
    } else {
        attn = attn_fb;
    }

    const int STATS_SMEM = 2 * 128 * TSTR * 4;                 // 69,632 B
    const int FUSED_SMEM = (3 * 128 * TSTR + 128 * PSTR) * 4;  // 172,032 B
    static bool attr_done = false;
    if (!attr_done) {
        cudaFuncSetAttribute(attn_stats, cudaFuncAttributeMaxDynamicSharedMemorySize, STATS_SMEM);
        cudaFuncSetAttribute(attn_fused, cudaFuncAttributeMaxDynamicSharedMemorySize, FUSED_SMEM);
        attr_done = true;
    }

    // projections: M=8192, N=1024, K=1024 -> head-major layout [z][s][64]
    gemm_nt_tc<1><<<dim3(8, 64, 1), 256>>>(q, w_q, qh, MROWS, DQ, DQ, 1.0f);
    gemm_nt_tc<1><<<dim3(8, 64, 1), 256>>>(k, w_k, kh, MROWS, DQ, DQ, 1.0f);
    gemm_nt_tc<1><<<dim3(8, 64, 1), 256>>>(v, w_v, vh, MROWS, DQ, DQ, 1.0f);

    // pass 1: softmax row stats (no S materialization)
    attn_stats<<<dim3(16, 64), 256, STATS_SMEM>>>(qh, kh);

    // pass 2: recompute S, write normalized P once, fused P·V
    attn_fused<<<dim3(16, 64), 256, FUSED_SMEM>>>(qh, kh, vh, attn, ctx);

    if (write_out) {
        gemm_nt_tc<0><<<dim3(8, 64, 1), 256>>>(ctx, w_fc, fc, MROWS, DQ, DQ, 1.0f);
        add_ln_kernel<<<MROWS, 256>>>(fc, q, ga, be, out);
    }
}

// round 5
// speedup vs baseline: 1.0988x; 1.0988x over previous
#include <cuda_runtime.h>
#include <cuda_bf16.h>

// Problem constants
#define NHEAD 16
#define DQ    1024
#define DKEY  64
#define BATCH 4
#define SEQ   2048
#define MROWS (BATCH * SEQ)          // 8192
#define OUT_ELEMS  (8192L * 1024L)           // 8,388,608
#define ATTN_ELEMS (64L * 2048L * 2048L)     // 268,435,456

// ---------------- scratch ---------------------------------------------------
__device__ float g_qh[MROWS * DQ];     // [B,H,S,64]  (z-major: z = b*16+h)
__device__ float g_kh[MROWS * DQ];
__device__ float g_vh[MROWS * DQ];
__device__ float g_ctx[MROWS * DQ];    // [B,S,H*64]
__device__ float g_fc[MROWS * DQ];
__device__ float g_rowm[64 * SEQ];     // per-row softmax max
__device__ float g_rowl[64 * SEQ];     // per-row 1/sum
__device__ float g_attn_fb[ATTN_ELEMS];

// ---------------- tf32 helpers ---------------------------------------------
__device__ __forceinline__ unsigned f2tf32(float x) {
    unsigned r;
    asm("cvt.rna.tf32.f32 %0, %1;" : "=r"(r) : "f"(x));
    return r;
}

__device__ __forceinline__ void mma_tf32(float c[4],
                                         unsigned a0, unsigned a1, unsigned a2, unsigned a3,
                                         unsigned b0, unsigned b1) {
    asm volatile(
        "mma.sync.aligned.m16n8k8.row.col.f32.tf32.tf32.f32 "
        "{%0,%1,%2,%3}, {%4,%5,%6,%7}, {%8,%9}, {%0,%1,%2,%3};"
        : "+f"(c[0]), "+f"(c[1]), "+f"(c[2]), "+f"(c[3])
        : "r"(a0), "r"(a1), "r"(a2), "r"(a3), "r"(b0), "r"(b1));
}

#define TSTR 68     // smem stride for 64-wide tf32 tiles (conflict-free frags)

// cooperative load of a 128x64 fp32 tile -> tf32 smem tile (stride TSTR)
__device__ __forceinline__ void load_tile64(unsigned* dst, const float* src, int tid)
{
    const int lr = tid >> 4;          // 0..15
    const int lc = (tid & 15) * 4;    // 0..60
#pragma unroll
    for (int i = 0; i < 8; i++) {
        const int r = lr + i * 16;
        float4 v = *(const float4*)(src + (long)r * 64 + lc);
        uint4 u;
        u.x = f2tf32(v.x); u.y = f2tf32(v.y);
        u.z = f2tf32(v.z); u.w = f2tf32(v.w);
        *(uint4*)&dst[r * TSTR + lc] = u;
    }
}

// V tile loader: [k][d] with XOR swizzle on d (conflict-free stores AND PV reads)
__device__ __forceinline__ void load_vtile(unsigned* dst, const float* src, int tid)
{
    const int lr = tid >> 4;
    const int lc = (tid & 15) * 4;
#pragma unroll
    for (int i = 0; i < 8; i++) {
        const int r = lr + i * 16;
        float4 v = *(const float4*)(src + (long)r * 64 + lc);
        uint4 u;
        u.x = f2tf32(v.x); u.y = f2tf32(v.y);
        u.z = f2tf32(v.z); u.w = f2tf32(v.w);
        *(uint4*)&dst[r * 64 + (lc ^ ((r & 7) * 8))] = u;
    }
}

// ---------------- pass 1: row stats (max, 1/sumexp) of softmax(QK^T*scale) --
__global__ __launch_bounds__(256)
void attn_stats(const float* __restrict__ qh, const float* __restrict__ kh)
{
    extern __shared__ unsigned smem[];
    unsigned* Qs = smem;                  // [128][TSTR]
    unsigned* Ks = smem + 128 * TSTR;     // [128][TSTR]

    const int z  = blockIdx.y;
    const int qb = blockIdx.x * 128;
    const float* Qz = qh + (long)z * SEQ * 64 + (long)qb * 64;
    const float* Kz = kh + (long)z * SEQ * 64;

    const int tid  = threadIdx.x;
    const int warp = tid >> 5, lane = tid & 31;
    const int wm = warp * 16;
    const int g = lane >> 2, t = lane & 3;

    load_tile64(Qs, Qz, tid);

    float m0 = -1e30f, m1 = -1e30f, l0 = 0.f, l1 = 0.f;
    const float scale = 0.125f;

    for (int k0 = 0; k0 < SEQ; k0 += 128) {
        __syncthreads();
        load_tile64(Ks, Kz + (long)k0 * 64, tid);
        __syncthreads();

        float sacc[16][4];
#pragma unroll
        for (int j = 0; j < 16; j++)
#pragma unroll
            for (int r = 0; r < 4; r++) sacc[j][r] = 0.f;

#pragma unroll
        for (int kk = 0; kk < 64; kk += 8) {
            unsigned a0 = Qs[(wm + g) * TSTR + kk + t];
            unsigned a1 = Qs[(wm + g + 8) * TSTR + kk + t];
            unsigned a2 = Qs[(wm + g) * TSTR + kk + t + 4];
            unsigned a3 = Qs[(wm + g + 8) * TSTR + kk + t + 4];
#pragma unroll
            for (int j = 0; j < 16; j++) {
                unsigned b0 = Ks[(j * 8 + g) * TSTR + kk + t];
                unsigned b1 = Ks[(j * 8 + g) * TSTR + kk + t + 4];
                mma_tf32(sacc[j], a0, a1, a2, a3, b0, b1);
            }
        }

        float t0 = -1e30f, t1 = -1e30f;
#pragma unroll
        for (int j = 0; j < 16; j++) {
            t0 = fmaxf(t0, fmaxf(sacc[j][0], sacc[j][1]));
            t1 = fmaxf(t1, fmaxf(sacc[j][2], sacc[j][3]));
        }
        t0 *= scale; t1 *= scale;
        t0 = fmaxf(t0, __shfl_xor_sync(0xffffffffu, t0, 1));
        t0 = fmaxf(t0, __shfl_xor_sync(0xffffffffu, t0, 2));
        t1 = fmaxf(t1, __shfl_xor_sync(0xffffffffu, t1, 1));
        t1 = fmaxf(t1, __shfl_xor_sync(0xffffffffu, t1, 2));

        float m0n = fmaxf(m0, t0), m1n = fmaxf(m1, t1);
        float s0 = 0.f, s1 = 0.f;
#pragma unroll
        for (int j = 0; j < 16; j++) {
            s0 += __expf(sacc[j][0] * scale - m0n) + __expf(sacc[j][1] * scale - m0n);
            s1 += __expf(sacc[j][2] * scale - m1n) + __expf(sacc[j][3] * scale - m1n);
        }
        s0 += __shfl_xor_sync(0xffffffffu, s0, 1);
        s0 += __shfl_xor_sync(0xffffffffu, s0, 2);
        s1 += __shfl_xor_sync(0xffffffffu, s1, 1);
        s1 += __shfl_xor_sync(0xffffffffu, s1, 2);

        l0 = l0 * __expf(m0 - m0n) + s0;
        l1 = l1 * __expf(m1 - m1n) + s1;
        m0 = m0n; m1 = m1n;
    }

    if (t == 0) {
        const long base = (long)z * SEQ + qb + wm;
        g_rowm[base + g]     = m0;
        g_rowm[base + g + 8] = m1;
        g_rowl[base + g]     = 1.0f / l0;
        g_rowl[base + g + 8] = 1.0f / l1;
    }
}

// ---------------- pass 2: fused P write + P·V (register-resident P) ---------
__global__ __launch_bounds__(256, 2)
void attn_fused(const float* __restrict__ qh, const float* __restrict__ kh,
                const float* __restrict__ vh, float* __restrict__ attn,
                float* __restrict__ ctx)
{
    extern __shared__ unsigned smem[];
    unsigned* Qs = smem;                       // [128][TSTR]
    unsigned* Ks = smem + 128 * TSTR;          // [128][TSTR]
    unsigned* Vs = smem + 2 * 128 * TSTR;      // [128][64] xor-swizzled

    const int z  = blockIdx.y;
    const int b  = z >> 4, h = z & 15;
    const int qb = blockIdx.x * 128;
    const float* Qz = qh + (long)z * SEQ * 64 + (long)qb * 64;
    const float* Kz = kh + (long)z * SEQ * 64;
    const float* Vz = vh + (long)z * SEQ * 64;
    float* attnZ = attn + (long)z * SEQ * SEQ;

    const int tid  = threadIdx.x;
    const int warp = tid >> 5, lane = tid & 31;
    const int wm = warp * 16;
    const int g = lane >> 2, t = lane & 3;
    const int row0 = qb + wm + g, row1 = row0 + 8;

    load_tile64(Qs, Qz, tid);

    const long sbase = (long)z * SEQ;
    const float m0  = g_rowm[sbase + row0];
    const float m1  = g_rowm[sbase + row1];
    const float iv0 = g_rowl[sbase + row0];
    const float iv1 = g_rowl[sbase + row1];
    const float scale = 0.125f;

    float oacc[8][4];
#pragma unroll
    for (int j = 0; j < 8; j++)
#pragma unroll
        for (int r = 0; r < 4; r++) oacc[j][r] = 0.f;

    const int sl = (lane & ~3) + (t >> 1);   // shfl source: cols {t} of the quad
    const int sh = sl + 2;                   // shfl source: cols {t+4}
    const int x0 = 8 * t;                    // V swizzle for k-row t
    const int x1 = 8 * ((t + 4) & 7);        // V swizzle for k-row t+4

    for (int k0 = 0; k0 < SEQ; k0 += 128) {
        __syncthreads();
        load_tile64(Ks, Kz + (long)k0 * 64, tid);
        load_vtile (Vs, Vz + (long)k0 * 64, tid);
        __syncthreads();

        // ---- S = Q K^T for this 128x128 tile ----
        float sacc[16][4];
#pragma unroll
        for (int j = 0; j < 16; j++)
#pragma unroll
            for (int r = 0; r < 4; r++) sacc[j][r] = 0.f;

#pragma unroll
        for (int kk = 0; kk < 64; kk += 8) {
            unsigned a0 = Qs[(wm + g) * TSTR + kk + t];
            unsigned a1 = Qs[(wm + g + 8) * TSTR + kk + t];
            unsigned a2 = Qs[(wm + g) * TSTR + kk + t + 4];
            unsigned a3 = Qs[(wm + g + 8) * TSTR + kk + t + 4];
#pragma unroll
            for (int j = 0; j < 16; j++) {
                unsigned b0 = Ks[(j * 8 + g) * TSTR + kk + t];
                unsigned b1 = Ks[(j * 8 + g) * TSTR + kk + t + 4];
                mma_tf32(sacc[j], a0, a1, a2, a3, b0, b1);
            }
        }

        // ---- per 16x8 tile: p = exp(s*scale-m)*inv_l; write attn; PV mma ---
#pragma unroll
        for (int j = 0; j < 16; j++) {
            float p0 = __expf(sacc[j][0] * scale - m0) * iv0;
            float p1 = __expf(sacc[j][1] * scale - m0) * iv0;
            float p2 = __expf(sacc[j][2] * scale - m1) * iv1;
            float p3 = __expf(sacc[j][3] * scale - m1) * iv1;

            const int c = j * 8 + 2 * t;
            float2 lo; lo.x = p0; lo.y = p1;
            float2 hi; hi.x = p2; hi.y = p3;
            *(float2*)(attnZ + (long)row0 * SEQ + k0 + c) = lo;
            *(float2*)(attnZ + (long)row1 * SEQ + k0 + c) = hi;

            // C-frag (cols 2t,2t+1) -> A-frag (cols t,t+4) via quad shuffles
            unsigned u0 = f2tf32(p0), u1 = f2tf32(p1);
            unsigned u2 = f2tf32(p2), u3 = f2tf32(p3);
            unsigned e, o, a0, a1, a2, a3;
            e = __shfl_sync(0xffffffffu, u0, sl);
            o = __shfl_sync(0xffffffffu, u1, sl);
            a0 = (t & 1) ? o : e;
            e = __shfl_sync(0xffffffffu, u0, sh);
            o = __shfl_sync(0xffffffffu, u1, sh);
            a2 = (t & 1) ? o : e;
            e = __shfl_sync(0xffffffffu, u2, sl);
            o = __shfl_sync(0xffffffffu, u3, sl);
            a1 = (t & 1) ? o : e;
            e = __shfl_sync(0xffffffffu, u2, sh);
            o = __shfl_sync(0xffffffffu, u3, sh);
            a3 = (t & 1) ? o : e;

            const int kr0 = (j * 8 + t) * 64;
            const int kr1 = (j * 8 + t + 4) * 64;
#pragma unroll
            for (int jd = 0; jd < 8; jd++) {
                unsigned b0 = Vs[kr0 + ((jd * 8 + g) ^ x0)];
                unsigned b1 = Vs[kr1 + ((jd * 8 + g) ^ x1)];
                mma_tf32(oacc[jd], a0, a1, a2, a3, b0, b1);
            }
        }
    }

    // ---- write O to ctx[b, s, h*64+d] ----
#pragma unroll
    for (int j = 0; j < 8; j++) {
        const int d = j * 8 + 2 * t;
        float2 lo; lo.x = oacc[j][0]; lo.y = oacc[j][1];
        float2 hi; hi.x = oacc[j][2]; hi.y = oacc[j][3];
        *(float2*)(ctx + ((long)(b * SEQ + row0)) * DQ + h * 64 + d) = lo;
        *(float2*)(ctx + ((long)(b * SEQ + row1)) * DQ + h * 64 + d) = hi;
    }
}

// ---------------- tensor-core GEMM-NT (projections / FC) --------------------
// MODE 0: C row-major [M,N].  MODE 1: projection scatter [B,H,S,64].
template <int MODE>
__global__ __launch_bounds__(256)
void gemm_nt_tc(const float* __restrict__ A, const float* __restrict__ Bm,
                float* __restrict__ C, int M, int N, int K, float alpha)
{
    constexpr int BM = 128, BN = 128, BK = 32;
    __shared__ unsigned As[BM][BK + 4];
    __shared__ unsigned Bs[BN][BK + 4];

    const int bm = blockIdx.y * BM;
    const int bn = blockIdx.x * BN;
    const int tid  = threadIdx.x;
    const int warp = tid >> 5, lane = tid & 31;
    const int wm = (warp >> 2) * 64;
    const int wn = (warp & 3) * 32;
    const int g = lane >> 2, t = lane & 3;

    float acc[4][4][4];
#pragma unroll
    for (int i = 0; i < 4; i++)
#pragma unroll
        for (int j = 0; j < 4; j++)
#pragma unroll
            for (int r = 0; r < 4; r++) acc[i][j][r] = 0.f;

    const int lr = tid >> 3;
    const int lc = (tid & 7) * 4;

    for (int k0 = 0; k0 < K; k0 += BK) {
#pragma unroll
        for (int i = 0; i < 4; i++) {
            float4 va = *(const float4*)(A + (long)(bm + lr + i * 32) * K + k0 + lc);
            uint4 ua;
            ua.x = f2tf32(va.x); ua.y = f2tf32(va.y);
            ua.z = f2tf32(va.z); ua.w = f2tf32(va.w);
            *(uint4*)&As[lr + i * 32][lc] = ua;
            float4 vb = *(const float4*)(Bm + (long)(bn + lr + i * 32) * K + k0 + lc);
            uint4 ub;
            ub.x = f2tf32(vb.x); ub.y = f2tf32(vb.y);
            ub.z = f2tf32(vb.z); ub.w = f2tf32(vb.w);
            *(uint4*)&Bs[lr + i * 32][lc] = ub;
        }
        __syncthreads();

#pragma unroll
        for (int kk = 0; kk < BK; kk += 8) {
            unsigned af[4][4], bf[4][2];
#pragma unroll
            for (int i = 0; i < 4; i++) {
                int r = wm + i * 16;
                af[i][0] = As[r + g][kk + t];
                af[i][1] = As[r + g + 8][kk + t];
                af[i][2] = As[r + g][kk + t + 4];
                af[i][3] = As[r + g + 8][kk + t + 4];
            }
#pragma unroll
            for (int j = 0; j < 4; j++) {
                int c = wn + j * 8;
                bf[j][0] = Bs[c + g][kk + t];
                bf[j][1] = Bs[c + g][kk + t + 4];
            }
#pragma unroll
            for (int i = 0; i < 4; i++)
#pragma unroll
                for (int j = 0; j < 4; j++)
                    mma_tf32(acc[i][j], af[i][0], af[i][1], af[i][2], af[i][3],
                             bf[j][0], bf[j][1]);
        }
        __syncthreads();
    }

#pragma unroll
    for (int i = 0; i < 4; i++) {
#pragma unroll
        for (int j = 0; j < 4; j++) {
            const int mrow = bm + wm + i * 16 + g;
            const int ncol = bn + wn + j * 8 + 2 * t;
            float2 lo, hi;
            lo.x = alpha * acc[i][j][0]; lo.y = alpha * acc[i][j][1];
            hi.x = alpha * acc[i][j][2]; hi.y = alpha * acc[i][j][3];
            if (MODE == 0) {
                *(float2*)(C + (long)mrow * N + ncol)       = lo;
                *(float2*)(C + (long)(mrow + 8) * N + ncol) = hi;
            } else {
                const int h = ncol >> 6, d = ncol & 63;
                int b0 = mrow >> 11, s0 = mrow & 2047;
                *(float2*)(C + ((long)((b0 * NHEAD + h) * SEQ + s0)) * 64 + d) = lo;
                int m2 = mrow + 8;
                int b1 = m2 >> 11, s1 = m2 & 2047;
                *(float2*)(C + ((long)((b1 * NHEAD + h) * SEQ + s1)) * 64 + d) = hi;
            }
        }
    }
}

// ---------------- residual add + LayerNorm ----------------------------------
__global__ __launch_bounds__(256)
void add_ln_kernel(const float* __restrict__ fc, const float* __restrict__ res,
                   const float* __restrict__ gamma, const float* __restrict__ beta,
                   float* __restrict__ out)
{
    const long row = blockIdx.x;
    const int tid = threadIdx.x;
    float4 f = ((const float4*)(fc  + row * DQ))[tid];
    float4 r = ((const float4*)(res + row * DQ))[tid];
    float x0 = f.x + r.x, x1 = f.y + r.y, x2 = f.z + r.z, x3 = f.w + r.w;

    float s  = x0 + x1 + x2 + x3;
    float sq = x0 * x0 + x1 * x1 + x2 * x2 + x3 * x3;
#pragma unroll
    for (int off = 16; off > 0; off >>= 1) {
        s  += __shfl_xor_sync(0xffffffffu, s,  off);
        sq += __shfl_xor_sync(0xffffffffu, sq, off);
    }
    __shared__ float rs[8], rq[8];
    const int wid = tid >> 5, lane = tid & 31;
    if (lane == 0) { rs[wid] = s; rq[wid] = sq; }
    __syncthreads();
    float S = 0.f, SQ = 0.f;
#pragma unroll
    for (int w = 0; w < 8; w++) { S += rs[w]; SQ += rq[w]; }

    const float mu  = S * (1.0f / DQ);
    const float var = SQ * (1.0f / DQ) - mu * mu;
    const float rstd = rsqrtf(var + 1e-6f);

    float4 g  = ((const float4*)gamma)[tid];
    float4 be = ((const float4*)beta)[tid];
    float4 o;
    o.x = (x0 - mu) * rstd * g.x + be.x;
    o.y = (x1 - mu) * rstd * g.y + be.y;
    o.z = (x2 - mu) * rstd * g.z + be.z;
    o.w = (x3 - mu) * rstd * g.w + be.w;
    ((float4*)(out + row * DQ))[tid] = o;
}

// ---------------- launcher --------------------------------------------------
extern "C" void kernel_launch(void* const* d_in, const int* in_sizes, int n_in,
                              void* d_out, int out_size)
{
    const float* q    = (const float*)d_in[0];
    const float* k    = (const float*)d_in[1];
    const float* v    = (const float*)d_in[2];
    const float* w_q  = (const float*)d_in[3];
    const float* w_k  = (const float*)d_in[4];
    const float* w_v  = (const float*)d_in[5];
    const float* w_fc = (const float*)d_in[6];
    const float* ga   = (const float*)d_in[7];
    const float* be   = (const float*)d_in[8];
    float* out = (float*)d_out;

    float *qh, *kh, *vh, *ctx, *fc, *attn_fb;
    cudaGetSymbolAddress((void**)&qh,      g_qh);
    cudaGetSymbolAddress((void**)&kh,      g_kh);
    cudaGetSymbolAddress((void**)&vh,      g_vh);
    cudaGetSymbolAddress((void**)&ctx,     g_ctx);
    cudaGetSymbolAddress((void**)&fc,      g_fc);
    cudaGetSymbolAddress((void**)&attn_fb, g_attn_fb);

    float* attn;
    bool write_out = true;
    if ((long)out_size >= OUT_ELEMS + ATTN_ELEMS) {
        attn = out + OUT_ELEMS;
    } else if ((long)out_size == ATTN_ELEMS) {
        attn = out;
        write_out = false;
    } else {
        attn = attn_fb;
    }

    const int STATS_SMEM = 2 * 128 * TSTR * 4;                 // 69,632 B
    const int FUSED_SMEM = (2 * 128 * TSTR + 128 * 64) * 4;    // 102,400 B
    static bool attr_done = false;
    if (!attr_done) {
        cudaFuncSetAttribute(attn_stats, cudaFuncAttributeMaxDynamicSharedMemorySize, STATS_SMEM);
        cudaFuncSetAttribute(attn_fused, cudaFuncAttributeMaxDynamicSharedMemorySize, FUSED_SMEM);
        attr_done = true;
    }

    // projections: M=8192, N=1024, K=1024 -> head-major layout [z][s][64]
    gemm_nt_tc<1><<<dim3(8, 64, 1), 256>>>(q, w_q, qh, MROWS, DQ, DQ, 1.0f);
    gemm_nt_tc<1><<<dim3(8, 64, 1), 256>>>(k, w_k, kh, MROWS, DQ, DQ, 1.0f);
    gemm_nt_tc<1><<<dim3(8, 64, 1), 256>>>(v, w_v, vh, MROWS, DQ, DQ, 1.0f);

    // pass 1: softmax row stats (no S materialization)
    attn_stats<<<dim3(16, 64), 256, STATS_SMEM>>>(qh, kh);

    // pass 2: recompute S, write normalized P once, fused register-P · V
    attn_fused<<<dim3(16, 64), 256, FUSED_SMEM>>>(qh, kh, vh, attn, ctx);

    if (write_out) {
        gemm_nt_tc<0><<<dim3(8, 64, 1), 256>>>(ctx, w_fc, fc, MROWS, DQ, DQ, 1.0f);
        add_ln_kernel<<<MROWS, 256>>>(fc, q, ga, be, out);
    }
}

// round 6
// speedup vs baseline: 1.1920x; 1.0848x over previous
#include <cuda_runtime.h>
#include <cuda_bf16.h>

// Problem constants
#define NHEAD 16
#define DQ    1024
#define DKEY  64
#define BATCH 4
#define SEQ   2048
#define MROWS (BATCH * SEQ)          // 8192
#define OUT_ELEMS  (8192L * 1024L)           // 8,388,608
#define ATTN_ELEMS (64L * 2048L * 2048L)     // 268,435,456

// ---------------- scratch ---------------------------------------------------
__device__ float g_qh[MROWS * DQ];     // [B,H,S,64]  (z-major: z = b*16+h)
__device__ float g_kh[MROWS * DQ];
__device__ float g_vh[MROWS * DQ];
__device__ float g_ctx[MROWS * DQ];    // [B,S,H*64]
__device__ float g_fc[MROWS * DQ];
__device__ float g_rowm[64 * SEQ];     // per-row softmax max
__device__ float g_rowl[64 * SEQ];     // per-row 1/sum
__device__ float g_attn_fb[ATTN_ELEMS];

// ---------------- tf32 / cp.async helpers -----------------------------------
__device__ __forceinline__ unsigned f2tf32(float x) {
    unsigned r;
    asm("cvt.rna.tf32.f32 %0, %1;" : "=r"(r) : "f"(x));
    return r;
}

__device__ __forceinline__ void mma_tf32(float c[4],
                                         unsigned a0, unsigned a1, unsigned a2, unsigned a3,
                                         unsigned b0, unsigned b1) {
    asm volatile(
        "mma.sync.aligned.m16n8k8.row.col.f32.tf32.tf32.f32 "
        "{%0,%1,%2,%3}, {%4,%5,%6,%7}, {%8,%9}, {%0,%1,%2,%3};"
        : "+f"(c[0]), "+f"(c[1]), "+f"(c[2]), "+f"(c[3])
        : "r"(a0), "r"(a1), "r"(a2), "r"(a3), "r"(b0), "r"(b1));
}

__device__ __forceinline__ void cp16(void* smem_dst, const void* gsrc) {
    unsigned saddr = (unsigned)__cvta_generic_to_shared(smem_dst);
    asm volatile("cp.async.cg.shared.global [%0], [%1], 16;" :: "r"(saddr), "l"(gsrc));
}
#define CP_COMMIT() asm volatile("cp.async.commit_group;")
#define CP_WAIT(n)  asm volatile("cp.async.wait_group %0;" :: "n"(n) : "memory")

#define TSTR 68     // smem stride for 64-wide tf32 tiles (conflict-free frags)
#define GSTR 36     // smem stride for gemm 32-wide k tiles

// cooperative load of a 128x64 fp32 tile -> tf32 smem tile (stride TSTR)
__device__ __forceinline__ void load_tile64(unsigned* dst, const float* src, int tid)
{
    const int lr = tid >> 4;          // 0..15
    const int lc = (tid & 15) * 4;    // 0..60
#pragma unroll
    for (int i = 0; i < 8; i++) {
        const int r = lr + i * 16;
        float4 v = *(const float4*)(src + (long)r * 64 + lc);
        uint4 u;
        u.x = f2tf32(v.x); u.y = f2tf32(v.y);
        u.z = f2tf32(v.z); u.w = f2tf32(v.w);
        *(uint4*)&dst[r * TSTR + lc] = u;
    }
}

// V tile loader: [k][d] with XOR swizzle on d (conflict-free stores AND PV reads)
__device__ __forceinline__ void load_vtile(unsigned* dst, const float* src, int tid)
{
    const int lr = tid >> 4;
    const int lc = (tid & 15) * 4;
#pragma unroll
    for (int i = 0; i < 8; i++) {
        const int r = lr + i * 16;
        float4 v = *(const float4*)(src + (long)r * 64 + lc);
        uint4 u;
        u.x = f2tf32(v.x); u.y = f2tf32(v.y);
        u.z = f2tf32(v.z); u.w = f2tf32(v.w);
        *(uint4*)&dst[r * 64 + (lc ^ ((r & 7) * 8))] = u;
    }
}

// ---------------- pass 1: row stats (max, 1/sumexp) of softmax(QK^T*scale) --
__global__ __launch_bounds__(256)
void attn_stats(const float* __restrict__ qh, const float* __restrict__ kh)
{
    extern __shared__ unsigned smem[];
    unsigned* Qs = smem;                  // [128][TSTR]
    unsigned* Ks = smem + 128 * TSTR;     // [128][TSTR]

    const int z  = blockIdx.y;
    const int qb = blockIdx.x * 128;
    const float* Qz = qh + (long)z * SEQ * 64 + (long)qb * 64;
    const float* Kz = kh + (long)z * SEQ * 64;

    const int tid  = threadIdx.x;
    const int warp = tid >> 5, lane = tid & 31;
    const int wm = warp * 16;
    const int g = lane >> 2, t = lane & 3;

    load_tile64(Qs, Qz, tid);

    float m0 = -1e30f, m1 = -1e30f, l0 = 0.f, l1 = 0.f;
    const float scale = 0.125f;

    for (int k0 = 0; k0 < SEQ; k0 += 128) {
        __syncthreads();
        load_tile64(Ks, Kz + (long)k0 * 64, tid);
        __syncthreads();

        float sacc[16][4];
#pragma unroll
        for (int j = 0; j < 16; j++)
#pragma unroll
            for (int r = 0; r < 4; r++) sacc[j][r] = 0.f;

#pragma unroll
        for (int kk = 0; kk < 64; kk += 8) {
            unsigned a0 = Qs[(wm + g) * TSTR + kk + t];
            unsigned a1 = Qs[(wm + g + 8) * TSTR + kk + t];
            unsigned a2 = Qs[(wm + g) * TSTR + kk + t + 4];
            unsigned a3 = Qs[(wm + g + 8) * TSTR + kk + t + 4];
#pragma unroll
            for (int j = 0; j < 16; j++) {
                unsigned b0 = Ks[(j * 8 + g) * TSTR + kk + t];
                unsigned b1 = Ks[(j * 8 + g) * TSTR + kk + t + 4];
                mma_tf32(sacc[j], a0, a1, a2, a3, b0, b1);
            }
        }

        float t0 = -1e30f, t1 = -1e30f;
#pragma unroll
        for (int j = 0; j < 16; j++) {
            t0 = fmaxf(t0, fmaxf(sacc[j][0], sacc[j][1]));
            t1 = fmaxf(t1, fmaxf(sacc[j][2], sacc[j][3]));
        }
        t0 *= scale; t1 *= scale;
        t0 = fmaxf(t0, __shfl_xor_sync(0xffffffffu, t0, 1));
        t0 = fmaxf(t0, __shfl_xor_sync(0xffffffffu, t0, 2));
        t1 = fmaxf(t1, __shfl_xor_sync(0xffffffffu, t1, 1));
        t1 = fmaxf(t1, __shfl_xor_sync(0xffffffffu, t1, 2));

        float m0n = fmaxf(m0, t0), m1n = fmaxf(m1, t1);
        float s0 = 0.f, s1 = 0.f;
#pragma unroll
        for (int j = 0; j < 16; j++) {
            s0 += __expf(sacc[j][0] * scale - m0n) + __expf(sacc[j][1] * scale - m0n);
            s1 += __expf(sacc[j][2] * scale - m1n) + __expf(sacc[j][3] * scale - m1n);
        }
        s0 += __shfl_xor_sync(0xffffffffu, s0, 1);
        s0 += __shfl_xor_sync(0xffffffffu, s0, 2);
        s1 += __shfl_xor_sync(0xffffffffu, s1, 1);
        s1 += __shfl_xor_sync(0xffffffffu, s1, 2);

        l0 = l0 * __expf(m0 - m0n) + s0;
        l1 = l1 * __expf(m1 - m1n) + s1;
        m0 = m0n; m1 = m1n;
    }

    if (t == 0) {
        const long base = (long)z * SEQ + qb + wm;
        g_rowm[base + g]     = m0;
        g_rowm[base + g + 8] = m1;
        g_rowl[base + g]     = 1.0f / l0;
        g_rowl[base + g + 8] = 1.0f / l1;
    }
}

// ---------------- pass 2: fused P write + P·V (register P, half-tile sacc) --
__global__ __launch_bounds__(256, 2)
void attn_fused(const float* __restrict__ qh, const float* __restrict__ kh,
                const float* __restrict__ vh, float* __restrict__ attn,
                float* __restrict__ ctx)
{
    extern __shared__ unsigned smem[];
    unsigned* Qs = smem;                       // [128][TSTR]
    unsigned* Ks = smem + 128 * TSTR;          // [128][TSTR]
    unsigned* Vs = smem + 2 * 128 * TSTR;      // [128][64] xor-swizzled

    const int z  = blockIdx.y;
    const int b  = z >> 4, h = z & 15;
    const int qb = blockIdx.x * 128;
    const float* Qz = qh + (long)z * SEQ * 64 + (long)qb * 64;
    const float* Kz = kh + (long)z * SEQ * 64;
    const float* Vz = vh + (long)z * SEQ * 64;
    float* attnZ = attn + (long)z * SEQ * SEQ;

    const int tid  = threadIdx.x;
    const int warp = tid >> 5, lane = tid & 31;
    const int wm = warp * 16;
    const int g = lane >> 2, t = lane & 3;
    const int row0 = qb + wm + g, row1 = row0 + 8;

    load_tile64(Qs, Qz, tid);

    const long sbase = (long)z * SEQ;
    const float m0  = g_rowm[sbase + row0];
    const float m1  = g_rowm[sbase + row1];
    const float iv0 = g_rowl[sbase + row0];
    const float iv1 = g_rowl[sbase + row1];
    const float scale = 0.125f;

    float oacc[8][4];
#pragma unroll
    for (int j = 0; j < 8; j++)
#pragma unroll
        for (int r = 0; r < 4; r++) oacc[j][r] = 0.f;

    const int sl = (lane & ~3) + (t >> 1);   // shfl source: cols {t} of the quad
    const int sh = sl + 2;                   // shfl source: cols {t+4}
    const int x0 = 8 * t;                    // V swizzle for k-row t
    const int x1 = 8 * ((t + 4) & 7);        // V swizzle for k-row t+4

    for (int k0 = 0; k0 < SEQ; k0 += 128) {
        __syncthreads();
        load_tile64(Ks, Kz + (long)k0 * 64, tid);
        load_vtile (Vs, Vz + (long)k0 * 64, tid);
        __syncthreads();

        // two 64-column halves: keeps sacc at 8x4 regs (no spills)
#pragma unroll
        for (int jh = 0; jh < 2; jh++) {
            float sacc[8][4];
#pragma unroll
            for (int j = 0; j < 8; j++)
#pragma unroll
                for (int r = 0; r < 4; r++) sacc[j][r] = 0.f;

#pragma unroll
            for (int kk = 0; kk < 64; kk += 8) {
                unsigned a0 = Qs[(wm + g) * TSTR + kk + t];
                unsigned a1 = Qs[(wm + g + 8) * TSTR + kk + t];
                unsigned a2 = Qs[(wm + g) * TSTR + kk + t + 4];
                unsigned a3 = Qs[(wm + g + 8) * TSTR + kk + t + 4];
#pragma unroll
                for (int j = 0; j < 8; j++) {
                    const int jj = jh * 8 + j;
                    unsigned b0 = Ks[(jj * 8 + g) * TSTR + kk + t];
                    unsigned b1 = Ks[(jj * 8 + g) * TSTR + kk + t + 4];
                    mma_tf32(sacc[j], a0, a1, a2, a3, b0, b1);
                }
            }

#pragma unroll
            for (int j = 0; j < 8; j++) {
                const int jj = jh * 8 + j;
                float p0 = __expf(sacc[j][0] * scale - m0) * iv0;
                float p1 = __expf(sacc[j][1] * scale - m0) * iv0;
                float p2 = __expf(sacc[j][2] * scale - m1) * iv1;
                float p3 = __expf(sacc[j][3] * scale - m1) * iv1;

                const int c = jj * 8 + 2 * t;
                float2 lo; lo.x = p0; lo.y = p1;
                float2 hi; hi.x = p2; hi.y = p3;
                *(float2*)(attnZ + (long)row0 * SEQ + k0 + c) = lo;
                *(float2*)(attnZ + (long)row1 * SEQ + k0 + c) = hi;

                // C-frag (cols 2t,2t+1) -> A-frag (cols t,t+4) via quad shuffles
                unsigned u0 = f2tf32(p0), u1 = f2tf32(p1);
                unsigned u2 = f2tf32(p2), u3 = f2tf32(p3);
                unsigned e, o, a0, a1, a2, a3;
                e = __shfl_sync(0xffffffffu, u0, sl);
                o = __shfl_sync(0xffffffffu, u1, sl);
                a0 = (t & 1) ? o : e;
                e = __shfl_sync(0xffffffffu, u0, sh);
                o = __shfl_sync(0xffffffffu, u1, sh);
                a2 = (t & 1) ? o : e;
                e = __shfl_sync(0xffffffffu, u2, sl);
                o = __shfl_sync(0xffffffffu, u3, sl);
                a1 = (t & 1) ? o : e;
                e = __shfl_sync(0xffffffffu, u2, sh);
                o = __shfl_sync(0xffffffffu, u3, sh);
                a3 = (t & 1) ? o : e;

                const int kr0 = (jj * 8 + t) * 64;
                const int kr1 = (jj * 8 + t + 4) * 64;
#pragma unroll
                for (int jd = 0; jd < 8; jd++) {
                    unsigned b0 = Vs[kr0 + ((jd * 8 + g) ^ x0)];
                    unsigned b1 = Vs[kr1 + ((jd * 8 + g) ^ x1)];
                    mma_tf32(oacc[jd], a0, a1, a2, a3, b0, b1);
                }
            }
        }
    }

    // ---- write O to ctx[b, s, h*64+d] ----
#pragma unroll
    for (int j = 0; j < 8; j++) {
        const int d = j * 8 + 2 * t;
        float2 lo; lo.x = oacc[j][0]; lo.y = oacc[j][1];
        float2 hi; hi.x = oacc[j][2]; hi.y = oacc[j][3];
        *(float2*)(ctx + ((long)(b * SEQ + row0)) * DQ + h * 64 + d) = lo;
        *(float2*)(ctx + ((long)(b * SEQ + row1)) * DQ + h * 64 + d) = hi;
    }
}

// ---------------- pipelined tensor-core GEMM-NT (projections / FC) ----------
// C[m,n] = alpha * sum_k A[m,k]*B[n,k].  K must be a multiple of 32.
// MODE 0: C row-major [M,N].  MODE 1: projection scatter [B,H,S,64].
template <int MODE>
__global__ __launch_bounds__(256, 2)
void gemm_nt_tc(const float* __restrict__ A, const float* __restrict__ Bm,
                float* __restrict__ C, int M, int N, int K, float alpha)
{
    constexpr int BM = 128, BN = 128, BK = 32;
    extern __shared__ unsigned smem[];
    unsigned* As = smem;                    // [2][128][GSTR]
    unsigned* Bs = smem + 2 * BM * GSTR;    // [2][128][GSTR]

    const int bm = blockIdx.y * BM;
    const int bn = blockIdx.x * BN;
    const int tid  = threadIdx.x;
    const int warp = tid >> 5, lane = tid & 31;
    const int wm = (warp >> 2) * 64;
    const int wn = (warp & 3) * 32;
    const int g = lane >> 2, t = lane & 3;

    const int lr = tid >> 3;        // 0..31
    const int lc = (tid & 7) * 4;   // 0..28

    float acc[4][4][4];
#pragma unroll
    for (int i = 0; i < 4; i++)
#pragma unroll
        for (int j = 0; j < 4; j++)
#pragma unroll
            for (int r = 0; r < 4; r++) acc[i][j][r] = 0.f;

    const int nt = K / BK;

    // prologue: stage 0
    {
        unsigned* Ad = As;
        unsigned* Bd = Bs;
#pragma unroll
        for (int i = 0; i < 4; i++) {
            const int r = lr + i * 32;
            cp16(&Ad[r * GSTR + lc], A  + (long)(bm + r) * K + lc);
            cp16(&Bd[r * GSTR + lc], Bm + (long)(bn + r) * K + lc);
        }
        CP_COMMIT();
    }

    for (int kt = 0; kt < nt; kt++) {
        if (kt + 1 < nt) {
            const int st = (kt + 1) & 1;
            const int k0 = (kt + 1) * BK;
            unsigned* Ad = As + st * BM * GSTR;
            unsigned* Bd = Bs + st * BM * GSTR;
#pragma unroll
            for (int i = 0; i < 4; i++) {
                const int r = lr + i * 32;
                cp16(&Ad[r * GSTR + lc], A  + (long)(bm + r) * K + k0 + lc);
                cp16(&Bd[r * GSTR + lc], Bm + (long)(bn + r) * K + k0 + lc);
            }
            CP_COMMIT();
            CP_WAIT(1);
        } else {
            CP_WAIT(0);
        }
        __syncthreads();

        const unsigned* Ac = As + (kt & 1) * BM * GSTR;
        const unsigned* Bc = Bs + (kt & 1) * BM * GSTR;

#pragma unroll
        for (int kk = 0; kk < BK; kk += 8) {
            unsigned af[4][4], bf[4][2];
#pragma unroll
            for (int i = 0; i < 4; i++) {
                int r = wm + i * 16;
                af[i][0] = f2tf32(__uint_as_float(Ac[(r + g) * GSTR + kk + t]));
                af[i][1] = f2tf32(__uint_as_float(Ac[(r + g + 8) * GSTR + kk + t]));
                af[i][2] = f2tf32(__uint_as_float(Ac[(r + g) * GSTR + kk + t + 4]));
                af[i][3] = f2tf32(__uint_as_float(Ac[(r + g + 8) * GSTR + kk + t + 4]));
            }
#pragma unroll
            for (int j = 0; j < 4; j++) {
                int c = wn + j * 8;
                bf[j][0] = f2tf32(__uint_as_float(Bc[(c + g) * GSTR + kk + t]));
                bf[j][1] = f2tf32(__uint_as_float(Bc[(c + g) * GSTR + kk + t + 4]));
            }
#pragma unroll
            for (int i = 0; i < 4; i++)
#pragma unroll
                for (int j = 0; j < 4; j++)
                    mma_tf32(acc[i][j], af[i][0], af[i][1], af[i][2], af[i][3],
                             bf[j][0], bf[j][1]);
        }
        __syncthreads();
    }

#pragma unroll
    for (int i = 0; i < 4; i++) {
#pragma unroll
        for (int j = 0; j < 4; j++) {
            const int mrow = bm + wm + i * 16 + g;
            const int ncol = bn + wn + j * 8 + 2 * t;
            float2 lo, hi;
            lo.x = alpha * acc[i][j][0]; lo.y = alpha * acc[i][j][1];
            hi.x = alpha * acc[i][j][2]; hi.y = alpha * acc[i][j][3];
            if (MODE == 0) {
                *(float2*)(C + (long)mrow * N + ncol)       = lo;
                *(float2*)(C + (long)(mrow + 8) * N + ncol) = hi;
            } else {
                const int h = ncol >> 6, d = ncol & 63;
                int b0 = mrow >> 11, s0 = mrow & 2047;
                *(float2*)(C + ((long)((b0 * NHEAD + h) * SEQ + s0)) * 64 + d) = lo;
                int m2 = mrow + 8;
                int b1 = m2 >> 11, s1 = m2 & 2047;
                *(float2*)(C + ((long)((b1 * NHEAD + h) * SEQ + s1)) * 64 + d) = hi;
            }
        }
    }
}

// ---------------- residual add + LayerNorm ----------------------------------
__global__ __launch_bounds__(256)
void add_ln_kernel(const float* __restrict__ fc, const float* __restrict__ res,
                   const float* __restrict__ gamma, const float* __restrict__ beta,
                   float* __restrict__ out)
{
    const long row = blockIdx.x;
    const int tid = threadIdx.x;
    float4 f = ((const float4*)(fc  + row * DQ))[tid];
    float4 r = ((const float4*)(res + row * DQ))[tid];
    float x0 = f.x + r.x, x1 = f.y + r.y, x2 = f.z + r.z, x3 = f.w + r.w;

    float s  = x0 + x1 + x2 + x3;
    float sq = x0 * x0 + x1 * x1 + x2 * x2 + x3 * x3;
#pragma unroll
    for (int off = 16; off > 0; off >>= 1) {
        s  += __shfl_xor_sync(0xffffffffu, s,  off);
        sq += __shfl_xor_sync(0xffffffffu, sq, off);
    }
    __shared__ float rs[8], rq[8];
    const int wid = tid >> 5, lane = tid & 31;
    if (lane == 0) { rs[wid] = s; rq[wid] = sq; }
    __syncthreads();
    float S = 0.f, SQ = 0.f;
#pragma unroll
    for (int w = 0; w < 8; w++) { S += rs[w]; SQ += rq[w]; }

    const float mu  = S * (1.0f / DQ);
    const float var = SQ * (1.0f / DQ) - mu * mu;
    const float rstd = rsqrtf(var + 1e-6f);

    float4 g  = ((const float4*)gamma)[tid];
    float4 be = ((const float4*)beta)[tid];
    float4 o;
    o.x = (x0 - mu) * rstd * g.x + be.x;
    o.y = (x1 - mu) * rstd * g.y + be.y;
    o.z = (x2 - mu) * rstd * g.z + be.z;
    o.w = (x3 - mu) * rstd * g.w + be.w;
    ((float4*)(out + row * DQ))[tid] = o;
}

// ---------------- launcher --------------------------------------------------
extern "C" void kernel_launch(void* const* d_in, const int* in_sizes, int n_in,
                              void* d_out, int out_size)
{
    const float* q    = (const float*)d_in[0];
    const float* k    = (const float*)d_in[1];
    const float* v    = (const float*)d_in[2];
    const float* w_q  = (const float*)d_in[3];
    const float* w_k  = (const float*)d_in[4];
    const float* w_v  = (const float*)d_in[5];
    const float* w_fc = (const float*)d_in[6];
    const float* ga   = (const float*)d_in[7];
    const float* be   = (const float*)d_in[8];
    float* out = (float*)d_out;

    float *qh, *kh, *vh, *ctx, *fc, *attn_fb;
    cudaGetSymbolAddress((void**)&qh,      g_qh);
    cudaGetSymbolAddress((void**)&kh,      g_kh);
    cudaGetSymbolAddress((void**)&vh,      g_vh);
    cudaGetSymbolAddress((void**)&ctx,     g_ctx);
    cudaGetSymbolAddress((void**)&fc,      g_fc);
    cudaGetSymbolAddress((void**)&attn_fb, g_attn_fb);

    float* attn;
    bool write_out = true;
    if ((long)out_size >= OUT_ELEMS + ATTN_ELEMS) {
        attn = out + OUT_ELEMS;
    } else if ((long)out_size == ATTN_ELEMS) {
        attn = out;
        write_out = false;
    } else {
        attn = attn_fb;
    }

    const int STATS_SMEM = 2 * 128 * TSTR * 4;                 // 69,632 B
    const int FUSED_SMEM = (2 * 128 * TSTR + 128 * 64) * 4;    // 102,400 B
    const int GEMM_SMEM  = 4 * 128 * GSTR * 4;                 // 73,728 B
    static bool attr_done = false;
    if (!attr_done) {
        cudaFuncSetAttribute(attn_stats, cudaFuncAttributeMaxDynamicSharedMemorySize, STATS_SMEM);
        cudaFuncSetAttribute(attn_fused, cudaFuncAttributeMaxDynamicSharedMemorySize, FUSED_SMEM);
        cudaFuncSetAttribute(gemm_nt_tc<0>, cudaFuncAttributeMaxDynamicSharedMemorySize, GEMM_SMEM);
        cudaFuncSetAttribute(gemm_nt_tc<1>, cudaFuncAttributeMaxDynamicSharedMemorySize, GEMM_SMEM);
        attr_done = true;
    }

    // projections: M=8192, N=1024, K=1024 -> head-major layout [z][s][64]
    gemm_nt_tc<1><<<dim3(8, 64, 1), 256, GEMM_SMEM>>>(q, w_q, qh, MROWS, DQ, DQ, 1.0f);
    gemm_nt_tc<1><<<dim3(8, 64, 1), 256, GEMM_SMEM>>>(k, w_k, kh, MROWS, DQ, DQ, 1.0f);
    gemm_nt_tc<1><<<dim3(8, 64, 1), 256, GEMM_SMEM>>>(v, w_v, vh, MROWS, DQ, DQ, 1.0f);

    // pass 1: softmax row stats (no S materialization)
    attn_stats<<<dim3(16, 64), 256, STATS_SMEM>>>(qh, kh);

    // pass 2: recompute S, write normalized P once, fused register-P · V
    attn_fused<<<dim3(16, 64), 256, FUSED_SMEM>>>(qh, kh, vh, attn, ctx);

    if (write_out) {
        gemm_nt_tc<0><<<dim3(8, 64, 1), 256, GEMM_SMEM>>>(ctx, w_fc, fc, MROWS, DQ, DQ, 1.0f);
        add_ln_kernel<<<MROWS, 256>>>(fc, q, ga, be, out);
    }
}

// round 7
// speedup vs baseline: 1.2667x; 1.0627x over previous
#include <cuda_runtime.h>
#include <cuda_bf16.h>

// Problem constants
#define NHEAD 16
#define DQ    1024
#define DKEY  64
#define BATCH 4
#define SEQ   2048
#define MROWS (BATCH * SEQ)          // 8192
#define OUT_ELEMS  (8192L * 1024L)           // 8,388,608
#define ATTN_ELEMS (64L * 2048L * 2048L)     // 268,435,456

// ---------------- scratch ---------------------------------------------------
__device__ float g_qh[MROWS * DQ];     // [B,H,S,64]  (z-major: z = b*16+h)
__device__ float g_kh[MROWS * DQ];
__device__ float g_vh[MROWS * DQ];
__device__ float g_ctx[MROWS * DQ];    // [B,S,H*64]
__device__ float g_fc[MROWS * DQ];
__device__ float g_rowm[64 * SEQ];     // per-row softmax max
__device__ float g_rowl[64 * SEQ];     // per-row 1/sum
__device__ float g_attn_fb[ATTN_ELEMS];

// ---------------- tf32 / cp.async helpers -----------------------------------
__device__ __forceinline__ unsigned f2tf32(float x) {
    unsigned r;
    asm("cvt.rna.tf32.f32 %0, %1;" : "=r"(r) : "f"(x));
    return r;
}

__device__ __forceinline__ void mma_tf32(float c[4],
                                         unsigned a0, unsigned a1, unsigned a2, unsigned a3,
                                         unsigned b0, unsigned b1) {
    asm volatile(
        "mma.sync.aligned.m16n8k8.row.col.f32.tf32.tf32.f32 "
        "{%0,%1,%2,%3}, {%4,%5,%6,%7}, {%8,%9}, {%0,%1,%2,%3};"
        : "+f"(c[0]), "+f"(c[1]), "+f"(c[2]), "+f"(c[3])
        : "r"(a0), "r"(a1), "r"(a2), "r"(a3), "r"(b0), "r"(b1));
}

__device__ __forceinline__ void cp16(void* smem_dst, const void* gsrc) {
    unsigned saddr = (unsigned)__cvta_generic_to_shared(smem_dst);
    asm volatile("cp.async.cg.shared.global [%0], [%1], 16;" :: "r"(saddr), "l"(gsrc));
}
#define CP_COMMIT() asm volatile("cp.async.commit_group;")
#define CP_WAIT(n)  asm volatile("cp.async.wait_group %0;" :: "n"(n) : "memory")

#define KSTR 68     // fp32 smem stride for 64-wide K chunks (conflict-free frags)
#define GSTR 36     // smem stride for gemm 32-wide k tiles
#define NCH  (SEQ / 64)   // 32 chunks

// load this thread's Q fragments (16 rows x 64 cols of one q-strip) into regs
__device__ __forceinline__ void load_qfrag(unsigned aq[8][4], const float* Qz,
                                           int row0, int t)
{
    const float* Q0 = Qz + (long)row0 * 64;
    const float* Q1 = Q0 + 8 * 64;
#pragma unroll
    for (int k8 = 0; k8 < 8; k8++) {
        aq[k8][0] = f2tf32(Q0[k8 * 8 + t]);
        aq[k8][1] = f2tf32(Q1[k8 * 8 + t]);
        aq[k8][2] = f2tf32(Q0[k8 * 8 + t + 4]);
        aq[k8][3] = f2tf32(Q1[k8 * 8 + t + 4]);
    }
}

// cp.async a 64x64 fp32 chunk into smem with stride KSTR
__device__ __forceinline__ void cp_chunk_k(float* dst, const float* src, int tid)
{
#pragma unroll
    for (int i = 0; i < 4; i++) {
        const int idx = tid + i * 256;
        const int r = idx >> 4, c4 = (idx & 15) * 4;
        cp16(&dst[r * KSTR + c4], src + (long)r * 64 + c4);
    }
}

// cp.async a 64x64 fp32 chunk into xor-swizzled [64][64] smem
__device__ __forceinline__ void cp_chunk_v(float* dst, const float* src, int tid)
{
#pragma unroll
    for (int i = 0; i < 4; i++) {
        const int idx = tid + i * 256;
        const int r = idx >> 4, c4 = (idx & 15) * 4;
        cp16(&dst[r * 64 + (c4 ^ ((r & 7) * 8))], src + (long)r * 64 + c4);
    }
}

// ---------------- pass 1: row stats (max, 1/sumexp) of softmax(QK^T*scale) --
__global__ __launch_bounds__(256, 2)
void attn_stats(const float* __restrict__ qh, const float* __restrict__ kh)
{
    extern __shared__ float smK[];     // [2][64][KSTR]

    const int z  = blockIdx.y;
    const int qb = blockIdx.x * 128;
    const float* Kz = kh + (long)z * SEQ * 64;

    const int tid = threadIdx.x;
    const int warp = tid >> 5, lane = tid & 31;
    const int wm = warp * 16;
    const int g = lane >> 2, t = lane & 3;
    const int row0 = qb + wm + g;

    unsigned aq[8][4];
    load_qfrag(aq, qh + (long)z * SEQ * 64, row0, t);

    const float scale = 0.125f;
    float m0 = -1e30f, m1 = -1e30f, l0 = 0.f, l1 = 0.f;

    cp_chunk_k(smK, Kz, tid);
    CP_COMMIT();

    for (int ch = 0; ch < NCH; ch++) {
        if (ch + 1 < NCH) {
            cp_chunk_k(smK + ((ch + 1) & 1) * 64 * KSTR,
                       Kz + (long)(ch + 1) * 64 * 64, tid);
            CP_COMMIT();
            CP_WAIT(1);
        } else {
            CP_WAIT(0);
        }
        __syncthreads();

        const float* Kc = smK + (ch & 1) * 64 * KSTR;

        float sacc[8][4];
#pragma unroll
        for (int j = 0; j < 8; j++)
#pragma unroll
            for (int r = 0; r < 4; r++) sacc[j][r] = 0.f;

#pragma unroll
        for (int kk = 0; kk < 8; kk++) {
#pragma unroll
            for (int j = 0; j < 8; j++) {
                unsigned b0 = f2tf32(Kc[(j * 8 + g) * KSTR + kk * 8 + t]);
                unsigned b1 = f2tf32(Kc[(j * 8 + g) * KSTR + kk * 8 + t + 4]);
                mma_tf32(sacc[j], aq[kk][0], aq[kk][1], aq[kk][2], aq[kk][3], b0, b1);
            }
        }

        float t0 = -1e30f, t1 = -1e30f;
#pragma unroll
        for (int j = 0; j < 8; j++) {
            t0 = fmaxf(t0, fmaxf(sacc[j][0], sacc[j][1]));
            t1 = fmaxf(t1, fmaxf(sacc[j][2], sacc[j][3]));
        }
        t0 *= scale; t1 *= scale;
        t0 = fmaxf(t0, __shfl_xor_sync(0xffffffffu, t0, 1));
        t0 = fmaxf(t0, __shfl_xor_sync(0xffffffffu, t0, 2));
        t1 = fmaxf(t1, __shfl_xor_sync(0xffffffffu, t1, 1));
        t1 = fmaxf(t1, __shfl_xor_sync(0xffffffffu, t1, 2));

        float m0n = fmaxf(m0, t0), m1n = fmaxf(m1, t1);
        float s0 = 0.f, s1 = 0.f;
#pragma unroll
        for (int j = 0; j < 8; j++) {
            s0 += __expf(sacc[j][0] * scale - m0n) + __expf(sacc[j][1] * scale - m0n);
            s1 += __expf(sacc[j][2] * scale - m1n) + __expf(sacc[j][3] * scale - m1n);
        }
        s0 += __shfl_xor_sync(0xffffffffu, s0, 1);
        s0 += __shfl_xor_sync(0xffffffffu, s0, 2);
        s1 += __shfl_xor_sync(0xffffffffu, s1, 1);
        s1 += __shfl_xor_sync(0xffffffffu, s1, 2);

        l0 = l0 * __expf(m0 - m0n) + s0;
        l1 = l1 * __expf(m1 - m1n) + s1;
        m0 = m0n; m1 = m1n;
        __syncthreads();
    }

    if (t == 0) {
        const long base = (long)z * SEQ + qb + wm;
        g_rowm[base + g]     = m0;
        g_rowm[base + g + 8] = m1;
        g_rowl[base + g]     = 1.0f / l0;
        g_rowl[base + g + 8] = 1.0f / l1;
    }
}

// ---------------- pass 2: fused P write + P·V (register P & Q) --------------
__global__ __launch_bounds__(256, 2)
void attn_fused(const float* __restrict__ qh, const float* __restrict__ kh,
                const float* __restrict__ vh, float* __restrict__ attn,
                float* __restrict__ ctx)
{
    extern __shared__ float smKV[];
    float* Kb = smKV;                    // [2][64][KSTR]
    float* Vb = smKV + 2 * 64 * KSTR;    // [2][64][64] xor-swizzled

    const int z  = blockIdx.y;
    const int b  = z >> 4, h = z & 15;
    const int qb = blockIdx.x * 128;
    const float* Kz = kh + (long)z * SEQ * 64;
    const float* Vz = vh + (long)z * SEQ * 64;
    float* attnZ = attn + (long)z * SEQ * SEQ;

    const int tid  = threadIdx.x;
    const int warp = tid >> 5, lane = tid & 31;
    const int wm = warp * 16;
    const int g = lane >> 2, t = lane & 3;
    const int row0 = qb + wm + g, row1 = row0 + 8;

    unsigned aq[8][4];
    load_qfrag(aq, qh + (long)z * SEQ * 64, row0, t);

    const long sbase = (long)z * SEQ;
    const float m0  = g_rowm[sbase + row0];
    const float m1  = g_rowm[sbase + row1];
    const float iv0 = g_rowl[sbase + row0];
    const float iv1 = g_rowl[sbase + row1];
    const float scale = 0.125f;

    float oacc[8][4];
#pragma unroll
    for (int j = 0; j < 8; j++)
#pragma unroll
        for (int r = 0; r < 4; r++) oacc[j][r] = 0.f;

    const int sl = (lane & ~3) + (t >> 1);   // shfl source: cols {t} of the quad
    const int sh = sl + 2;                   // shfl source: cols {t+4}
    const int x0v = 8 * t;                   // V swizzle for k-row t
    const int x1v = 8 * ((t + 4) & 7);       // V swizzle for k-row t+4

    cp_chunk_k(Kb, Kz, tid); CP_COMMIT();
    cp_chunk_v(Vb, Vz, tid); CP_COMMIT();

    for (int ch = 0; ch < NCH; ch++) {
        if (ch + 1 < NCH) {
            const int st = (ch + 1) & 1;
            cp_chunk_k(Kb + st * 64 * KSTR, Kz + (long)(ch + 1) * 64 * 64, tid);
            CP_COMMIT();
            cp_chunk_v(Vb + st * 64 * 64,  Vz + (long)(ch + 1) * 64 * 64, tid);
            CP_COMMIT();
            CP_WAIT(2);
        } else {
            CP_WAIT(0);
        }
        __syncthreads();

        const float* Kc = Kb + (ch & 1) * 64 * KSTR;
        const float* Vc = Vb + (ch & 1) * 64 * 64;

        // ---- S = Q K^T for this 128x64 chunk ----
        float sacc[8][4];
#pragma unroll
        for (int j = 0; j < 8; j++)
#pragma unroll
            for (int r = 0; r < 4; r++) sacc[j][r] = 0.f;

#pragma unroll
        for (int kk = 0; kk < 8; kk++) {
#pragma unroll
            for (int j = 0; j < 8; j++) {
                unsigned b0 = f2tf32(Kc[(j * 8 + g) * KSTR + kk * 8 + t]);
                unsigned b1 = f2tf32(Kc[(j * 8 + g) * KSTR + kk * 8 + t + 4]);
                mma_tf32(sacc[j], aq[kk][0], aq[kk][1], aq[kk][2], aq[kk][3], b0, b1);
            }
        }

        // ---- p = exp(s*scale - m)*inv_l; write attn; PV mma ----
#pragma unroll
        for (int j = 0; j < 8; j++) {
            float p0 = __expf(sacc[j][0] * scale - m0) * iv0;
            float p1 = __expf(sacc[j][1] * scale - m0) * iv0;
            float p2 = __expf(sacc[j][2] * scale - m1) * iv1;
            float p3 = __expf(sacc[j][3] * scale - m1) * iv1;

            const int c = ch * 64 + j * 8 + 2 * t;
            float2 lo; lo.x = p0; lo.y = p1;
            float2 hi; hi.x = p2; hi.y = p3;
            *(float2*)(attnZ + (long)row0 * SEQ + c) = lo;
            *(float2*)(attnZ + (long)row1 * SEQ + c) = hi;

            // C-frag (cols 2t,2t+1) -> A-frag (cols t,t+4) via quad shuffles
            unsigned u0 = f2tf32(p0), u1 = f2tf32(p1);
            unsigned u2 = f2tf32(p2), u3 = f2tf32(p3);
            unsigned e, o, a0, a1, a2, a3;
            e = __shfl_sync(0xffffffffu, u0, sl);
            o = __shfl_sync(0xffffffffu, u1, sl);
            a0 = (t & 1) ? o : e;
            e = __shfl_sync(0xffffffffu, u0, sh);
            o = __shfl_sync(0xffffffffu, u1, sh);
            a2 = (t & 1) ? o : e;
            e = __shfl_sync(0xffffffffu, u2, sl);
            o = __shfl_sync(0xffffffffu, u3, sl);
            a1 = (t & 1) ? o : e;
            e = __shfl_sync(0xffffffffu, u2, sh);
            o = __shfl_sync(0xffffffffu, u3, sh);
            a3 = (t & 1) ? o : e;

            const int kr0 = (j * 8 + t) * 64;
            const int kr1 = (j * 8 + t + 4) * 64;
#pragma unroll
            for (int jd = 0; jd < 8; jd++) {
                unsigned b0 = f2tf32(Vc[kr0 + ((jd * 8 + g) ^ x0v)]);
                unsigned b1 = f2tf32(Vc[kr1 + ((jd * 8 + g) ^ x1v)]);
                mma_tf32(oacc[jd], a0, a1, a2, a3, b0, b1);
            }
        }
        __syncthreads();
    }

    // ---- write O to ctx[b, s, h*64+d] ----
#pragma unroll
    for (int j = 0; j < 8; j++) {
        const int d = j * 8 + 2 * t;
        float2 lo; lo.x = oacc[j][0]; lo.y = oacc[j][1];
        float2 hi; hi.x = oacc[j][2]; hi.y = oacc[j][3];
        *(float2*)(ctx + ((long)(b * SEQ + row0)) * DQ + h * 64 + d) = lo;
        *(float2*)(ctx + ((long)(b * SEQ + row1)) * DQ + h * 64 + d) = hi;
    }
}

// ---------------- pipelined tensor-core GEMM-NT body ------------------------
// C[m,n] = alpha * sum_k A[m,k]*B[n,k].  K multiple of 32.
// MODE 0: C row-major [M,N].  MODE 1: projection scatter [B,H,S,64].
template <int MODE>
__device__ __forceinline__
void gemm_body(const float* __restrict__ A, const float* __restrict__ Bm,
               float* __restrict__ C, int M, int N, int K, float alpha,
               unsigned* smem)
{
    constexpr int BM = 128, BN = 128, BK = 32;
    unsigned* As = smem;                    // [2][128][GSTR]
    unsigned* Bs = smem + 2 * BM * GSTR;    // [2][128][GSTR]

    const int bm = blockIdx.y * BM;
    const int bn = blockIdx.x * BN;
    const int tid  = threadIdx.x;
    const int warp = tid >> 5, lane = tid & 31;
    const int wm = (warp >> 2) * 64;
    const int wn = (warp & 3) * 32;
    const int g = lane >> 2, t = lane & 3;

    const int lr = tid >> 3;        // 0..31
    const int lc = (tid & 7) * 4;   // 0..28

    float acc[4][4][4];
#pragma unroll
    for (int i = 0; i < 4; i++)
#pragma unroll
        for (int j = 0; j < 4; j++)
#pragma unroll
            for (int r = 0; r < 4; r++) acc[i][j][r] = 0.f;

    const int nt = K / BK;

    {
#pragma unroll
        for (int i = 0; i < 4; i++) {
            const int r = lr + i * 32;
            cp16(&As[r * GSTR + lc], A  + (long)(bm + r) * K + lc);
            cp16(&Bs[r * GSTR + lc], Bm + (long)(bn + r) * K + lc);
        }
        CP_COMMIT();
    }

    for (int kt = 0; kt < nt; kt++) {
        if (kt + 1 < nt) {
            const int st = (kt + 1) & 1;
            const int k0 = (kt + 1) * BK;
            unsigned* Ad = As + st * BM * GSTR;
            unsigned* Bd = Bs + st * BM * GSTR;
#pragma unroll
            for (int i = 0; i < 4; i++) {
                const int r = lr + i * 32;
                cp16(&Ad[r * GSTR + lc], A  + (long)(bm + r) * K + k0 + lc);
                cp16(&Bd[r * GSTR + lc], Bm + (long)(bn + r) * K + k0 + lc);
            }
            CP_COMMIT();
            CP_WAIT(1);
        } else {
            CP_WAIT(0);
        }
        __syncthreads();

        const unsigned* Ac = As + (kt & 1) * BM * GSTR;
        const unsigned* Bc = Bs + (kt & 1) * BM * GSTR;

#pragma unroll
        for (int kk = 0; kk < BK; kk += 8) {
            unsigned af[4][4], bf[4][2];
#pragma unroll
            for (int i = 0; i < 4; i++) {
                int r = wm + i * 16;
                af[i][0] = f2tf32(__uint_as_float(Ac[(r + g) * GSTR + kk + t]));
                af[i][1] = f2tf32(__uint_as_float(Ac[(r + g + 8) * GSTR + kk + t]));
                af[i][2] = f2tf32(__uint_as_float(Ac[(r + g) * GSTR + kk + t + 4]));
                af[i][3] = f2tf32(__uint_as_float(Ac[(r + g + 8) * GSTR + kk + t + 4]));
            }
#pragma unroll
            for (int j = 0; j < 4; j++) {
                int c = wn + j * 8;
                bf[j][0] = f2tf32(__uint_as_float(Bc[(c + g) * GSTR + kk + t]));
                bf[j][1] = f2tf32(__uint_as_float(Bc[(c + g) * GSTR + kk + t + 4]));
            }
#pragma unroll
            for (int i = 0; i < 4; i++)
#pragma unroll
                for (int j = 0; j < 4; j++)
                    mma_tf32(acc[i][j], af[i][0], af[i][1], af[i][2], af[i][3],
                             bf[j][0], bf[j][1]);
        }
        __syncthreads();
    }

#pragma unroll
    for (int i = 0; i < 4; i++) {
#pragma unroll
        for (int j = 0; j < 4; j++) {
            const int mrow = bm + wm + i * 16 + g;
            const int ncol = bn + wn + j * 8 + 2 * t;
            float2 lo, hi;
            lo.x = alpha * acc[i][j][0]; lo.y = alpha * acc[i][j][1];
            hi.x = alpha * acc[i][j][2]; hi.y = alpha * acc[i][j][3];
            if (MODE == 0) {
                *(float2*)(C + (long)mrow * N + ncol)       = lo;
                *(float2*)(C + (long)(mrow + 8) * N + ncol) = hi;
            } else {
                const int h = ncol >> 6, d = ncol & 63;
                int b0 = mrow >> 11, s0 = mrow & 2047;
                *(float2*)(C + ((long)((b0 * NHEAD + h) * SEQ + s0)) * 64 + d) = lo;
                int m2 = mrow + 8;
                int b1 = m2 >> 11, s1 = m2 & 2047;
                *(float2*)(C + ((long)((b1 * NHEAD + h) * SEQ + s1)) * 64 + d) = hi;
            }
        }
    }
}

__global__ __launch_bounds__(256, 2)
void gemm_fc(const float* __restrict__ A, const float* __restrict__ Bm,
             float* __restrict__ C, int M, int N, int K, float alpha)
{
    extern __shared__ unsigned smemg[];
    gemm_body<0>(A, Bm, C, M, N, K, alpha, smemg);
}

struct Proj3 {
    const float *A0, *A1, *A2;
    const float *B0, *B1, *B2;
    float *C0, *C1, *C2;
};

__global__ __launch_bounds__(256, 2)
void gemm_proj3(Proj3 p, int M, int N, int K)
{
    extern __shared__ unsigned smemg[];
    const float* A = (blockIdx.z == 0) ? p.A0 : (blockIdx.z == 1) ? p.A1 : p.A2;
    const float* B = (blockIdx.z == 0) ? p.B0 : (blockIdx.z == 1) ? p.B1 : p.B2;
    float*       C = (blockIdx.z == 0) ? p.C0 : (blockIdx.z == 1) ? p.C1 : p.C2;
    gemm_body<1>(A, B, C, M, N, K, 1.0f, smemg);
}

// ---------------- residual add + LayerNorm ----------------------------------
__global__ __launch_bounds__(256)
void add_ln_kernel(const float* __restrict__ fc, const float* __restrict__ res,
                   const float* __restrict__ gamma, const float* __restrict__ beta,
                   float* __restrict__ out)
{
    const long row = blockIdx.x;
    const int tid = threadIdx.x;
    float4 f = ((const float4*)(fc  + row * DQ))[tid];
    float4 r = ((const float4*)(res + row * DQ))[tid];
    float x0 = f.x + r.x, x1 = f.y + r.y, x2 = f.z + r.z, x3 = f.w + r.w;

    float s  = x0 + x1 + x2 + x3;
    float sq = x0 * x0 + x1 * x1 + x2 * x2 + x3 * x3;
#pragma unroll
    for (int off = 16; off > 0; off >>= 1) {
        s  += __shfl_xor_sync(0xffffffffu, s,  off);
        sq += __shfl_xor_sync(0xffffffffu, sq, off);
    }
    __shared__ float rs[8], rq[8];
    const int wid = tid >> 5, lane = tid & 31;
    if (lane == 0) { rs[wid] = s; rq[wid] = sq; }
    __syncthreads();
    float S = 0.f, SQ = 0.f;
#pragma unroll
    for (int w = 0; w < 8; w++) { S += rs[w]; SQ += rq[w]; }

    const float mu  = S * (1.0f / DQ);
    const float var = SQ * (1.0f / DQ) - mu * mu;
    const float rstd = rsqrtf(var + 1e-6f);

    float4 g  = ((const float4*)gamma)[tid];
    float4 be = ((const float4*)beta)[tid];
    float4 o;
    o.x = (x0 - mu) * rstd * g.x + be.x;
    o.y = (x1 - mu) * rstd * g.y + be.y;
    o.z = (x2 - mu) * rstd * g.z + be.z;
    o.w = (x3 - mu) * rstd * g.w + be.w;
    ((float4*)(out + row * DQ))[tid] = o;
}

// ---------------- launcher --------------------------------------------------
extern "C" void kernel_launch(void* const* d_in, const int* in_sizes, int n_in,
                              void* d_out, int out_size)
{
    const float* q    = (const float*)d_in[0];
    const float* k    = (const float*)d_in[1];
    const float* v    = (const float*)d_in[2];
    const float* w_q  = (const float*)d_in[3];
    const float* w_k  = (const float*)d_in[4];
    const float* w_v  = (const float*)d_in[5];
    const float* w_fc = (const float*)d_in[6];
    const float* ga   = (const float*)d_in[7];
    const float* be   = (const float*)d_in[8];
    float* out = (float*)d_out;

    float *qh, *kh, *vh, *ctx, *fc, *attn_fb;
    cudaGetSymbolAddress((void**)&qh,      g_qh);
    cudaGetSymbolAddress((void**)&kh,      g_kh);
    cudaGetSymbolAddress((void**)&vh,      g_vh);
    cudaGetSymbolAddress((void**)&ctx,     g_ctx);
    cudaGetSymbolAddress((void**)&fc,      g_fc);
    cudaGetSymbolAddress((void**)&attn_fb, g_attn_fb);

    float* attn;
    bool write_out = true;
    if ((long)out_size >= OUT_ELEMS + ATTN_ELEMS) {
        attn = out + OUT_ELEMS;
    } else if ((long)out_size == ATTN_ELEMS) {
        attn = out;
        write_out = false;
    } else {
        attn = attn_fb;
    }

    const int STATS_SMEM = 2 * 64 * KSTR * 4;                    // 34,816 B
    const int FUSED_SMEM = (2 * 64 * KSTR + 2 * 64 * 64) * 4;    // 67,584 B
    const int GEMM_SMEM  = 4 * 128 * GSTR * 4;                   // 73,728 B
    static bool attr_done = false;
    if (!attr_done) {
        cudaFuncSetAttribute(attn_stats, cudaFuncAttributeMaxDynamicSharedMemorySize, STATS_SMEM);
        cudaFuncSetAttribute(attn_fused, cudaFuncAttributeMaxDynamicSharedMemorySize, FUSED_SMEM);
        cudaFuncSetAttribute(gemm_fc,    cudaFuncAttributeMaxDynamicSharedMemorySize, GEMM_SMEM);
        cudaFuncSetAttribute(gemm_proj3, cudaFuncAttributeMaxDynamicSharedMemorySize, GEMM_SMEM);
        attr_done = true;
    }

    // projections (merged): M=8192, N=1024, K=1024 -> head-major layout
    Proj3 p;
    p.A0 = q;  p.A1 = k;  p.A2 = v;
    p.B0 = w_q; p.B1 = w_k; p.B2 = w_v;
    p.C0 = qh; p.C1 = kh; p.C2 = vh;
    gemm_proj3<<<dim3(8, 64, 3), 256, GEMM_SMEM>>>(p, MROWS, DQ, DQ);

    // pass 1: softmax row stats (no S materialization)
    attn_stats<<<dim3(16, 64), 256, STATS_SMEM>>>(qh, kh);

    // pass 2: recompute S, write normalized P once, fused register-P · V
    attn_fused<<<dim3(16, 64), 256, FUSED_SMEM>>>(qh, kh, vh, attn, ctx);

    if (write_out) {
        gemm_fc<<<dim3(8, 64, 1), 256, GEMM_SMEM>>>(ctx, w_fc, fc, MROWS, DQ, DQ, 1.0f);
        add_ln_kernel<<<MROWS, 256>>>(fc, q, ga, be, out);
    }
}

// round 8
// speedup vs baseline: 1.3199x; 1.0420x over previous
#include <cuda_runtime.h>
#include <cuda_bf16.h>

// Problem constants
#define NHEAD 16
#define DQ    1024
#define DKEY  64
#define BATCH 4
#define SEQ   2048
#define MROWS (BATCH * SEQ)          // 8192
#define OUT_ELEMS  (8192L * 1024L)           // 8,388,608
#define ATTN_ELEMS (64L * 2048L * 2048L)     // 268,435,456

// ---------------- scratch ---------------------------------------------------
__device__ float g_qh[MROWS * DQ];     // [z][s][64]   z = b*16+h
__device__ float g_kh[MROWS * DQ];     // [z][s][64]
__device__ float g_vh[MROWS * DQ];     // TRANSPOSED: [z][d][s]
__device__ float g_ctx[MROWS * DQ];    // [B,S,H*64]
__device__ float g_fc[MROWS * DQ];
__device__ float g_rowm[64 * SEQ];
__device__ float g_rowl[64 * SEQ];
__device__ float g_attn_fb[ATTN_ELEMS];

// ---------------- helpers ----------------------------------------------------
__device__ __forceinline__ unsigned f2tf32(float x) {
    unsigned r;
    asm("cvt.rna.tf32.f32 %0, %1;" : "=r"(r) : "f"(x));
    return r;
}
__device__ __forceinline__ unsigned cvtu(unsigned x) {   // raw fp32 bits -> tf32
    return f2tf32(__uint_as_float(x));
}

__device__ __forceinline__ void mma_tf32(float c[4],
                                         unsigned a0, unsigned a1, unsigned a2, unsigned a3,
                                         unsigned b0, unsigned b1) {
    asm volatile(
        "mma.sync.aligned.m16n8k8.row.col.f32.tf32.tf32.f32 "
        "{%0,%1,%2,%3}, {%4,%5,%6,%7}, {%8,%9}, {%0,%1,%2,%3};"
        : "+f"(c[0]), "+f"(c[1]), "+f"(c[2]), "+f"(c[3])
        : "r"(a0), "r"(a1), "r"(a2), "r"(a3), "r"(b0), "r"(b1));
}

__device__ __forceinline__ void ldsm4(unsigned& r0, unsigned& r1,
                                      unsigned& r2, unsigned& r3, unsigned addr) {
    asm volatile("ldmatrix.sync.aligned.m8n8.x4.shared.b16 {%0,%1,%2,%3}, [%4];"
                 : "=r"(r0), "=r"(r1), "=r"(r2), "=r"(r3) : "r"(addr));
}

__device__ __forceinline__ void cp16(void* smem_dst, const void* gsrc) {
    unsigned saddr = (unsigned)__cvta_generic_to_shared(smem_dst);
    asm volatile("cp.async.cg.shared.global [%0], [%1], 16;" :: "r"(saddr), "l"(gsrc));
}
#define CP_COMMIT() asm volatile("cp.async.commit_group;")
#define CP_WAIT(n)  asm volatile("cp.async.wait_group %0;" :: "n"(n) : "memory")

#define KSTR 68     // fp32 smem stride for 64-wide tiles (LDSM-conflict-free)
#define GSTR 36     // gemm smem stride (32-wide k tiles)
#define NCH  (SEQ / 64)

// load this thread's Q fragments (16 rows x 64 cols) into regs
__device__ __forceinline__ void load_qfrag(unsigned aq[8][4], const float* Qz,
                                           int row0, int t)
{
    const float* Q0 = Qz + (long)row0 * 64;
    const float* Q1 = Q0 + 8 * 64;
#pragma unroll
    for (int k8 = 0; k8 < 8; k8++) {
        aq[k8][0] = f2tf32(Q0[k8 * 8 + t]);
        aq[k8][1] = f2tf32(Q1[k8 * 8 + t]);
        aq[k8][2] = f2tf32(Q0[k8 * 8 + t + 4]);
        aq[k8][3] = f2tf32(Q1[k8 * 8 + t + 4]);
    }
}

// cp.async a 64x64 fp32 chunk (row stride `gstride` in gmem) into smem stride KSTR
__device__ __forceinline__ void cp_chunk(float* dst, const float* src,
                                         long gstride, int tid)
{
#pragma unroll
    for (int i = 0; i < 4; i++) {
        const int idx = tid + i * 256;
        const int r = idx >> 4, c4 = (idx & 15) * 4;
        cp16(&dst[r * KSTR + c4], src + (long)r * gstride + c4);
    }
}

// per-lane LDSM base offset (bytes) for K/V^T tiles of stride KSTR:
// row = (l>>4)*8 + (l&7), col-half = 4 tf32 * ((l>>3)&1)
__device__ __forceinline__ unsigned ldsm_lane_off(int lane, int stride)
{
    return (unsigned)((((lane >> 4) * 8 + (lane & 7)) * stride) * 4
                      + 16 * ((lane >> 3) & 1));
}

// ---------------- pass 1: softmax row stats ---------------------------------
__global__ __launch_bounds__(256, 2)
void attn_stats(const float* __restrict__ qh, const float* __restrict__ kh)
{
    extern __shared__ float smK[];     // [2][64][KSTR]

    const int z  = blockIdx.y;
    const int qb = blockIdx.x * 128;
    const float* Kz = kh + (long)z * SEQ * 64;

    const int tid = threadIdx.x;
    const int warp = tid >> 5, lane = tid & 31;
    const int wm = warp * 16;
    const int g = lane >> 2, t = lane & 3;
    const int row0 = qb + wm + g;

    unsigned aq[8][4];
    load_qfrag(aq, qh + (long)z * SEQ * 64, row0, t);

    const unsigned smK_u = (unsigned)__cvta_generic_to_shared(smK);
    const unsigned kLane = smK_u + ldsm_lane_off(lane, KSTR);

    const float scale = 0.125f;
    float m0 = -1e30f, m1 = -1e30f, l0 = 0.f, l1 = 0.f;

    cp_chunk(smK, Kz, 64, tid);
    CP_COMMIT();

    for (int ch = 0; ch < NCH; ch++) {
        if (ch + 1 < NCH) {
            cp_chunk(smK + ((ch + 1) & 1) * 64 * KSTR,
                     Kz + (long)(ch + 1) * 64 * 64, 64, tid);
            CP_COMMIT();
            CP_WAIT(1);
        } else {
            CP_WAIT(0);
        }
        __syncthreads();

        const unsigned kBuf = kLane + (unsigned)((ch & 1) * 64 * KSTR * 4);

        float sacc[8][4];
#pragma unroll
        for (int j = 0; j < 8; j++)
#pragma unroll
            for (int r = 0; r < 4; r++) sacc[j][r] = 0.f;

#pragma unroll
        for (int kk = 0; kk < 8; kk++) {
#pragma unroll
            for (int jp = 0; jp < 4; jp++) {
                unsigned r0, r1, r2, r3;
                ldsm4(r0, r1, r2, r3,
                      kBuf + (unsigned)((jp * 16 * KSTR + kk * 8) * 4));
                r0 = cvtu(r0); r1 = cvtu(r1); r2 = cvtu(r2); r3 = cvtu(r3);
                mma_tf32(sacc[2 * jp],     aq[kk][0], aq[kk][1], aq[kk][2], aq[kk][3], r0, r1);
                mma_tf32(sacc[2 * jp + 1], aq[kk][0], aq[kk][1], aq[kk][2], aq[kk][3], r2, r3);
            }
        }

        float t0 = -1e30f, t1 = -1e30f;
#pragma unroll
        for (int j = 0; j < 8; j++) {
            t0 = fmaxf(t0, fmaxf(sacc[j][0], sacc[j][1]));
            t1 = fmaxf(t1, fmaxf(sacc[j][2], sacc[j][3]));
        }
        t0 *= scale; t1 *= scale;
        t0 = fmaxf(t0, __shfl_xor_sync(0xffffffffu, t0, 1));
        t0 = fmaxf(t0, __shfl_xor_sync(0xffffffffu, t0, 2));
        t1 = fmaxf(t1, __shfl_xor_sync(0xffffffffu, t1, 1));
        t1 = fmaxf(t1, __shfl_xor_sync(0xffffffffu, t1, 2));

        float m0n = fmaxf(m0, t0), m1n = fmaxf(m1, t1);
        float s0 = 0.f, s1 = 0.f;
#pragma unroll
        for (int j = 0; j < 8; j++) {
            s0 += __expf(sacc[j][0] * scale - m0n) + __expf(sacc[j][1] * scale - m0n);
            s1 += __expf(sacc[j][2] * scale - m1n) + __expf(sacc[j][3] * scale - m1n);
        }
        s0 += __shfl_xor_sync(0xffffffffu, s0, 1);
        s0 += __shfl_xor_sync(0xffffffffu, s0, 2);
        s1 += __shfl_xor_sync(0xffffffffu, s1, 1);
        s1 += __shfl_xor_sync(0xffffffffu, s1, 2);

        l0 = l0 * __expf(m0 - m0n) + s0;
        l1 = l1 * __expf(m1 - m1n) + s1;
        m0 = m0n; m1 = m1n;
        __syncthreads();
    }

    if (t == 0) {
        const long base = (long)z * SEQ + qb + wm;
        g_rowm[base + g]     = m0;
        g_rowm[base + g + 8] = m1;
        g_rowl[base + g]     = 1.0f / l0;
        g_rowl[base + g + 8] = 1.0f / l1;
    }
}

// ---------------- pass 2: fused P write + P·V --------------------------------
__global__ __launch_bounds__(256, 2)
void attn_fused(const float* __restrict__ qh, const float* __restrict__ kh,
                const float* __restrict__ vt, float* __restrict__ attn,
                float* __restrict__ ctx)
{
    extern __shared__ float smKV[];
    float* Kb = smKV;                    // [2][64][KSTR]
    float* Vb = smKV + 2 * 64 * KSTR;    // [2][64][KSTR]  V^T: rows=d, cols=k

    const int z  = blockIdx.y;
    const int b  = z >> 4, h = z & 15;
    const int qb = blockIdx.x * 128;
    const float* Kz  = kh + (long)z * SEQ * 64;
    const float* Vtz = vt + (long)z * SEQ * 64;   // [64 d][2048 s]
    float* attnZ = attn + (long)z * SEQ * SEQ;

    const int tid  = threadIdx.x;
    const int warp = tid >> 5, lane = tid & 31;
    const int wm = warp * 16;
    const int g = lane >> 2, t = lane & 3;
    const int row0 = qb + wm + g, row1 = row0 + 8;

    unsigned aq[8][4];
    load_qfrag(aq, qh + (long)z * SEQ * 64, row0, t);

    const long sbase = (long)z * SEQ;
    const float m0  = g_rowm[sbase + row0];
    const float m1  = g_rowm[sbase + row1];
    const float iv0 = g_rowl[sbase + row0];
    const float iv1 = g_rowl[sbase + row1];
    const float scale = 0.125f;

    const unsigned kLane = (unsigned)__cvta_generic_to_shared(Kb) + ldsm_lane_off(lane, KSTR);
    const unsigned vLane = (unsigned)__cvta_generic_to_shared(Vb) + ldsm_lane_off(lane, KSTR);

    float oacc[8][4];
#pragma unroll
    for (int j = 0; j < 8; j++)
#pragma unroll
        for (int r = 0; r < 4; r++) oacc[j][r] = 0.f;

    const int sl = (lane & ~3) + (t >> 1);
    const int sh = sl + 2;

    cp_chunk(Kb, Kz, 64, tid);        CP_COMMIT();
    cp_chunk(Vb, Vtz, SEQ, tid);      CP_COMMIT();

    for (int ch = 0; ch < NCH; ch++) {
        if (ch + 1 < NCH) {
            const int st = (ch + 1) & 1;
            cp_chunk(Kb + st * 64 * KSTR, Kz + (long)(ch + 1) * 64 * 64, 64, tid);
            CP_COMMIT();
            cp_chunk(Vb + st * 64 * KSTR, Vtz + (long)(ch + 1) * 64, SEQ, tid);
            CP_COMMIT();
            CP_WAIT(2);
        } else {
            CP_WAIT(0);
        }
        __syncthreads();

        const unsigned kBuf = kLane + (unsigned)((ch & 1) * 64 * KSTR * 4);
        const unsigned vBuf = vLane + (unsigned)((ch & 1) * 64 * KSTR * 4);

        // ---- S = Q K^T for this 128x64 chunk ----
        float sacc[8][4];
#pragma unroll
        for (int j = 0; j < 8; j++)
#pragma unroll
            for (int r = 0; r < 4; r++) sacc[j][r] = 0.f;

#pragma unroll
        for (int kk = 0; kk < 8; kk++) {
#pragma unroll
            for (int jp = 0; jp < 4; jp++) {
                unsigned r0, r1, r2, r3;
                ldsm4(r0, r1, r2, r3,
                      kBuf + (unsigned)((jp * 16 * KSTR + kk * 8) * 4));
                r0 = cvtu(r0); r1 = cvtu(r1); r2 = cvtu(r2); r3 = cvtu(r3);
                mma_tf32(sacc[2 * jp],     aq[kk][0], aq[kk][1], aq[kk][2], aq[kk][3], r0, r1);
                mma_tf32(sacc[2 * jp + 1], aq[kk][0], aq[kk][1], aq[kk][2], aq[kk][3], r2, r3);
            }
        }

        // ---- p = exp(s*scale - m)*inv_l; write attn; PV mma ----
#pragma unroll
        for (int j = 0; j < 8; j++) {
            float p0 = __expf(sacc[j][0] * scale - m0) * iv0;
            float p1 = __expf(sacc[j][1] * scale - m0) * iv0;
            float p2 = __expf(sacc[j][2] * scale - m1) * iv1;
            float p3 = __expf(sacc[j][3] * scale - m1) * iv1;

            const int c = ch * 64 + j * 8 + 2 * t;
            float2 lo; lo.x = p0; lo.y = p1;
            float2 hi; hi.x = p2; hi.y = p3;
            *(float2*)(attnZ + (long)row0 * SEQ + c) = lo;
            *(float2*)(attnZ + (long)row1 * SEQ + c) = hi;

            // C-frag (cols 2t,2t+1) -> A-frag (cols t,t+4) via quad shuffles
            unsigned u0 = f2tf32(p0), u1 = f2tf32(p1);
            unsigned u2 = f2tf32(p2), u3 = f2tf32(p3);
            unsigned e, o, a0, a1, a2, a3;
            e = __shfl_sync(0xffffffffu, u0, sl);
            o = __shfl_sync(0xffffffffu, u1, sl);
            a0 = (t & 1) ? o : e;
            e = __shfl_sync(0xffffffffu, u0, sh);
            o = __shfl_sync(0xffffffffu, u1, sh);
            a2 = (t & 1) ? o : e;
            e = __shfl_sync(0xffffffffu, u2, sl);
            o = __shfl_sync(0xffffffffu, u3, sl);
            a1 = (t & 1) ? o : e;
            e = __shfl_sync(0xffffffffu, u2, sh);
            o = __shfl_sync(0xffffffffu, u3, sh);
            a3 = (t & 1) ? o : e;

            // PV B-frags via LDSM from V^T [d][k]
#pragma unroll
            for (int jdp = 0; jdp < 4; jdp++) {
                unsigned r0, r1, r2, r3;
                ldsm4(r0, r1, r2, r3,
                      vBuf + (unsigned)((jdp * 16 * KSTR + j * 8) * 4));
                r0 = cvtu(r0); r1 = cvtu(r1); r2 = cvtu(r2); r3 = cvtu(r3);
                mma_tf32(oacc[2 * jdp],     a0, a1, a2, a3, r0, r1);
                mma_tf32(oacc[2 * jdp + 1], a0, a1, a2, a3, r2, r3);
            }
        }
        __syncthreads();
    }

    // ---- write O to ctx[b, s, h*64+d] ----
#pragma unroll
    for (int j = 0; j < 8; j++) {
        const int d = j * 8 + 2 * t;
        float2 lo; lo.x = oacc[j][0]; lo.y = oacc[j][1];
        float2 hi; hi.x = oacc[j][2]; hi.y = oacc[j][3];
        *(float2*)(ctx + ((long)(b * SEQ + row0)) * DQ + h * 64 + d) = lo;
        *(float2*)(ctx + ((long)(b * SEQ + row1)) * DQ + h * 64 + d) = hi;
    }
}

// ---------------- pipelined tensor-core GEMM-NT body ------------------------
// MODE 0: C row-major [M,N].  MODE 1: scatter [z][s][64].  MODE 2: scatter [z][d][s].
template <int MODE>
__device__ __forceinline__
void gemm_body(const float* __restrict__ A, const float* __restrict__ Bm,
               float* __restrict__ C, int M, int N, int K, float alpha,
               unsigned* smem)
{
    constexpr int BM = 128, BN = 128, BK = 32;
    unsigned* As = smem;                    // [2][128][GSTR] raw fp32
    unsigned* Bs = smem + 2 * BM * GSTR;

    const int bm = blockIdx.y * BM;
    const int bn = blockIdx.x * BN;
    const int tid  = threadIdx.x;
    const int warp = tid >> 5, lane = tid & 31;
    const int wm = (warp >> 2) * 64;
    const int wn = (warp & 3) * 32;
    const int g = lane >> 2, t = lane & 3;

    const int lr = tid >> 3;
    const int lc = (tid & 7) * 4;

    // LDSM lane bases
    // A tiles: row = (l&7) + 8*((l>>3)&1), col-half = 4*(l>>4)
    const unsigned As_u = (unsigned)__cvta_generic_to_shared(As);
    const unsigned Bs_u = (unsigned)__cvta_generic_to_shared(Bs);
    const unsigned aLane = As_u
        + (unsigned)((((lane & 7) + 8 * ((lane >> 3) & 1)) * GSTR) * 4 + 16 * (lane >> 4));
    const unsigned bLane = Bs_u + ldsm_lane_off(lane, GSTR);

    float acc[4][4][4];
#pragma unroll
    for (int i = 0; i < 4; i++)
#pragma unroll
        for (int j = 0; j < 4; j++)
#pragma unroll
            for (int r = 0; r < 4; r++) acc[i][j][r] = 0.f;

    const int nt = K / BK;

    {
#pragma unroll
        for (int i = 0; i < 4; i++) {
            const int r = lr + i * 32;
            cp16(&As[r * GSTR + lc], A  + (long)(bm + r) * K + lc);
            cp16(&Bs[r * GSTR + lc], Bm + (long)(bn + r) * K + lc);
        }
        CP_COMMIT();
    }

    for (int kt = 0; kt < nt; kt++) {
        if (kt + 1 < nt) {
            const int st = (kt + 1) & 1;
            const int k0 = (kt + 1) * BK;
            unsigned* Ad = As + st * BM * GSTR;
            unsigned* Bd = Bs + st * BM * GSTR;
#pragma unroll
            for (int i = 0; i < 4; i++) {
                const int r = lr + i * 32;
                cp16(&Ad[r * GSTR + lc], A  + (long)(bm + r) * K + k0 + lc);
                cp16(&Bd[r * GSTR + lc], Bm + (long)(bn + r) * K + k0 + lc);
            }
            CP_COMMIT();
            CP_WAIT(1);
        } else {
            CP_WAIT(0);
        }
        __syncthreads();

        const unsigned bufOff = (unsigned)((kt & 1) * BM * GSTR * 4);
        const unsigned aB = aLane + bufOff;
        const unsigned bB = bLane + bufOff;

#pragma unroll
        for (int kk = 0; kk < BK; kk += 8) {
            unsigned af[4][4], bf[4][2];
#pragma unroll
            for (int i = 0; i < 4; i++) {
                ldsm4(af[i][0], af[i][1], af[i][2], af[i][3],
                      aB + (unsigned)(((wm + i * 16) * GSTR + kk) * 4));
                af[i][0] = cvtu(af[i][0]); af[i][1] = cvtu(af[i][1]);
                af[i][2] = cvtu(af[i][2]); af[i][3] = cvtu(af[i][3]);
            }
#pragma unroll
            for (int jp = 0; jp < 2; jp++) {
                unsigned r0, r1, r2, r3;
                ldsm4(r0, r1, r2, r3,
                      bB + (unsigned)(((wn + jp * 16) * GSTR + kk) * 4));
                bf[2 * jp][0]     = cvtu(r0);
                bf[2 * jp][1]     = cvtu(r1);
                bf[2 * jp + 1][0] = cvtu(r2);
                bf[2 * jp + 1][1] = cvtu(r3);
            }
#pragma unroll
            for (int i = 0; i < 4; i++)
#pragma unroll
                for (int j = 0; j < 4; j++)
                    mma_tf32(acc[i][j], af[i][0], af[i][1], af[i][2], af[i][3],
                             bf[j][0], bf[j][1]);
        }
        __syncthreads();
    }

#pragma unroll
    for (int i = 0; i < 4; i++) {
#pragma unroll
        for (int j = 0; j < 4; j++) {
            const int mrow = bm + wm + i * 16 + g;
            const int ncol = bn + wn + j * 8 + 2 * t;
            float2 lo, hi;
            lo.x = alpha * acc[i][j][0]; lo.y = alpha * acc[i][j][1];
            hi.x = alpha * acc[i][j][2]; hi.y = alpha * acc[i][j][3];
            if (MODE == 0) {
                *(float2*)(C + (long)mrow * N + ncol)       = lo;
                *(float2*)(C + (long)(mrow + 8) * N + ncol) = hi;
            } else if (MODE == 1) {
                const int h = ncol >> 6, d = ncol & 63;
                int b0 = mrow >> 11, s0 = mrow & 2047;
                *(float2*)(C + ((long)((b0 * NHEAD + h) * SEQ + s0)) * 64 + d) = lo;
                int m2 = mrow + 8;
                int b1 = m2 >> 11, s1 = m2 & 2047;
                *(float2*)(C + ((long)((b1 * NHEAD + h) * SEQ + s1)) * 64 + d) = hi;
            } else {
                // V transposed: [z][d][s]
                const int h = ncol >> 6, d = ncol & 63;
                int b0 = mrow >> 11, s0 = mrow & 2047;
                float* p0 = C + ((long)((b0 * NHEAD + h) * 64 + d)) * SEQ + s0;
                p0[0]   = lo.x;
                p0[SEQ] = lo.y;
                int m2 = mrow + 8;
                int b1 = m2 >> 11, s1 = m2 & 2047;
                float* p1 = C + ((long)((b1 * NHEAD + h) * 64 + d)) * SEQ + s1;
                p1[0]   = hi.x;
                p1[SEQ] = hi.y;
            }
        }
    }
}

__global__ __launch_bounds__(256, 2)
void gemm_fc(const float* __restrict__ A, const float* __restrict__ Bm,
             float* __restrict__ C, int M, int N, int K, float alpha)
{
    extern __shared__ unsigned smemg[];
    gemm_body<0>(A, Bm, C, M, N, K, alpha, smemg);
}

struct Proj3 {
    const float *A0, *A1, *A2;
    const float *B0, *B1, *B2;
    float *C0, *C1, *C2;
};

__global__ __launch_bounds__(256, 2)
void gemm_proj3(Proj3 p, int M, int N, int K)
{
    extern __shared__ unsigned smemg[];
    if (blockIdx.z == 0)      gemm_body<1>(p.A0, p.B0, p.C0, M, N, K, 1.0f, smemg);
    else if (blockIdx.z == 1) gemm_body<1>(p.A1, p.B1, p.C1, M, N, K, 1.0f, smemg);
    else                      gemm_body<2>(p.A2, p.B2, p.C2, M, N, K, 1.0f, smemg);
}

// ---------------- residual add + LayerNorm ----------------------------------
__global__ __launch_bounds__(256)
void add_ln_kernel(const float* __restrict__ fc, const float* __restrict__ res,
                   const float* __restrict__ gamma, const float* __restrict__ beta,
                   float* __restrict__ out)
{
    const long row = blockIdx.x;
    const int tid = threadIdx.x;
    float4 f = ((const float4*)(fc  + row * DQ))[tid];
    float4 r = ((const float4*)(res + row * DQ))[tid];
    float x0 = f.x + r.x, x1 = f.y + r.y, x2 = f.z + r.z, x3 = f.w + r.w;

    float s  = x0 + x1 + x2 + x3;
    float sq = x0 * x0 + x1 * x1 + x2 * x2 + x3 * x3;
#pragma unroll
    for (int off = 16; off > 0; off >>= 1) {
        s  += __shfl_xor_sync(0xffffffffu, s,  off);
        sq += __shfl_xor_sync(0xffffffffu, sq, off);
    }
    __shared__ float rs[8], rq[8];
    const int wid = tid >> 5, lane = tid & 31;
    if (lane == 0) { rs[wid] = s; rq[wid] = sq; }
    __syncthreads();
    float S = 0.f, SQ = 0.f;
#pragma unroll
    for (int w = 0; w < 8; w++) { S += rs[w]; SQ += rq[w]; }

    const float mu  = S * (1.0f / DQ);
    const float var = SQ * (1.0f / DQ) - mu * mu;
    const float rstd = rsqrtf(var + 1e-6f);

    float4 g  = ((const float4*)gamma)[tid];
    float4 be = ((const float4*)beta)[tid];
    float4 o;
    o.x = (x0 - mu) * rstd * g.x + be.x;
    o.y = (x1 - mu) * rstd * g.y + be.y;
    o.z = (x2 - mu) * rstd * g.z + be.z;
    o.w = (x3 - mu) * rstd * g.w + be.w;
    ((float4*)(out + row * DQ))[tid] = o;
}

// ---------------- launcher --------------------------------------------------
extern "C" void kernel_launch(void* const* d_in, const int* in_sizes, int n_in,
                              void* d_out, int out_size)
{
    const float* q    = (const float*)d_in[0];
    const float* k    = (const float*)d_in[1];
    const float* v    = (const float*)d_in[2];
    const float* w_q  = (const float*)d_in[3];
    const float* w_k  = (const float*)d_in[4];
    const float* w_v  = (const float*)d_in[5];
    const float* w_fc = (const float*)d_in[6];
    const float* ga   = (const float*)d_in[7];
    const float* be   = (const float*)d_in[8];
    float* out = (float*)d_out;

    float *qh, *kh, *vh, *ctx, *fc, *attn_fb;
    cudaGetSymbolAddress((void**)&qh,      g_qh);
    cudaGetSymbolAddress((void**)&kh,      g_kh);
    cudaGetSymbolAddress((void**)&vh,      g_vh);
    cudaGetSymbolAddress((void**)&ctx,     g_ctx);
    cudaGetSymbolAddress((void**)&fc,      g_fc);
    cudaGetSymbolAddress((void**)&attn_fb, g_attn_fb);

    float* attn;
    bool write_out = true;
    if ((long)out_size >= OUT_ELEMS + ATTN_ELEMS) {
        attn = out + OUT_ELEMS;
    } else if ((long)out_size == ATTN_ELEMS) {
        attn = out;
        write_out = false;
    } else {
        attn = attn_fb;
    }

    const int STATS_SMEM = 2 * 64 * KSTR * 4;     // 34,816 B
    const int FUSED_SMEM = 4 * 64 * KSTR * 4;     // 69,632 B
    const int GEMM_SMEM  = 4 * 128 * GSTR * 4;    // 73,728 B
    static bool attr_done = false;
    if (!attr_done) {
        cudaFuncSetAttribute(attn_stats, cudaFuncAttributeMaxDynamicSharedMemorySize, STATS_SMEM);
        cudaFuncSetAttribute(attn_fused, cudaFuncAttributeMaxDynamicSharedMemorySize, FUSED_SMEM);
        cudaFuncSetAttribute(gemm_fc,    cudaFuncAttributeMaxDynamicSharedMemorySize, GEMM_SMEM);
        cudaFuncSetAttribute(gemm_proj3, cudaFuncAttributeMaxDynamicSharedMemorySize, GEMM_SMEM);
        attr_done = true;
    }

    // projections (merged): z=0,1 -> [z][s][64]; z=2 (V) -> transposed [z][d][s]
    Proj3 p;
    p.A0 = q;  p.A1 = k;  p.A2 = v;
    p.B0 = w_q; p.B1 = w_k; p.B2 = w_v;
    p.C0 = qh; p.C1 = kh; p.C2 = vh;
    gemm_proj3<<<dim3(8, 64, 3), 256, GEMM_SMEM>>>(p, MROWS, DQ, DQ);

    // pass 1: softmax row stats
    attn_stats<<<dim3(16, 64), 256, STATS_SMEM>>>(qh, kh);

    // pass 2: recompute S, write normalized P once, fused register-P · V^T
    attn_fused<<<dim3(16, 64), 256, FUSED_SMEM>>>(qh, kh, vh, attn, ctx);

    if (write_out) {
        gemm_fc<<<dim3(8, 64, 1), 256, GEMM_SMEM>>>(ctx, w_fc, fc, MROWS, DQ, DQ, 1.0f);
        add_ln_kernel<<<MROWS, 256>>>(fc, q, ga, be, out);
    }
}

// round 9
// speedup vs baseline: 1.3984x; 1.0595x over previous
#include <cuda_runtime.h>
#include <cuda_bf16.h>

// Problem constants
#define NHEAD 16
#define DQ    1024
#define DKEY  64
#define BATCH 4
#define SEQ   2048
#define MROWS (BATCH * SEQ)          // 8192
#define OUT_ELEMS  (8192L * 1024L)           // 8,388,608
#define ATTN_ELEMS (64L * 2048L * 2048L)     // 268,435,456

// ---------------- scratch ---------------------------------------------------
__device__ float g_qh[MROWS * DQ];     // [z][s][64]  tf32-rounded
__device__ float g_kh[MROWS * DQ];     // [z][s][64]  tf32-rounded
__device__ float g_vh[MROWS * DQ];     // TRANSPOSED [z][d][s], tf32-rounded
__device__ float g_ctx[MROWS * DQ];    // [B,S,H*64], tf32-rounded
__device__ float g_fc[MROWS * DQ];
__device__ float g_wfc[DQ * DQ];       // tf32-rounded copy of w_fc
__device__ float g_rowm[64 * SEQ];
__device__ float g_rowl[64 * SEQ];
__device__ float g_attn_fb[ATTN_ELEMS];

// ---------------- helpers ----------------------------------------------------
__device__ __forceinline__ unsigned f2tf32(float x) {
    unsigned r;
    asm("cvt.rna.tf32.f32 %0, %1;" : "=r"(r) : "f"(x));
    return r;
}
__device__ __forceinline__ float rnd(float x) { return __uint_as_float(f2tf32(x)); }
__device__ __forceinline__ unsigned cvtu(unsigned x) {
    return f2tf32(__uint_as_float(x));
}

__device__ __forceinline__ void mma_tf32(float c[4],
                                         unsigned a0, unsigned a1, unsigned a2, unsigned a3,
                                         unsigned b0, unsigned b1) {
    asm volatile(
        "mma.sync.aligned.m16n8k8.row.col.f32.tf32.tf32.f32 "
        "{%0,%1,%2,%3}, {%4,%5,%6,%7}, {%8,%9}, {%0,%1,%2,%3};"
        : "+f"(c[0]), "+f"(c[1]), "+f"(c[2]), "+f"(c[3])
        : "r"(a0), "r"(a1), "r"(a2), "r"(a3), "r"(b0), "r"(b1));
}

__device__ __forceinline__ void ldsm4(unsigned& r0, unsigned& r1,
                                      unsigned& r2, unsigned& r3, unsigned addr) {
    asm volatile("ldmatrix.sync.aligned.m8n8.x4.shared.b16 {%0,%1,%2,%3}, [%4];"
                 : "=r"(r0), "=r"(r1), "=r"(r2), "=r"(r3) : "r"(addr));
}

__device__ __forceinline__ void cp16(void* smem_dst, const void* gsrc) {
    unsigned saddr = (unsigned)__cvta_generic_to_shared(smem_dst);
    asm volatile("cp.async.cg.shared.global [%0], [%1], 16;" :: "r"(saddr), "l"(gsrc));
}
#define CP_COMMIT() asm volatile("cp.async.commit_group;")
#define CP_WAIT(n)  asm volatile("cp.async.wait_group %0;" :: "n"(n) : "memory")

#define KSTR 68     // fp32 smem stride for 64-wide tiles (LDSM-conflict-free)
#define GSTR 36     // gemm smem stride
#define NCH  (SEQ / 64)

// Q fragments (values in gmem already tf32-rounded -> raw bit loads)
__device__ __forceinline__ void load_qfrag(unsigned aq[8][4], const float* Qz,
                                           int row0, int t)
{
    const unsigned* Q0 = (const unsigned*)(Qz + (long)row0 * 64);
    const unsigned* Q1 = Q0 + 8 * 64;
#pragma unroll
    for (int k8 = 0; k8 < 8; k8++) {
        aq[k8][0] = Q0[k8 * 8 + t];
        aq[k8][1] = Q1[k8 * 8 + t];
        aq[k8][2] = Q0[k8 * 8 + t + 4];
        aq[k8][3] = Q1[k8 * 8 + t + 4];
    }
}

__device__ __forceinline__ void cp_chunk(float* dst, const float* src,
                                         long gstride, int tid)
{
#pragma unroll
    for (int i = 0; i < 4; i++) {
        const int idx = tid + i * 256;
        const int r = idx >> 4, c4 = (idx & 15) * 4;
        cp16(&dst[r * KSTR + c4], src + (long)r * gstride + c4);
    }
}

__device__ __forceinline__ unsigned ldsm_lane_off(int lane, int stride)
{
    return (unsigned)((((lane >> 4) * 8 + (lane & 7)) * stride) * 4
                      + 16 * ((lane >> 3) & 1));
}

// ---------------- pass 1: softmax row stats ---------------------------------
__global__ __launch_bounds__(256, 2)
void attn_stats(const float* __restrict__ qh, const float* __restrict__ kh)
{
    extern __shared__ float smK[];     // [2][64][KSTR]

    const int z  = blockIdx.y;
    const int qb = blockIdx.x * 128;
    const float* Kz = kh + (long)z * SEQ * 64;

    const int tid = threadIdx.x;
    const int warp = tid >> 5, lane = tid & 31;
    const int wm = warp * 16;
    const int g = lane >> 2, t = lane & 3;
    const int row0 = qb + wm + g;

    unsigned aq[8][4];
    load_qfrag(aq, qh + (long)z * SEQ * 64, row0, t);

    const unsigned kLane = (unsigned)__cvta_generic_to_shared(smK) + ldsm_lane_off(lane, KSTR);

    const float scale = 0.125f;
    float m0 = -1e30f, m1 = -1e30f, l0 = 0.f, l1 = 0.f;

    cp_chunk(smK, Kz, 64, tid);
    CP_COMMIT();

    for (int ch = 0; ch < NCH; ch++) {
        if (ch + 1 < NCH) {
            cp_chunk(smK + ((ch + 1) & 1) * 64 * KSTR,
                     Kz + (long)(ch + 1) * 64 * 64, 64, tid);
            CP_COMMIT();
            CP_WAIT(1);
        } else {
            CP_WAIT(0);
        }
        __syncthreads();

        const unsigned kBuf = kLane + (unsigned)((ch & 1) * 64 * KSTR * 4);

        float sacc[8][4];
#pragma unroll
        for (int j = 0; j < 8; j++)
#pragma unroll
            for (int r = 0; r < 4; r++) sacc[j][r] = 0.f;

#pragma unroll
        for (int kk = 0; kk < 8; kk++) {
#pragma unroll
            for (int jp = 0; jp < 4; jp++) {
                unsigned r0, r1, r2, r3;
                ldsm4(r0, r1, r2, r3,
                      kBuf + (unsigned)((jp * 16 * KSTR + kk * 8) * 4));
                mma_tf32(sacc[2 * jp],     aq[kk][0], aq[kk][1], aq[kk][2], aq[kk][3], r0, r1);
                mma_tf32(sacc[2 * jp + 1], aq[kk][0], aq[kk][1], aq[kk][2], aq[kk][3], r2, r3);
            }
        }

        float t0 = -1e30f, t1 = -1e30f;
#pragma unroll
        for (int j = 0; j < 8; j++) {
            t0 = fmaxf(t0, fmaxf(sacc[j][0], sacc[j][1]));
            t1 = fmaxf(t1, fmaxf(sacc[j][2], sacc[j][3]));
        }
        t0 *= scale; t1 *= scale;
        t0 = fmaxf(t0, __shfl_xor_sync(0xffffffffu, t0, 1));
        t0 = fmaxf(t0, __shfl_xor_sync(0xffffffffu, t0, 2));
        t1 = fmaxf(t1, __shfl_xor_sync(0xffffffffu, t1, 1));
        t1 = fmaxf(t1, __shfl_xor_sync(0xffffffffu, t1, 2));

        float m0n = fmaxf(m0, t0), m1n = fmaxf(m1, t1);
        float s0 = 0.f, s1 = 0.f;
#pragma unroll
        for (int j = 0; j < 8; j++) {
            s0 += __expf(sacc[j][0] * scale - m0n) + __expf(sacc[j][1] * scale - m0n);
            s1 += __expf(sacc[j][2] * scale - m1n) + __expf(sacc[j][3] * scale - m1n);
        }
        s0 += __shfl_xor_sync(0xffffffffu, s0, 1);
        s0 += __shfl_xor_sync(0xffffffffu, s0, 2);
        s1 += __shfl_xor_sync(0xffffffffu, s1, 1);
        s1 += __shfl_xor_sync(0xffffffffu, s1, 2);

        l0 = l0 * __expf(m0 - m0n) + s0;
        l1 = l1 * __expf(m1 - m1n) + s1;
        m0 = m0n; m1 = m1n;
        __syncthreads();
    }

    if (t == 0) {
        const long base = (long)z * SEQ + qb + wm;
        g_rowm[base + g]     = m0;
        g_rowm[base + g + 8] = m1;
        g_rowl[base + g]     = 1.0f / l0;
        g_rowl[base + g + 8] = 1.0f / l1;
    }
}

// ---------------- pass 2: fused P write + P·V --------------------------------
__global__ __launch_bounds__(256, 2)
void attn_fused(const float* __restrict__ qh, const float* __restrict__ kh,
                const float* __restrict__ vt, float* __restrict__ attn,
                float* __restrict__ ctx)
{
    extern __shared__ float smKV[];
    float* Kb = smKV;                    // [2][64][KSTR]
    float* Vb = smKV + 2 * 64 * KSTR;    // [2][64][KSTR]  V^T: rows=d, cols=k

    const int z  = blockIdx.y;
    const int b  = z >> 4, h = z & 15;
    const int qb = blockIdx.x * 128;
    const float* Kz  = kh + (long)z * SEQ * 64;
    const float* Vtz = vt + (long)z * SEQ * 64;
    float* attnZ = attn + (long)z * SEQ * SEQ;

    const int tid  = threadIdx.x;
    const int warp = tid >> 5, lane = tid & 31;
    const int wm = warp * 16;
    const int g = lane >> 2, t = lane & 3;
    const int row0 = qb + wm + g, row1 = row0 + 8;

    unsigned aq[8][4];
    load_qfrag(aq, qh + (long)z * SEQ * 64, row0, t);

    const long sbase = (long)z * SEQ;
    const float m0  = g_rowm[sbase + row0];
    const float m1  = g_rowm[sbase + row1];
    const float iv0 = g_rowl[sbase + row0];
    const float iv1 = g_rowl[sbase + row1];
    const float scale = 0.125f;

    const unsigned kLane = (unsigned)__cvta_generic_to_shared(Kb) + ldsm_lane_off(lane, KSTR);
    const unsigned vLane = (unsigned)__cvta_generic_to_shared(Vb) + ldsm_lane_off(lane, KSTR);

    float oacc[8][4];
#pragma unroll
    for (int j = 0; j < 8; j++)
#pragma unroll
        for (int r = 0; r < 4; r++) oacc[j][r] = 0.f;

    const int sl = (lane & ~3) + (t >> 1);
    const int sh = sl + 2;

    cp_chunk(Kb, Kz, 64, tid);        CP_COMMIT();
    cp_chunk(Vb, Vtz, SEQ, tid);      CP_COMMIT();

    for (int ch = 0; ch < NCH; ch++) {
        if (ch + 1 < NCH) {
            const int st = (ch + 1) & 1;
            cp_chunk(Kb + st * 64 * KSTR, Kz + (long)(ch + 1) * 64 * 64, 64, tid);
            CP_COMMIT();
            cp_chunk(Vb + st * 64 * KSTR, Vtz + (long)(ch + 1) * 64, SEQ, tid);
            CP_COMMIT();
            CP_WAIT(2);
        } else {
            CP_WAIT(0);
        }
        __syncthreads();

        const unsigned kBuf = kLane + (unsigned)((ch & 1) * 64 * KSTR * 4);
        const unsigned vBuf = vLane + (unsigned)((ch & 1) * 64 * KSTR * 4);

        float sacc[8][4];
#pragma unroll
        for (int j = 0; j < 8; j++)
#pragma unroll
            for (int r = 0; r < 4; r++) sacc[j][r] = 0.f;

#pragma unroll
        for (int kk = 0; kk < 8; kk++) {
#pragma unroll
            for (int jp = 0; jp < 4; jp++) {
                unsigned r0, r1, r2, r3;
                ldsm4(r0, r1, r2, r3,
                      kBuf + (unsigned)((jp * 16 * KSTR + kk * 8) * 4));
                mma_tf32(sacc[2 * jp],     aq[kk][0], aq[kk][1], aq[kk][2], aq[kk][3], r0, r1);
                mma_tf32(sacc[2 * jp + 1], aq[kk][0], aq[kk][1], aq[kk][2], aq[kk][3], r2, r3);
            }
        }

#pragma unroll
        for (int j = 0; j < 8; j++) {
            float p0 = __expf(sacc[j][0] * scale - m0) * iv0;
            float p1 = __expf(sacc[j][1] * scale - m0) * iv0;
            float p2 = __expf(sacc[j][2] * scale - m1) * iv1;
            float p3 = __expf(sacc[j][3] * scale - m1) * iv1;

            const int c = ch * 64 + j * 8 + 2 * t;
            float2 lo; lo.x = p0; lo.y = p1;
            float2 hi; hi.x = p2; hi.y = p3;
            *(float2*)(attnZ + (long)row0 * SEQ + c) = lo;
            *(float2*)(attnZ + (long)row1 * SEQ + c) = hi;

            unsigned u0 = f2tf32(p0), u1 = f2tf32(p1);
            unsigned u2 = f2tf32(p2), u3 = f2tf32(p3);
            unsigned e, o, a0, a1, a2, a3;
            e = __shfl_sync(0xffffffffu, u0, sl);
            o = __shfl_sync(0xffffffffu, u1, sl);
            a0 = (t & 1) ? o : e;
            e = __shfl_sync(0xffffffffu, u0, sh);
            o = __shfl_sync(0xffffffffu, u1, sh);
            a2 = (t & 1) ? o : e;
            e = __shfl_sync(0xffffffffu, u2, sl);
            o = __shfl_sync(0xffffffffu, u3, sl);
            a1 = (t & 1) ? o : e;
            e = __shfl_sync(0xffffffffu, u2, sh);
            o = __shfl_sync(0xffffffffu, u3, sh);
            a3 = (t & 1) ? o : e;

#pragma unroll
            for (int jdp = 0; jdp < 4; jdp++) {
                unsigned r0, r1, r2, r3;
                ldsm4(r0, r1, r2, r3,
                      vBuf + (unsigned)((jdp * 16 * KSTR + j * 8) * 4));
                mma_tf32(oacc[2 * jdp],     a0, a1, a2, a3, r0, r1);
                mma_tf32(oacc[2 * jdp + 1], a0, a1, a2, a3, r2, r3);
            }
        }
        __syncthreads();
    }

    // ---- write O (tf32-rounded: consumed only by gemm_fc) ----
#pragma unroll
    for (int j = 0; j < 8; j++) {
        const int d = j * 8 + 2 * t;
        float2 lo; lo.x = rnd(oacc[j][0]); lo.y = rnd(oacc[j][1]);
        float2 hi; hi.x = rnd(oacc[j][2]); hi.y = rnd(oacc[j][3]);
        *(float2*)(ctx + ((long)(b * SEQ + row0)) * DQ + h * 64 + d) = lo;
        *(float2*)(ctx + ((long)(b * SEQ + row1)) * DQ + h * 64 + d) = hi;
    }
}

// ---------------- pipelined tensor-core GEMM-NT body ------------------------
// MODE 0: C row-major.  MODE 1: scatter [z][s][64].  MODE 2: scatter [z][d][s].
// CVT: convert fragments to tf32 after LDSM.  RND: round outputs to tf32.
template <int MODE, bool CVT, bool RND>
__device__ __forceinline__
void gemm_body(const float* __restrict__ A, const float* __restrict__ Bm,
               float* __restrict__ C, int M, int N, int K, float alpha,
               unsigned* smem)
{
    constexpr int BM = 128, BN = 128, BK = 32;
    unsigned* As = smem;
    unsigned* Bs = smem + 2 * BM * GSTR;

    const int bm = blockIdx.y * BM;
    const int bn = blockIdx.x * BN;
    const int tid  = threadIdx.x;
    const int warp = tid >> 5, lane = tid & 31;
    const int wm = (warp >> 2) * 64;
    const int wn = (warp & 3) * 32;
    const int g = lane >> 2, t = lane & 3;

    const int lr = tid >> 3;
    const int lc = (tid & 7) * 4;

    const unsigned As_u = (unsigned)__cvta_generic_to_shared(As);
    const unsigned Bs_u = (unsigned)__cvta_generic_to_shared(Bs);
    const unsigned aLane = As_u
        + (unsigned)((((lane & 7) + 8 * ((lane >> 3) & 1)) * GSTR) * 4 + 16 * (lane >> 4));
    const unsigned bLane = Bs_u + ldsm_lane_off(lane, GSTR);

    float acc[4][4][4];
#pragma unroll
    for (int i = 0; i < 4; i++)
#pragma unroll
        for (int j = 0; j < 4; j++)
#pragma unroll
            for (int r = 0; r < 4; r++) acc[i][j][r] = 0.f;

    const int nt = K / BK;

    {
#pragma unroll
        for (int i = 0; i < 4; i++) {
            const int r = lr + i * 32;
            cp16(&As[r * GSTR + lc], A  + (long)(bm + r) * K + lc);
            cp16(&Bs[r * GSTR + lc], Bm + (long)(bn + r) * K + lc);
        }
        CP_COMMIT();
    }

    for (int kt = 0; kt < nt; kt++) {
        if (kt + 1 < nt) {
            const int st = (kt + 1) & 1;
            const int k0 = (kt + 1) * BK;
            unsigned* Ad = As + st * BM * GSTR;
            unsigned* Bd = Bs + st * BM * GSTR;
#pragma unroll
            for (int i = 0; i < 4; i++) {
                const int r = lr + i * 32;
                cp16(&Ad[r * GSTR + lc], A  + (long)(bm + r) * K + k0 + lc);
                cp16(&Bd[r * GSTR + lc], Bm + (long)(bn + r) * K + k0 + lc);
            }
            CP_COMMIT();
            CP_WAIT(1);
        } else {
            CP_WAIT(0);
        }
        __syncthreads();

        const unsigned bufOff = (unsigned)((kt & 1) * BM * GSTR * 4);
        const unsigned aB = aLane + bufOff;
        const unsigned bB = bLane + bufOff;

#pragma unroll
        for (int kk = 0; kk < BK; kk += 8) {
            unsigned af[4][4], bf[4][2];
#pragma unroll
            for (int i = 0; i < 4; i++) {
                ldsm4(af[i][0], af[i][1], af[i][2], af[i][3],
                      aB + (unsigned)(((wm + i * 16) * GSTR + kk) * 4));
                if (CVT) {
                    af[i][0] = cvtu(af[i][0]); af[i][1] = cvtu(af[i][1]);
                    af[i][2] = cvtu(af[i][2]); af[i][3] = cvtu(af[i][3]);
                }
            }
#pragma unroll
            for (int jp = 0; jp < 2; jp++) {
                unsigned r0, r1, r2, r3;
                ldsm4(r0, r1, r2, r3,
                      bB + (unsigned)(((wn + jp * 16) * GSTR + kk) * 4));
                if (CVT) { r0 = cvtu(r0); r1 = cvtu(r1); r2 = cvtu(r2); r3 = cvtu(r3); }
                bf[2 * jp][0]     = r0;
                bf[2 * jp][1]     = r1;
                bf[2 * jp + 1][0] = r2;
                bf[2 * jp + 1][1] = r3;
            }
#pragma unroll
            for (int i = 0; i < 4; i++)
#pragma unroll
                for (int j = 0; j < 4; j++)
                    mma_tf32(acc[i][j], af[i][0], af[i][1], af[i][2], af[i][3],
                             bf[j][0], bf[j][1]);
        }
        __syncthreads();
    }

#pragma unroll
    for (int i = 0; i < 4; i++) {
#pragma unroll
        for (int j = 0; j < 4; j++) {
            const int mrow = bm + wm + i * 16 + g;
            const int ncol = bn + wn + j * 8 + 2 * t;
            float v0 = alpha * acc[i][j][0], v1 = alpha * acc[i][j][1];
            float v2 = alpha * acc[i][j][2], v3 = alpha * acc[i][j][3];
            if (RND) { v0 = rnd(v0); v1 = rnd(v1); v2 = rnd(v2); v3 = rnd(v3); }
            float2 lo; lo.x = v0; lo.y = v1;
            float2 hi; hi.x = v2; hi.y = v3;
            if (MODE == 0) {
                *(float2*)(C + (long)mrow * N + ncol)       = lo;
                *(float2*)(C + (long)(mrow + 8) * N + ncol) = hi;
            } else if (MODE == 1) {
                const int h = ncol >> 6, d = ncol & 63;
                int b0 = mrow >> 11, s0 = mrow & 2047;
                *(float2*)(C + ((long)((b0 * NHEAD + h) * SEQ + s0)) * 64 + d) = lo;
                int m2 = mrow + 8;
                int b1 = m2 >> 11, s1 = m2 & 2047;
                *(float2*)(C + ((long)((b1 * NHEAD + h) * SEQ + s1)) * 64 + d) = hi;
            } else {
                const int h = ncol >> 6, d = ncol & 63;
                int b0 = mrow >> 11, s0 = mrow & 2047;
                float* p0 = C + ((long)((b0 * NHEAD + h) * 64 + d)) * SEQ + s0;
                p0[0]   = lo.x;
                p0[SEQ] = lo.y;
                int m2 = mrow + 8;
                int b1 = m2 >> 11, s1 = m2 & 2047;
                float* p1 = C + ((long)((b1 * NHEAD + h) * 64 + d)) * SEQ + s1;
                p1[0]   = hi.x;
                p1[SEQ] = hi.y;
            }
        }
    }
}

__global__ __launch_bounds__(256, 2)
void gemm_fc(const float* __restrict__ A, const float* __restrict__ Bm,
             float* __restrict__ C, int M, int N, int K, float alpha)
{
    extern __shared__ unsigned smemg[];
    gemm_body<0, false, false>(A, Bm, C, M, N, K, alpha, smemg);
}

struct Proj3 {
    const float *A0, *A1, *A2;
    const float *B0, *B1, *B2;
    float *C0, *C1, *C2;
};

__global__ __launch_bounds__(256, 2)
void gemm_proj3(Proj3 p, int M, int N, int K)
{
    extern __shared__ unsigned smemg[];
    if (blockIdx.z == 0)      gemm_body<1, true, true>(p.A0, p.B0, p.C0, M, N, K, 1.0f, smemg);
    else if (blockIdx.z == 1) gemm_body<1, true, true>(p.A1, p.B1, p.C1, M, N, K, 1.0f, smemg);
    else                      gemm_body<2, true, true>(p.A2, p.B2, p.C2, M, N, K, 1.0f, smemg);
}

// ---------------- w_fc pre-round --------------------------------------------
__global__ __launch_bounds__(256)
void round_wfc(const float* __restrict__ src, float* __restrict__ dst)
{
    const int i = blockIdx.x * 256 + threadIdx.x;
    float4 v = ((const float4*)src)[i];
    v.x = rnd(v.x); v.y = rnd(v.y); v.z = rnd(v.z); v.w = rnd(v.w);
    ((float4*)dst)[i] = v;
}

// ---------------- residual add + LayerNorm ----------------------------------
__global__ __launch_bounds__(256)
void add_ln_kernel(const float* __restrict__ fc, const float* __restrict__ res,
                   const float* __restrict__ gamma, const float* __restrict__ beta,
                   float* __restrict__ out)
{
    const long row = blockIdx.x;
    const int tid = threadIdx.x;
    float4 f = ((const float4*)(fc  + row * DQ))[tid];
    float4 r = ((const float4*)(res + row * DQ))[tid];
    float x0 = f.x + r.x, x1 = f.y + r.y, x2 = f.z + r.z, x3 = f.w + r.w;

    float s  = x0 + x1 + x2 + x3;
    float sq = x0 * x0 + x1 * x1 + x2 * x2 + x3 * x3;
#pragma unroll
    for (int off = 16; off > 0; off >>= 1) {
        s  += __shfl_xor_sync(0xffffffffu, s,  off);
        sq += __shfl_xor_sync(0xffffffffu, sq, off);
    }
    __shared__ float rs[8], rq[8];
    const int wid = tid >> 5, lane = tid & 31;
    if (lane == 0) { rs[wid] = s; rq[wid] = sq; }
    __syncthreads();
    float S = 0.f, SQ = 0.f;
#pragma unroll
    for (int w = 0; w < 8; w++) { S += rs[w]; SQ += rq[w]; }

    const float mu  = S * (1.0f / DQ);
    const float var = SQ * (1.0f / DQ) - mu * mu;
    const float rstd = rsqrtf(var + 1e-6f);

    float4 g  = ((const float4*)gamma)[tid];
    float4 be = ((const float4*)beta)[tid];
    float4 o;
    o.x = (x0 - mu) * rstd * g.x + be.x;
    o.y = (x1 - mu) * rstd * g.y + be.y;
    o.z = (x2 - mu) * rstd * g.z + be.z;
    o.w = (x3 - mu) * rstd * g.w + be.w;
    ((float4*)(out + row * DQ))[tid] = o;
}

// ---------------- launcher --------------------------------------------------
extern "C" void kernel_launch(void* const* d_in, const int* in_sizes, int n_in,
                              void* d_out, int out_size)
{
    const float* q    = (const float*)d_in[0];
    const float* k    = (const float*)d_in[1];
    const float* v    = (const float*)d_in[2];
    const float* w_q  = (const float*)d_in[3];
    const float* w_k  = (const float*)d_in[4];
    const float* w_v  = (const float*)d_in[5];
    const float* w_fc = (const float*)d_in[6];
    const float* ga   = (const float*)d_in[7];
    const float* be   = (const float*)d_in[8];
    float* out = (float*)d_out;

    float *qh, *kh, *vh, *ctx, *fc, *wfc, *attn_fb;
    cudaGetSymbolAddress((void**)&qh,      g_qh);
    cudaGetSymbolAddress((void**)&kh,      g_kh);
    cudaGetSymbolAddress((void**)&vh,      g_vh);
    cudaGetSymbolAddress((void**)&ctx,     g_ctx);
    cudaGetSymbolAddress((void**)&fc,      g_fc);
    cudaGetSymbolAddress((void**)&wfc,     g_wfc);
    cudaGetSymbolAddress((void**)&attn_fb, g_attn_fb);

    float* attn;
    bool write_out = true;
    if ((long)out_size >= OUT_ELEMS + ATTN_ELEMS) {
        attn = out + OUT_ELEMS;
    } else if ((long)out_size == ATTN_ELEMS) {
        attn = out;
        write_out = false;
    } else {
        attn = attn_fb;
    }

    const int STATS_SMEM = 2 * 64 * KSTR * 4;     // 34,816 B
    const int FUSED_SMEM = 4 * 64 * KSTR * 4;     // 69,632 B
    const int GEMM_SMEM  = 4 * 128 * GSTR * 4;    // 73,728 B
    static bool attr_done = false;
    if (!attr_done) {
        cudaFuncSetAttribute(attn_stats, cudaFuncAttributeMaxDynamicSharedMemorySize, STATS_SMEM);
        cudaFuncSetAttribute(attn_fused, cudaFuncAttributeMaxDynamicSharedMemorySize, FUSED_SMEM);
        cudaFuncSetAttribute(gemm_fc,    cudaFuncAttributeMaxDynamicSharedMemorySize, GEMM_SMEM);
        cudaFuncSetAttribute(gemm_proj3, cudaFuncAttributeMaxDynamicSharedMemorySize, GEMM_SMEM);
        attr_done = true;
    }

    // pre-round w_fc to tf32 (only used if write_out, but cheap & unconditional)
    round_wfc<<<DQ * DQ / 1024, 256>>>(w_fc, wfc);

    // projections (merged), outputs tf32-rounded; V transposed [z][d][s]
    Proj3 p;
    p.A0 = q;  p.A1 = k;  p.A2 = v;
    p.B0 = w_q; p.B1 = w_k; p.B2 = w_v;
    p.C0 = qh; p.C1 = kh; p.C2 = vh;
    gemm_proj3<<<dim3(8, 64, 3), 256, GEMM_SMEM>>>(p, MROWS, DQ, DQ);

    attn_stats<<<dim3(16, 64), 256, STATS_SMEM>>>(qh, kh);
    attn_fused<<<dim3(16, 64), 256, FUSED_SMEM>>>(qh, kh, vh, attn, ctx);

    if (write_out) {
        gemm_fc<<<dim3(8, 64, 1), 256, GEMM_SMEM>>>(ctx, wfc, fc, MROWS, DQ, DQ, 1.0f);
        add_ln_kernel<<<MROWS, 256>>>(fc, q, ga, be, out);
    }
}

// round 11
// speedup vs baseline: 1.4253x; 1.0192x over previous
#include <cuda_runtime.h>
#include <cuda_bf16.h>

// Problem constants
#define NHEAD 16
#define DQ    1024
#define DKEY  64
#define BATCH 4
#define SEQ   2048
#define MROWS (BATCH * SEQ)          // 8192
#define OUT_ELEMS  (8192L * 1024L)           // 8,388,608
#define ATTN_ELEMS (64L * 2048L * 2048L)     // 268,435,456

// ---------------- scratch ---------------------------------------------------
__device__ float g_qh[MROWS * DQ];     // [z][s][64]  tf32-rounded
__device__ float g_kh[MROWS * DQ];     // [z][s][64]  tf32-rounded
__device__ float g_vh[MROWS * DQ];     // TRANSPOSED [z][d][s], tf32-rounded
__device__ float g_ctx[MROWS * DQ];    // [B,S,H*64], tf32-rounded
__device__ float g_fc[MROWS * DQ];
__device__ float g_wfc[DQ * DQ];       // tf32-rounded copy of w_fc
__device__ float g_rowm[64 * SEQ];
__device__ float g_rowl[64 * SEQ];
__device__ float g_attn_fb[ATTN_ELEMS];

// ---------------- helpers ----------------------------------------------------
__device__ __forceinline__ unsigned f2tf32(float x) {
    unsigned r;
    asm("cvt.rna.tf32.f32 %0, %1;" : "=r"(r) : "f"(x));
    return r;
}
__device__ __forceinline__ float rnd(float x) { return __uint_as_float(f2tf32(x)); }
__device__ __forceinline__ unsigned cvtu(unsigned x) {
    return f2tf32(__uint_as_float(x));
}

__device__ __forceinline__ void mma_tf32(float c[4],
                                         unsigned a0, unsigned a1, unsigned a2, unsigned a3,
                                         unsigned b0, unsigned b1) {
    asm volatile(
        "mma.sync.aligned.m16n8k8.row.col.f32.tf32.tf32.f32 "
        "{%0,%1,%2,%3}, {%4,%5,%6,%7}, {%8,%9}, {%0,%1,%2,%3};"
        : "+f"(c[0]), "+f"(c[1]), "+f"(c[2]), "+f"(c[3])
        : "r"(a0), "r"(a1), "r"(a2), "r"(a3), "r"(b0), "r"(b1));
}

__device__ __forceinline__ void ldsm4(unsigned& r0, unsigned& r1,
                                      unsigned& r2, unsigned& r3, unsigned addr) {
    asm volatile("ldmatrix.sync.aligned.m8n8.x4.shared.b16 {%0,%1,%2,%3}, [%4];"
                 : "=r"(r0), "=r"(r1), "=r"(r2), "=r"(r3) : "r"(addr));
}

__device__ __forceinline__ void cp16(void* smem_dst, const void* gsrc) {
    unsigned saddr = (unsigned)__cvta_generic_to_shared(smem_dst);
    asm volatile("cp.async.cg.shared.global [%0], [%1], 16;" :: "r"(saddr), "l"(gsrc));
}
#define CP_COMMIT() asm volatile("cp.async.commit_group;")
#define CP_WAIT(n)  asm volatile("cp.async.wait_group %0;" :: "n"(n) : "memory")

#define KSTR 68     // fp32 smem stride for 64-wide tiles (LDSM-conflict-free)
#define GSTR 36     // gemm smem stride
#define NCH  (SEQ / 64)

// Q fragments (values in gmem already tf32-rounded -> raw bit loads)
__device__ __forceinline__ void load_qfrag(unsigned aq[8][4], const float* Qz,
                                           int row0, int t)
{
    const unsigned* Q0 = (const unsigned*)(Qz + (long)row0 * 64);
    const unsigned* Q1 = Q0 + 8 * 64;
#pragma unroll
    for (int k8 = 0; k8 < 8; k8++) {
        aq[k8][0] = Q0[k8 * 8 + t];
        aq[k8][1] = Q1[k8 * 8 + t];
        aq[k8][2] = Q0[k8 * 8 + t + 4];
        aq[k8][3] = Q1[k8 * 8 + t + 4];
    }
}

__device__ __forceinline__ void cp_chunk(float* dst, const float* src,
                                         long gstride, int tid)
{
#pragma unroll
    for (int i = 0; i < 4; i++) {
        const int idx = tid + i * 256;
        const int r = idx >> 4, c4 = (idx & 15) * 4;
        cp16(&dst[r * KSTR + c4], src + (long)r * gstride + c4);
    }
}

__device__ __forceinline__ unsigned ldsm_lane_off(int lane, int stride)
{
    return (unsigned)((((lane >> 4) * 8 + (lane & 7)) * stride) * 4
                      + 16 * ((lane >> 3) & 1));
}

// A-side LDSM lane offset: rows (l&7)+8*((l>>3)&1), col-half (l>>4)
__device__ __forceinline__ unsigned ldsm_lane_off_A(int lane, int stride)
{
    return (unsigned)((((lane & 7) + 8 * ((lane >> 3) & 1)) * stride) * 4
                      + 16 * (lane >> 4));
}

// ---------------- pass 1: softmax row stats ---------------------------------
__global__ __launch_bounds__(256, 2)
void attn_stats(const float* __restrict__ qh, const float* __restrict__ kh)
{
    extern __shared__ float smK[];     // [2][64][KSTR]

    const int z  = blockIdx.y;
    const int qb = blockIdx.x * 128;
    const float* Kz = kh + (long)z * SEQ * 64;

    const int tid = threadIdx.x;
    const int warp = tid >> 5, lane = tid & 31;
    const int wm = warp * 16;
    const int g = lane >> 2, t = lane & 3;
    const int row0 = qb + wm + g;

    unsigned aq[8][4];
    load_qfrag(aq, qh + (long)z * SEQ * 64, row0, t);

    const unsigned kLane = (unsigned)__cvta_generic_to_shared(smK) + ldsm_lane_off(lane, KSTR);

    const float scale = 0.125f;
    float m0 = -1e30f, m1 = -1e30f, l0 = 0.f, l1 = 0.f;

    cp_chunk(smK, Kz, 64, tid);
    CP_COMMIT();

    for (int ch = 0; ch < NCH; ch++) {
        if (ch + 1 < NCH) {
            cp_chunk(smK + ((ch + 1) & 1) * 64 * KSTR,
                     Kz + (long)(ch + 1) * 64 * 64, 64, tid);
            CP_COMMIT();
            CP_WAIT(1);
        } else {
            CP_WAIT(0);
        }
        __syncthreads();

        const unsigned kBuf = kLane + (unsigned)((ch & 1) * 64 * KSTR * 4);

        float sacc[8][4];
#pragma unroll
        for (int j = 0; j < 8; j++)
#pragma unroll
            for (int r = 0; r < 4; r++) sacc[j][r] = 0.f;

#pragma unroll
        for (int kk = 0; kk < 8; kk++) {
#pragma unroll
            for (int jp = 0; jp < 4; jp++) {
                unsigned r0, r1, r2, r3;
                ldsm4(r0, r1, r2, r3,
                      kBuf + (unsigned)((jp * 16 * KSTR + kk * 8) * 4));
                mma_tf32(sacc[2 * jp],     aq[kk][0], aq[kk][1], aq[kk][2], aq[kk][3], r0, r1);
                mma_tf32(sacc[2 * jp + 1], aq[kk][0], aq[kk][1], aq[kk][2], aq[kk][3], r2, r3);
            }
        }

        float t0 = -1e30f, t1 = -1e30f;
#pragma unroll
        for (int j = 0; j < 8; j++) {
            t0 = fmaxf(t0, fmaxf(sacc[j][0], sacc[j][1]));
            t1 = fmaxf(t1, fmaxf(sacc[j][2], sacc[j][3]));
        }
        t0 *= scale; t1 *= scale;
        t0 = fmaxf(t0, __shfl_xor_sync(0xffffffffu, t0, 1));
        t0 = fmaxf(t0, __shfl_xor_sync(0xffffffffu, t0, 2));
        t1 = fmaxf(t1, __shfl_xor_sync(0xffffffffu, t1, 1));
        t1 = fmaxf(t1, __shfl_xor_sync(0xffffffffu, t1, 2));

        float m0n = fmaxf(m0, t0), m1n = fmaxf(m1, t1);
        float s0 = 0.f, s1 = 0.f;
#pragma unroll
        for (int j = 0; j < 8; j++) {
            s0 += __expf(sacc[j][0] * scale - m0n) + __expf(sacc[j][1] * scale - m0n);
            s1 += __expf(sacc[j][2] * scale - m1n) + __expf(sacc[j][3] * scale - m1n);
        }
        s0 += __shfl_xor_sync(0xffffffffu, s0, 1);
        s0 += __shfl_xor_sync(0xffffffffu, s0, 2);
        s1 += __shfl_xor_sync(0xffffffffu, s1, 1);
        s1 += __shfl_xor_sync(0xffffffffu, s1, 2);

        l0 = l0 * __expf(m0 - m0n) + s0;
        l1 = l1 * __expf(m1 - m1n) + s1;
        m0 = m0n; m1 = m1n;
        __syncthreads();
    }

    if (t == 0) {
        const long base = (long)z * SEQ + qb + wm;
        g_rowm[base + g]     = m0;
        g_rowm[base + g + 8] = m1;
        g_rowl[base + g]     = 1.0f / l0;
        g_rowl[base + g + 8] = 1.0f / l1;
    }
}

// ---------------- pass 2: fused P write + P·V (P staged in smem) ------------
__global__ __launch_bounds__(256, 2)
void attn_fused(const float* __restrict__ qh, const float* __restrict__ kh,
                const float* __restrict__ vt, float* __restrict__ attn,
                float* __restrict__ ctx)
{
    extern __shared__ float smKV[];
    float* Kb = smKV;                    // [2][64][KSTR]
    float* Vb = smKV + 2 * 64 * KSTR;    // [2][64][KSTR]  V^T: rows=d, cols=k
    float* Pb = smKV + 4 * 64 * KSTR;    // [128][KSTR]    P tile (fp32), warp-private rows

    const int z  = blockIdx.y;
    const int b  = z >> 4, h = z & 15;
    const int qb = blockIdx.x * 128;
    const float* Kz  = kh + (long)z * SEQ * 64;
    const float* Vtz = vt + (long)z * SEQ * 64;
    float* attnZ = attn + (long)z * SEQ * SEQ;

    const int tid  = threadIdx.x;
    const int warp = tid >> 5, lane = tid & 31;
    const int wm = warp * 16;
    const int g = lane >> 2, t = lane & 3;
    const int row0 = qb + wm + g, row1 = row0 + 8;

    unsigned aq[8][4];
    load_qfrag(aq, qh + (long)z * SEQ * 64, row0, t);

    const long sbase = (long)z * SEQ;
    const float m0  = g_rowm[sbase + row0];
    const float m1  = g_rowm[sbase + row1];
    const float iv0 = g_rowl[sbase + row0];
    const float iv1 = g_rowl[sbase + row1];
    const float scale = 0.125f;

    const unsigned kLane = (unsigned)__cvta_generic_to_shared(Kb) + ldsm_lane_off(lane, KSTR);
    const unsigned vLane = (unsigned)__cvta_generic_to_shared(Vb) + ldsm_lane_off(lane, KSTR);
    const unsigned pLane = (unsigned)__cvta_generic_to_shared(Pb) + ldsm_lane_off_A(lane, KSTR);

    // copy-out lane mapping: half-warp per row, full 64 cols (2x128B wavefronts)
    const int cr = lane >> 4;            // 0..1 (row within pair)
    const int cc = (lane & 15) * 4;      // 0..60 (float4 col)

    float oacc[8][4];
#pragma unroll
    for (int j = 0; j < 8; j++)
#pragma unroll
        for (int r = 0; r < 4; r++) oacc[j][r] = 0.f;

    cp_chunk(Kb, Kz, 64, tid);        CP_COMMIT();
    cp_chunk(Vb, Vtz, SEQ, tid);      CP_COMMIT();

    for (int ch = 0; ch < NCH; ch++) {
        if (ch + 1 < NCH) {
            const int st = (ch + 1) & 1;
            cp_chunk(Kb + st * 64 * KSTR, Kz + (long)(ch + 1) * 64 * 64, 64, tid);
            CP_COMMIT();
            cp_chunk(Vb + st * 64 * KSTR, Vtz + (long)(ch + 1) * 64, SEQ, tid);
            CP_COMMIT();
            CP_WAIT(2);
        } else {
            CP_WAIT(0);
        }
        __syncthreads();

        const unsigned kBuf = kLane + (unsigned)((ch & 1) * 64 * KSTR * 4);
        const unsigned vBuf = vLane + (unsigned)((ch & 1) * 64 * KSTR * 4);

        // ---- S = Q K^T for this 128x64 chunk ----
        float sacc[8][4];
#pragma unroll
        for (int j = 0; j < 8; j++)
#pragma unroll
            for (int r = 0; r < 4; r++) sacc[j][r] = 0.f;

#pragma unroll
        for (int kk = 0; kk < 8; kk++) {
#pragma unroll
            for (int jp = 0; jp < 4; jp++) {
                unsigned r0, r1, r2, r3;
                ldsm4(r0, r1, r2, r3,
                      kBuf + (unsigned)((jp * 16 * KSTR + kk * 8) * 4));
                mma_tf32(sacc[2 * jp],     aq[kk][0], aq[kk][1], aq[kk][2], aq[kk][3], r0, r1);
                mma_tf32(sacc[2 * jp + 1], aq[kk][0], aq[kk][1], aq[kk][2], aq[kk][3], r2, r3);
            }
        }

        // ---- p = exp(s*scale-m)*inv_l -> stage fp32 P in smem (warp rows) --
#pragma unroll
        for (int j = 0; j < 8; j++) {
            float p0 = __expf(sacc[j][0] * scale - m0) * iv0;
            float p1 = __expf(sacc[j][1] * scale - m0) * iv0;
            float p2 = __expf(sacc[j][2] * scale - m1) * iv1;
            float p3 = __expf(sacc[j][3] * scale - m1) * iv1;
            float2 lo; lo.x = p0; lo.y = p1;
            float2 hi; hi.x = p2; hi.y = p3;
            *(float2*)&Pb[(wm + g) * KSTR + j * 8 + 2 * t]     = lo;
            *(float2*)&Pb[(wm + g + 8) * KSTR + j * 8 + 2 * t] = hi;
        }
        __syncwarp();

        // ---- PV: A-frags via LDSM on P tile; B-frags via LDSM on V^T -------
#pragma unroll
        for (int j = 0; j < 8; j++) {
            unsigned a0, a1, a2, a3;
            ldsm4(a0, a1, a2, a3, pLane + (unsigned)((wm * KSTR + j * 8) * 4));
            a0 = cvtu(a0); a1 = cvtu(a1); a2 = cvtu(a2); a3 = cvtu(a3);
#pragma unroll
            for (int jdp = 0; jdp < 4; jdp++) {
                unsigned r0, r1, r2, r3;
                ldsm4(r0, r1, r2, r3,
                      vBuf + (unsigned)((jdp * 16 * KSTR + j * 8) * 4));
                mma_tf32(oacc[2 * jdp],     a0, a1, a2, a3, r0, r1);
                mma_tf32(oacc[2 * jdp + 1], a0, a1, a2, a3, r2, r3);
            }
        }

        // ---- copy P tile to attn: 8 x (2 rows, full 64 cols) per warp ------
#pragma unroll
        for (int i = 0; i < 8; i++) {
            const int r = wm + cr + i * 2;
            float4 v = *(float4*)&Pb[r * KSTR + cc];
            *(float4*)(attnZ + (long)(qb + r) * SEQ + ch * 64 + cc) = v;
        }
        __syncthreads();
    }

    // ---- write O (tf32-rounded: consumed only by gemm_fc) ----
#pragma unroll
    for (int j = 0; j < 8; j++) {
        const int d = j * 8 + 2 * t;
        float2 lo; lo.x = rnd(oacc[j][0]); lo.y = rnd(oacc[j][1]);
        float2 hi; hi.x = rnd(oacc[j][2]); hi.y = rnd(oacc[j][3]);
        *(float2*)(ctx + ((long)(b * SEQ + row0)) * DQ + h * 64 + d) = lo;
        *(float2*)(ctx + ((long)(b * SEQ + row1)) * DQ + h * 64 + d) = hi;
    }
}

// ---------------- pipelined tensor-core GEMM-NT body ------------------------
// MODE 0: C row-major.  MODE 1: scatter [z][s][64].  MODE 2: scatter [z][d][s].
template <int MODE, bool CVT, bool RND>
__device__ __forceinline__
void gemm_body(const float* __restrict__ A, const float* __restrict__ Bm,
               float* __restrict__ C, int M, int N, int K, float alpha,
               unsigned* smem)
{
    constexpr int BM = 128, BN = 128, BK = 32;
    unsigned* As = smem;
    unsigned* Bs = smem + 2 * BM * GSTR;

    const int bm = blockIdx.y * BM;
    const int bn = blockIdx.x * BN;
    const int tid  = threadIdx.x;
    const int warp = tid >> 5, lane = tid & 31;
    const int wm = (warp >> 2) * 64;
    const int wn = (warp & 3) * 32;
    const int g = lane >> 2, t = lane & 3;

    const int lr = tid >> 3;
    const int lc = (tid & 7) * 4;

    const unsigned As_u = (unsigned)__cvta_generic_to_shared(As);
    const unsigned Bs_u = (unsigned)__cvta_generic_to_shared(Bs);
    const unsigned aLane = As_u + ldsm_lane_off_A(lane, GSTR);
    const unsigned bLane = Bs_u + ldsm_lane_off(lane, GSTR);

    float acc[4][4][4];
#pragma unroll
    for (int i = 0; i < 4; i++)
#pragma unroll
        for (int j = 0; j < 4; j++)
#pragma unroll
            for (int r = 0; r < 4; r++) acc[i][j][r] = 0.f;

    const int nt = K / BK;

    {
#pragma unroll
        for (int i = 0; i < 4; i++) {
            const int r = lr + i * 32;
            cp16(&As[r * GSTR + lc], A  + (long)(bm + r) * K + lc);
            cp16(&Bs[r * GSTR + lc], Bm + (long)(bn + r) * K + lc);
        }
        CP_COMMIT();
    }

    for (int kt = 0; kt < nt; kt++) {
        if (kt + 1 < nt) {
            const int st = (kt + 1) & 1;
            const int k0 = (kt + 1) * BK;
            unsigned* Ad = As + st * BM * GSTR;
            unsigned* Bd = Bs + st * BM * GSTR;
#pragma unroll
            for (int i = 0; i < 4; i++) {
                const int r = lr + i * 32;
                cp16(&Ad[r * GSTR + lc], A  + (long)(bm + r) * K + k0 + lc);
                cp16(&Bd[r * GSTR + lc], Bm + (long)(bn + r) * K + k0 + lc);
            }
            CP_COMMIT();
            CP_WAIT(1);
        } else {
            CP_WAIT(0);
        }
        __syncthreads();

        const unsigned bufOff = (unsigned)((kt & 1) * BM * GSTR * 4);
        const unsigned aB = aLane + bufOff;
        const unsigned bB = bLane + bufOff;

#pragma unroll
        for (int kk = 0; kk < BK; kk += 8) {
            unsigned af[4][4], bf[4][2];
#pragma unroll
            for (int i = 0; i < 4; i++) {
                ldsm4(af[i][0], af[i][1], af[i][2], af[i][3],
                      aB + (unsigned)(((wm + i * 16) * GSTR + kk) * 4));
                if (CVT) {
                    af[i][0] = cvtu(af[i][0]); af[i][1] = cvtu(af[i][1]);
                    af[i][2] = cvtu(af[i][2]); af[i][3] = cvtu(af[i][3]);
                }
            }
#pragma unroll
            for (int jp = 0; jp < 2; jp++) {
                unsigned r0, r1, r2, r3;
                ldsm4(r0, r1, r2, r3,
                      bB + (unsigned)(((wn + jp * 16) * GSTR + kk) * 4));
                if (CVT) { r0 = cvtu(r0); r1 = cvtu(r1); r2 = cvtu(r2); r3 = cvtu(r3); }
                bf[2 * jp][0]     = r0;
                bf[2 * jp][1]     = r1;
                bf[2 * jp + 1][0] = r2;
                bf[2 * jp + 1][1] = r3;
            }
#pragma unroll
            for (int i = 0; i < 4; i++)
#pragma unroll
                for (int j = 0; j < 4; j++)
                    mma_tf32(acc[i][j], af[i][0], af[i][1], af[i][2], af[i][3],
                             bf[j][0], bf[j][1]);
        }
        __syncthreads();
    }

#pragma unroll
    for (int i = 0; i < 4; i++) {
#pragma unroll
        for (int j = 0; j < 4; j++) {
            const int mrow = bm + wm + i * 16 + g;
            const int ncol = bn + wn + j * 8 + 2 * t;
            float v0 = alpha * acc[i][j][0], v1 = alpha * acc[i][j][1];
            float v2 = alpha * acc[i][j][2], v3 = alpha * acc[i][j][3];
            if (RND) { v0 = rnd(v0); v1 = rnd(v1); v2 = rnd(v2); v3 = rnd(v3); }
            float2 lo; lo.x = v0; lo.y = v1;
            float2 hi; hi.x = v2; hi.y = v3;
            if (MODE == 0) {
                *(float2*)(C + (long)mrow * N + ncol)       = lo;
                *(float2*)(C + (long)(mrow + 8) * N + ncol) = hi;
            } else if (MODE == 1) {
                const int h = ncol >> 6, d = ncol & 63;
                int b0 = mrow >> 11, s0 = mrow & 2047;
                *(float2*)(C + ((long)((b0 * NHEAD + h) * SEQ + s0)) * 64 + d) = lo;
                int m2 = mrow + 8;
                int b1 = m2 >> 11, s1 = m2 & 2047;
                *(float2*)(C + ((long)((b1 * NHEAD + h) * SEQ + s1)) * 64 + d) = hi;
            } else {
                const int h = ncol >> 6, d = ncol & 63;
                int b0 = mrow >> 11, s0 = mrow & 2047;
                float* p0 = C + ((long)((b0 * NHEAD + h) * 64 + d)) * SEQ + s0;
                p0[0]   = lo.x;
                p0[SEQ] = lo.y;
                int m2 = mrow + 8;
                int b1 = m2 >> 11, s1 = m2 & 2047;
                float* p1 = C + ((long)((b1 * NHEAD + h) * 64 + d)) * SEQ + s1;
                p1[0]   = hi.x;
                p1[SEQ] = hi.y;
            }
        }
    }
}

__global__ __launch_bounds__(256, 2)
void gemm_fc(const float* __restrict__ A, const float* __restrict__ Bm,
             float* __restrict__ C, int M, int N, int K, float alpha)
{
    extern __shared__ unsigned smemg[];
    gemm_body<0, false, false>(A, Bm, C, M, N, K, alpha, smemg);
}

struct Proj3 {
    const float *A0, *A1, *A2;
    const float *B0, *B1, *B2;
    float *C0, *C1, *C2;
};

__global__ __launch_bounds__(256, 2)
void gemm_proj3(Proj3 p, int M, int N, int K)
{
    extern __shared__ unsigned smemg[];
    if (blockIdx.z == 0)      gemm_body<1, true, true>(p.A0, p.B0, p.C0, M, N, K, 1.0f, smemg);
    else if (blockIdx.z == 1) gemm_body<1, true, true>(p.A1, p.B1, p.C1, M, N, K, 1.0f, smemg);
    else                      gemm_body<2, true, true>(p.A2, p.B2, p.C2, M, N, K, 1.0f, smemg);
}

// ---------------- w_fc pre-round --------------------------------------------
__global__ __launch_bounds__(256)
void round_wfc(const float* __restrict__ src, float* __restrict__ dst)
{
    const int i = blockIdx.x * 256 + threadIdx.x;
    float4 v = ((const float4*)src)[i];
    v.x = rnd(v.x); v.y = rnd(v.y); v.z = rnd(v.z); v.w = rnd(v.w);
    ((float4*)dst)[i] = v;
}

// ---------------- residual add + LayerNorm ----------------------------------
__global__ __launch_bounds__(256)
void add_ln_kernel(const float* __restrict__ fc, const float* __restrict__ res,
                   const float* __restrict__ gamma, const float* __restrict__ beta,
                   float* __restrict__ out)
{
    const long row = blockIdx.x;
    const int tid = threadIdx.x;
    float4 f = ((const float4*)(fc  + row * DQ))[tid];
    float4 r = ((const float4*)(res + row * DQ))[tid];
    float x0 = f.x + r.x, x1 = f.y + r.y, x2 = f.z + r.z, x3 = f.w + r.w;

    float s  = x0 + x1 + x2 + x3;
    float sq = x0 * x0 + x1 * x1 + x2 * x2 + x3 * x3;
#pragma unroll
    for (int off = 16; off > 0; off >>= 1) {
        s  += __shfl_xor_sync(0xffffffffu, s,  off);
        sq += __shfl_xor_sync(0xffffffffu, sq, off);
    }
    __shared__ float rs[8], rq[8];
    const int wid = tid >> 5, lane = tid & 31;
    if (lane == 0) { rs[wid] = s; rq[wid] = sq; }
    __syncthreads();
    float S = 0.f, SQ = 0.f;
#pragma unroll
    for (int w = 0; w < 8; w++) { S += rs[w]; SQ += rq[w]; }

    const float mu  = S * (1.0f / DQ);
    const float var = SQ * (1.0f / DQ) - mu * mu;
    const float rstd = rsqrtf(var + 1e-6f);

    float4 g  = ((const float4*)gamma)[tid];
    float4 be = ((const float4*)beta)[tid];
    float4 o;
    o.x = (x0 - mu) * rstd * g.x + be.x;
    o.y = (x1 - mu) * rstd * g.y + be.y;
    o.z = (x2 - mu) * rstd * g.z + be.z;
    o.w = (x3 - mu) * rstd * g.w + be.w;
    ((float4*)(out + row * DQ))[tid] = o;
}

// ---------------- launcher --------------------------------------------------
extern "C" void kernel_launch(void* const* d_in, const int* in_sizes, int n_in,
                              void* d_out, int out_size)
{
    const float* q    = (const float*)d_in[0];
    const float* k    = (const float*)d_in[1];
    const float* v    = (const float*)d_in[2];
    const float* w_q  = (const float*)d_in[3];
    const float* w_k  = (const float*)d_in[4];
    const float* w_v  = (const float*)d_in[5];
    const float* w_fc = (const float*)d_in[6];
    const float* ga   = (const float*)d_in[7];
    const float* be   = (const float*)d_in[8];
    float* out = (float*)d_out;

    float *qh, *kh, *vh, *ctx, *fc, *wfc, *attn_fb;
    cudaGetSymbolAddress((void**)&qh,      g_qh);
    cudaGetSymbolAddress((void**)&kh,      g_kh);
    cudaGetSymbolAddress((void**)&vh,      g_vh);
    cudaGetSymbolAddress((void**)&ctx,     g_ctx);
    cudaGetSymbolAddress((void**)&fc,      g_fc);
    cudaGetSymbolAddress((void**)&wfc,     g_wfc);
    cudaGetSymbolAddress((void**)&attn_fb, g_attn_fb);

    float* attn;
    bool write_out = true;
    if ((long)out_size >= OUT_ELEMS + ATTN_ELEMS) {
        attn = out + OUT_ELEMS;
    } else if ((long)out_size == ATTN_ELEMS) {
        attn = out;
        write_out = false;
    } else {
        attn = attn_fb;
    }

    const int STATS_SMEM = 2 * 64 * KSTR * 4;                  // 34,816 B
    const int FUSED_SMEM = (4 * 64 + 128) * KSTR * 4;          // 104,448 B
    const int GEMM_SMEM  = 4 * 128 * GSTR * 4;                 // 73,728 B
    static bool attr_done = false;
    if (!attr_done) {
        cudaFuncSetAttribute(attn_stats, cudaFuncAttributeMaxDynamicSharedMemorySize, STATS_SMEM);
        cudaFuncSetAttribute(attn_fused, cudaFuncAttributeMaxDynamicSharedMemorySize, FUSED_SMEM);
        cudaFuncSetAttribute(gemm_fc,    cudaFuncAttributeMaxDynamicSharedMemorySize, GEMM_SMEM);
        cudaFuncSetAttribute(gemm_proj3, cudaFuncAttributeMaxDynamicSharedMemorySize, GEMM_SMEM);
        attr_done = true;
    }

    // pre-round w_fc to tf32
    round_wfc<<<DQ * DQ / 1024, 256>>>(w_fc, wfc);

    // projections (merged), outputs tf32-rounded; V transposed [z][d][s]
    Proj3 p;
    p.A0 = q;  p.A1 = k;  p.A2 = v;
    p.B0 = w_q; p.B1 = w_k; p.B2 = w_v;
    p.C0 = qh; p.C1 = kh; p.C2 = vh;
    gemm_proj3<<<dim3(8, 64, 3), 256, GEMM_SMEM>>>(p, MROWS, DQ, DQ);

    attn_stats<<<dim3(16, 64), 256, STATS_SMEM>>>(qh, kh);
    attn_fused<<<dim3(16, 64), 256, FUSED_SMEM>>>(qh, kh, vh, attn, ctx);

    if (write_out) {
        gemm_fc<<<dim3(8, 64, 1), 256, GEMM_SMEM>>>(ctx, wfc, fc, MROWS, DQ, DQ, 1.0f);
        add_ln_kernel<<<MROWS, 256>>>(fc, q, ga, be, out);
    }
}

// round 12
// speedup vs baseline: 1.5347x; 1.0767x over previous
#include <cuda_runtime.h>
#include <cuda_bf16.h>

// Problem constants
#define NHEAD 16
#define DQ    1024
#define DKEY  64
#define BATCH 4
#define SEQ   2048
#define MROWS (BATCH * SEQ)          // 8192
#define OUT_ELEMS  (8192L * 1024L)           // 8,388,608
#define ATTN_ELEMS (64L * 2048L * 2048L)     // 268,435,456

// ---------------- scratch ---------------------------------------------------
__device__ float g_qh[MROWS * DQ];     // [z][s][64]  tf32-rounded
__device__ float g_kh[MROWS * DQ];     // [z][s][64]  tf32-rounded
__device__ __nv_bfloat16 g_vbh[MROWS * DQ];  // TRANSPOSED [z][d][s], bf16
__device__ float g_ctx[MROWS * DQ];    // [B,S,H*64], tf32-rounded
__device__ float g_fc[MROWS * DQ];
__device__ float g_wfc[DQ * DQ];       // tf32-rounded copy of w_fc
__device__ float g_rowl[64 * SEQ];     // per-row 1/sumexp
__device__ float g_attn_fb[ATTN_ELEMS];

// ---------------- helpers ----------------------------------------------------
__device__ __forceinline__ unsigned f2tf32(float x) {
    unsigned r;
    asm("cvt.rna.tf32.f32 %0, %1;" : "=r"(r) : "f"(x));
    return r;
}
__device__ __forceinline__ float rnd(float x) { return __uint_as_float(f2tf32(x)); }
__device__ __forceinline__ unsigned cvtu(unsigned x) {
    return f2tf32(__uint_as_float(x));
}
__device__ __forceinline__ unsigned pack_bf16(float lo, float hi) {
    unsigned d;
    asm("cvt.rn.bf16x2.f32 %0, %1, %2;" : "=r"(d) : "f"(hi), "f"(lo));
    return d;
}

__device__ __forceinline__ void mma_tf32(float c[4],
                                         unsigned a0, unsigned a1, unsigned a2, unsigned a3,
                                         unsigned b0, unsigned b1) {
    asm volatile(
        "mma.sync.aligned.m16n8k8.row.col.f32.tf32.tf32.f32 "
        "{%0,%1,%2,%3}, {%4,%5,%6,%7}, {%8,%9}, {%0,%1,%2,%3};"
        : "+f"(c[0]), "+f"(c[1]), "+f"(c[2]), "+f"(c[3])
        : "r"(a0), "r"(a1), "r"(a2), "r"(a3), "r"(b0), "r"(b1));
}

__device__ __forceinline__ void mma_bf16(float c[4],
                                         unsigned a0, unsigned a1, unsigned a2, unsigned a3,
                                         unsigned b0, unsigned b1) {
    asm volatile(
        "mma.sync.aligned.m16n8k16.row.col.f32.bf16.bf16.f32 "
        "{%0,%1,%2,%3}, {%4,%5,%6,%7}, {%8,%9}, {%0,%1,%2,%3};"
        : "+f"(c[0]), "+f"(c[1]), "+f"(c[2]), "+f"(c[3])
        : "r"(a0), "r"(a1), "r"(a2), "r"(a3), "r"(b0), "r"(b1));
}

__device__ __forceinline__ void ldsm4(unsigned& r0, unsigned& r1,
                                      unsigned& r2, unsigned& r3, unsigned addr) {
    asm volatile("ldmatrix.sync.aligned.m8n8.x4.shared.b16 {%0,%1,%2,%3}, [%4];"
                 : "=r"(r0), "=r"(r1), "=r"(r2), "=r"(r3) : "r"(addr));
}

__device__ __forceinline__ void cp16(void* smem_dst, const void* gsrc) {
    unsigned saddr = (unsigned)__cvta_generic_to_shared(smem_dst);
    asm volatile("cp.async.cg.shared.global [%0], [%1], 16;" :: "r"(saddr), "l"(gsrc));
}
#define CP_COMMIT() asm volatile("cp.async.commit_group;")
#define CP_WAIT(n)  asm volatile("cp.async.wait_group %0;" :: "n"(n) : "memory")

#define KSTR 68          // fp32 smem stride (floats) for 64-wide tiles
#define BSTRB 144        // bf16 smem row stride in BYTES (72 bf16) — conflict-free
#define GSTR 36          // gemm smem stride
#define NCH  (SEQ / 64)

// Q fragments (values in gmem already tf32-rounded -> raw bit loads)
__device__ __forceinline__ void load_qfrag(unsigned aq[8][4], const float* Qz,
                                           int row0, int t)
{
    const unsigned* Q0 = (const unsigned*)(Qz + (long)row0 * 64);
    const unsigned* Q1 = Q0 + 8 * 64;
#pragma unroll
    for (int k8 = 0; k8 < 8; k8++) {
        aq[k8][0] = Q0[k8 * 8 + t];
        aq[k8][1] = Q1[k8 * 8 + t];
        aq[k8][2] = Q0[k8 * 8 + t + 4];
        aq[k8][3] = Q1[k8 * 8 + t + 4];
    }
}

__device__ __forceinline__ void cp_chunk_k(float* dst, const float* src, int tid)
{
#pragma unroll
    for (int i = 0; i < 4; i++) {
        const int idx = tid + i * 256;
        const int r = idx >> 4, c4 = (idx & 15) * 4;
        cp16(&dst[r * KSTR + c4], src + (long)r * 64 + c4);
    }
}

// 64x64 bf16 chunk from [d][s] gmem (row stride SEQ) into [64][BSTRB] smem
__device__ __forceinline__ void cp_chunk_v(char* dst, const __nv_bfloat16* src, int tid)
{
#pragma unroll
    for (int i = 0; i < 2; i++) {
        const int idx = tid + i * 256;
        const int r = idx >> 3, c8 = (idx & 7);
        cp16(dst + r * BSTRB + c8 * 16, src + (long)r * SEQ + c8 * 8);
    }
}

__device__ __forceinline__ unsigned ldsm_lane_off(int lane, int stride)
{
    return (unsigned)((((lane >> 4) * 8 + (lane & 7)) * stride) * 4
                      + 16 * ((lane >> 3) & 1));
}
// bytes version (for bf16 tiles, stride in bytes)
__device__ __forceinline__ unsigned ldsm_lane_off_bytes(int lane, int strideB)
{
    return (unsigned)(((lane >> 4) * 8 + (lane & 7)) * strideB
                      + 16 * ((lane >> 3) & 1));
}
// A-side: rows (l&7)+8*((l>>3)&1), col-half (l>>4)
__device__ __forceinline__ unsigned ldsm_lane_off_A(int lane, int stride)
{
    return (unsigned)((((lane & 7) + 8 * ((lane >> 3) & 1)) * stride) * 4
                      + 16 * (lane >> 4));
}
__device__ __forceinline__ unsigned ldsm_lane_off_A_bytes(int lane, int strideB)
{
    return (unsigned)(((lane & 7) + 8 * ((lane >> 3) & 1)) * strideB
                      + 16 * (lane >> 4));
}

// ---------------- pass 1: softmax row sums (no max subtraction needed) ------
__global__ __launch_bounds__(256, 2)
void attn_stats(const float* __restrict__ qh, const float* __restrict__ kh)
{
    extern __shared__ float smK[];     // [2][64][KSTR]

    const int z  = blockIdx.y;
    const int qb = blockIdx.x * 128;
    const float* Kz = kh + (long)z * SEQ * 64;

    const int tid = threadIdx.x;
    const int warp = tid >> 5, lane = tid & 31;
    const int wm = warp * 16;
    const int g = lane >> 2, t = lane & 3;
    const int row0 = qb + wm + g;

    unsigned aq[8][4];
    load_qfrag(aq, qh + (long)z * SEQ * 64, row0, t);

    const unsigned kLane = (unsigned)__cvta_generic_to_shared(smK) + ldsm_lane_off(lane, KSTR);

    const float scale = 0.125f;
    float l0 = 0.f, l1 = 0.f;

    cp_chunk_k(smK, Kz, tid);
    CP_COMMIT();

    for (int ch = 0; ch < NCH; ch++) {
        if (ch + 1 < NCH) {
            cp_chunk_k(smK + ((ch + 1) & 1) * 64 * KSTR,
                       Kz + (long)(ch + 1) * 64 * 64, tid);
            CP_COMMIT();
            CP_WAIT(1);
        } else {
            CP_WAIT(0);
        }
        __syncthreads();

        const unsigned kBuf = kLane + (unsigned)((ch & 1) * 64 * KSTR * 4);

        float sacc[8][4];
#pragma unroll
        for (int j = 0; j < 8; j++)
#pragma unroll
            for (int r = 0; r < 4; r++) sacc[j][r] = 0.f;

#pragma unroll
        for (int kk = 0; kk < 8; kk++) {
#pragma unroll
            for (int jp = 0; jp < 4; jp++) {
                unsigned r0, r1, r2, r3;
                ldsm4(r0, r1, r2, r3,
                      kBuf + (unsigned)((jp * 16 * KSTR + kk * 8) * 4));
                mma_tf32(sacc[2 * jp],     aq[kk][0], aq[kk][1], aq[kk][2], aq[kk][3], r0, r1);
                mma_tf32(sacc[2 * jp + 1], aq[kk][0], aq[kk][1], aq[kk][2], aq[kk][3], r2, r3);
            }
        }

        float s0 = 0.f, s1 = 0.f;
#pragma unroll
        for (int j = 0; j < 8; j++) {
            s0 += __expf(sacc[j][0] * scale) + __expf(sacc[j][1] * scale);
            s1 += __expf(sacc[j][2] * scale) + __expf(sacc[j][3] * scale);
        }
        l0 += s0;
        l1 += s1;
        __syncthreads();
    }

    l0 += __shfl_xor_sync(0xffffffffu, l0, 1);
    l0 += __shfl_xor_sync(0xffffffffu, l0, 2);
    l1 += __shfl_xor_sync(0xffffffffu, l1, 1);
    l1 += __shfl_xor_sync(0xffffffffu, l1, 2);

    if (t == 0) {
        const long base = (long)z * SEQ + qb + wm;
        g_rowl[base + g]     = 1.0f / l0;
        g_rowl[base + g + 8] = 1.0f / l1;
    }
}

// ---------------- pass 2: fused P write + P·V (bf16 PV) ---------------------
__global__ __launch_bounds__(256, 2)
void attn_fused(const float* __restrict__ qh, const float* __restrict__ kh,
                const __nv_bfloat16* __restrict__ vt, float* __restrict__ attn,
                float* __restrict__ ctx)
{
    extern __shared__ char smemc[];
    float* Kb  = (float*)smemc;                     // [2][64][KSTR] fp32   34,816 B
    char*  Vb  = smemc + 34816;                     // [2][64][BSTRB] bf16  18,432 B
    float* Pb  = (float*)(smemc + 53248);           // [128][KSTR] fp32     34,816 B
    char*  Pbh = smemc + 88064;                     // [128][BSTRB] bf16    18,432 B

    const int z  = blockIdx.y;
    const int b  = z >> 4, h = z & 15;
    const int qb = blockIdx.x * 128;
    const float* Kz  = kh + (long)z * SEQ * 64;
    const __nv_bfloat16* Vtz = vt + (long)z * SEQ * 64;   // [64 d][2048 s]
    float* attnZ = attn + (long)z * SEQ * SEQ;

    const int tid  = threadIdx.x;
    const int warp = tid >> 5, lane = tid & 31;
    const int wm = warp * 16;
    const int g = lane >> 2, t = lane & 3;
    const int row0 = qb + wm + g, row1 = row0 + 8;

    unsigned aq[8][4];
    load_qfrag(aq, qh + (long)z * SEQ * 64, row0, t);

    const long sbase = (long)z * SEQ;
    const float iv0 = g_rowl[sbase + row0];
    const float iv1 = g_rowl[sbase + row1];
    const float scale = 0.125f;

    const unsigned kLane  = (unsigned)__cvta_generic_to_shared(Kb) + ldsm_lane_off(lane, KSTR);
    const unsigned vLane  = (unsigned)__cvta_generic_to_shared(Vb) + ldsm_lane_off_bytes(lane, BSTRB);
    const unsigned pbLane = (unsigned)__cvta_generic_to_shared(Pbh) + ldsm_lane_off_A_bytes(lane, BSTRB);

    // copy-out lane mapping: half-warp per row, full 64 cols (2x128B wavefronts)
    const int cr = lane >> 4;            // 0..1
    const int cc = (lane & 15) * 4;      // 0..60

    float oacc[8][4];
#pragma unroll
    for (int j = 0; j < 8; j++)
#pragma unroll
        for (int r = 0; r < 4; r++) oacc[j][r] = 0.f;

    cp_chunk_k(Kb, Kz, tid);        CP_COMMIT();
    cp_chunk_v(Vb, Vtz, tid);       CP_COMMIT();

    for (int ch = 0; ch < NCH; ch++) {
        if (ch + 1 < NCH) {
            const int st = (ch + 1) & 1;
            cp_chunk_k(Kb + st * 64 * KSTR, Kz + (long)(ch + 1) * 64 * 64, tid);
            CP_COMMIT();
            cp_chunk_v(Vb + st * 64 * BSTRB, Vtz + (long)(ch + 1) * 64, tid);
            CP_COMMIT();
            CP_WAIT(2);
        } else {
            CP_WAIT(0);
        }
        __syncthreads();

        const unsigned kBuf = kLane + (unsigned)((ch & 1) * 64 * KSTR * 4);
        const unsigned vBuf = vLane + (unsigned)((ch & 1) * 64 * BSTRB);

        // ---- S = Q K^T (tf32) for this 128x64 chunk ----
        float sacc[8][4];
#pragma unroll
        for (int j = 0; j < 8; j++)
#pragma unroll
            for (int r = 0; r < 4; r++) sacc[j][r] = 0.f;

#pragma unroll
        for (int kk = 0; kk < 8; kk++) {
#pragma unroll
            for (int jp = 0; jp < 4; jp++) {
                unsigned r0, r1, r2, r3;
                ldsm4(r0, r1, r2, r3,
                      kBuf + (unsigned)((jp * 16 * KSTR + kk * 8) * 4));
                mma_tf32(sacc[2 * jp],     aq[kk][0], aq[kk][1], aq[kk][2], aq[kk][3], r0, r1);
                mma_tf32(sacc[2 * jp + 1], aq[kk][0], aq[kk][1], aq[kk][2], aq[kk][3], r2, r3);
            }
        }

        // ---- p = exp(s*scale)*inv_l -> fp32 P (copyout) + bf16 P (PV) ------
#pragma unroll
        for (int j = 0; j < 8; j++) {
            float p0 = __expf(sacc[j][0] * scale) * iv0;
            float p1 = __expf(sacc[j][1] * scale) * iv0;
            float p2 = __expf(sacc[j][2] * scale) * iv1;
            float p3 = __expf(sacc[j][3] * scale) * iv1;
            float2 lo; lo.x = p0; lo.y = p1;
            float2 hi; hi.x = p2; hi.y = p3;
            const int c = j * 8 + 2 * t;
            *(float2*)&Pb[(wm + g) * KSTR + c]     = lo;
            *(float2*)&Pb[(wm + g + 8) * KSTR + c] = hi;
            *(unsigned*)(Pbh + (wm + g) * BSTRB + c * 2)     = pack_bf16(p0, p1);
            *(unsigned*)(Pbh + (wm + g + 8) * BSTRB + c * 2) = pack_bf16(p2, p3);
        }
        __syncwarp();

        // ---- PV (bf16 m16n8k16): A from Pbh, B from V^T ----
#pragma unroll
        for (int j16 = 0; j16 < 4; j16++) {
            unsigned a0, a1, a2, a3;
            ldsm4(a0, a1, a2, a3, pbLane + (unsigned)(wm * BSTRB + j16 * 32));
#pragma unroll
            for (int jdp = 0; jdp < 4; jdp++) {
                unsigned r0, r1, r2, r3;
                ldsm4(r0, r1, r2, r3,
                      vBuf + (unsigned)(jdp * 16 * BSTRB + j16 * 32));
                mma_bf16(oacc[2 * jdp],     a0, a1, a2, a3, r0, r1);
                mma_bf16(oacc[2 * jdp + 1], a0, a1, a2, a3, r2, r3);
            }
        }

        // ---- copy P tile to attn: 8 x (2 rows, full 64 cols) per warp ------
#pragma unroll
        for (int i = 0; i < 8; i++) {
            const int r = wm + cr + i * 2;
            float4 v = *(float4*)&Pb[r * KSTR + cc];
            *(float4*)(attnZ + (long)(qb + r) * SEQ + ch * 64 + cc) = v;
        }
        __syncthreads();
    }

    // ---- write O (tf32-rounded: consumed only by gemm_fc) ----
#pragma unroll
    for (int j = 0; j < 8; j++) {
        const int d = j * 8 + 2 * t;
        float2 lo; lo.x = rnd(oacc[j][0]); lo.y = rnd(oacc[j][1]);
        float2 hi; hi.x = rnd(oacc[j][2]); hi.y = rnd(oacc[j][3]);
        *(float2*)(ctx + ((long)(b * SEQ + row0)) * DQ + h * 64 + d) = lo;
        *(float2*)(ctx + ((long)(b * SEQ + row1)) * DQ + h * 64 + d) = hi;
    }
}

// ---------------- pipelined tensor-core GEMM-NT body ------------------------
// MODE 0: C row-major.  MODE 1: scatter [z][s][64] fp32.  MODE 2: scatter [z][d][s] bf16.
template <int MODE, bool CVT, bool RND>
__device__ __forceinline__
void gemm_body(const float* __restrict__ A, const float* __restrict__ Bm,
               float* __restrict__ C, int M, int N, int K, float alpha,
               unsigned* smem)
{
    constexpr int BM = 128, BN = 128, BK = 32;
    unsigned* As = smem;
    unsigned* Bs = smem + 2 * BM * GSTR;

    const int bm = blockIdx.y * BM;
    const int bn = blockIdx.x * BN;
    const int tid  = threadIdx.x;
    const int warp = tid >> 5, lane = tid & 31;
    const int wm = (warp >> 2) * 64;
    const int wn = (warp & 3) * 32;
    const int g = lane >> 2, t = lane & 3;

    const int lr = tid >> 3;
    const int lc = (tid & 7) * 4;

    const unsigned As_u = (unsigned)__cvta_generic_to_shared(As);
    const unsigned Bs_u = (unsigned)__cvta_generic_to_shared(Bs);
    const unsigned aLane = As_u + ldsm_lane_off_A(lane, GSTR);
    const unsigned bLane = Bs_u + ldsm_lane_off(lane, GSTR);

    float acc[4][4][4];
#pragma unroll
    for (int i = 0; i < 4; i++)
#pragma unroll
        for (int j = 0; j < 4; j++)
#pragma unroll
            for (int r = 0; r < 4; r++) acc[i][j][r] = 0.f;

    const int nt = K / BK;

    {
#pragma unroll
        for (int i = 0; i < 4; i++) {
            const int r = lr + i * 32;
            cp16(&As[r * GSTR + lc], A  + (long)(bm + r) * K + lc);
            cp16(&Bs[r * GSTR + lc], Bm + (long)(bn + r) * K + lc);
        }
        CP_COMMIT();
    }

    for (int kt = 0; kt < nt; kt++) {
        if (kt + 1 < nt) {
            const int st = (kt + 1) & 1;
            const int k0 = (kt + 1) * BK;
            unsigned* Ad = As + st * BM * GSTR;
            unsigned* Bd = Bs + st * BM * GSTR;
#pragma unroll
            for (int i = 0; i < 4; i++) {
                const int r = lr + i * 32;
                cp16(&Ad[r * GSTR + lc], A  + (long)(bm + r) * K + k0 + lc);
                cp16(&Bd[r * GSTR + lc], Bm + (long)(bn + r) * K + k0 + lc);
            }
            CP_COMMIT();
            CP_WAIT(1);
        } else {
            CP_WAIT(0);
        }
        __syncthreads();

        const unsigned bufOff = (unsigned)((kt & 1) * BM * GSTR * 4);
        const unsigned aB = aLane + bufOff;
        const unsigned bB = bLane + bufOff;

#pragma unroll
        for (int kk = 0; kk < BK; kk += 8) {
            unsigned af[4][4], bf[4][2];
#pragma unroll
            for (int i = 0; i < 4; i++) {
                ldsm4(af[i][0], af[i][1], af[i][2], af[i][3],
                      aB + (unsigned)(((wm + i * 16) * GSTR + kk) * 4));
                if (CVT) {
                    af[i][0] = cvtu(af[i][0]); af[i][1] = cvtu(af[i][1]);
                    af[i][2] = cvtu(af[i][2]); af[i][3] = cvtu(af[i][3]);
                }
            }
#pragma unroll
            for (int jp = 0; jp < 2; jp++) {
                unsigned r0, r1, r2, r3;
                ldsm4(r0, r1, r2, r3,
                      bB + (unsigned)(((wn + jp * 16) * GSTR + kk) * 4));
                if (CVT) { r0 = cvtu(r0); r1 = cvtu(r1); r2 = cvtu(r2); r3 = cvtu(r3); }
                bf[2 * jp][0]     = r0;
                bf[2 * jp][1]     = r1;
                bf[2 * jp + 1][0] = r2;
                bf[2 * jp + 1][1] = r3;
            }
#pragma unroll
            for (int i = 0; i < 4; i++)
#pragma unroll
                for (int j = 0; j < 4; j++)
                    mma_tf32(acc[i][j], af[i][0], af[i][1], af[i][2], af[i][3],
                             bf[j][0], bf[j][1]);
        }
        __syncthreads();
    }

#pragma unroll
    for (int i = 0; i < 4; i++) {
#pragma unroll
        for (int j = 0; j < 4; j++) {
            const int mrow = bm + wm + i * 16 + g;
            const int ncol = bn + wn + j * 8 + 2 * t;
            float v0 = alpha * acc[i][j][0], v1 = alpha * acc[i][j][1];
            float v2 = alpha * acc[i][j][2], v3 = alpha * acc[i][j][3];
            if (RND) { v0 = rnd(v0); v1 = rnd(v1); v2 = rnd(v2); v3 = rnd(v3); }
            if (MODE == 0) {
                float2 lo; lo.x = v0; lo.y = v1;
                float2 hi; hi.x = v2; hi.y = v3;
                *(float2*)(C + (long)mrow * N + ncol)       = lo;
                *(float2*)(C + (long)(mrow + 8) * N + ncol) = hi;
            } else if (MODE == 1) {
                float2 lo; lo.x = v0; lo.y = v1;
                float2 hi; hi.x = v2; hi.y = v3;
                const int h = ncol >> 6, d = ncol & 63;
                int b0 = mrow >> 11, s0 = mrow & 2047;
                *(float2*)(C + ((long)((b0 * NHEAD + h) * SEQ + s0)) * 64 + d) = lo;
                int m2 = mrow + 8;
                int b1 = m2 >> 11, s1 = m2 & 2047;
                *(float2*)(C + ((long)((b1 * NHEAD + h) * SEQ + s1)) * 64 + d) = hi;
            } else {
                // V: bf16 transposed [z][d][s]
                __nv_bfloat16* Cb = (__nv_bfloat16*)C;
                const int h = ncol >> 6, d = ncol & 63;
                int b0 = mrow >> 11, s0 = mrow & 2047;
                __nv_bfloat16* p0 = Cb + ((long)((b0 * NHEAD + h) * 64 + d)) * SEQ + s0;
                p0[0]   = __float2bfloat16(v0);
                p0[SEQ] = __float2bfloat16(v1);
                int m2 = mrow + 8;
                int b1 = m2 >> 11, s1 = m2 & 2047;
                __nv_bfloat16* p1 = Cb + ((long)((b1 * NHEAD + h) * 64 + d)) * SEQ + s1;
                p1[0]   = __float2bfloat16(v2);
                p1[SEQ] = __float2bfloat16(v3);
            }
        }
    }
}

__global__ __launch_bounds__(256, 2)
void gemm_fc(const float* __restrict__ A, const float* __restrict__ Bm,
             float* __restrict__ C, int M, int N, int K, float alpha)
{
    extern __shared__ unsigned smemg[];
    gemm_body<0, false, false>(A, Bm, C, M, N, K, alpha, smemg);
}

struct Proj3 {
    const float *A0, *A1, *A2;
    const float *B0, *B1, *B2;
    float *C0, *C1, *C2;
};

__global__ __launch_bounds__(256, 2)
void gemm_proj3(Proj3 p, int M, int N, int K)
{
    extern __shared__ unsigned smemg[];
    if (blockIdx.z == 0)      gemm_body<1, true, true>(p.A0, p.B0, p.C0, M, N, K, 1.0f, smemg);
    else if (blockIdx.z == 1) gemm_body<1, true, true>(p.A1, p.B1, p.C1, M, N, K, 1.0f, smemg);
    else                      gemm_body<2, true, false>(p.A2, p.B2, p.C2, M, N, K, 1.0f, smemg);
}

// ---------------- w_fc pre-round --------------------------------------------
__global__ __launch_bounds__(256)
void round_wfc(const float* __restrict__ src, float* __restrict__ dst)
{
    const int i = blockIdx.x * 256 + threadIdx.x;
    float4 v = ((const float4*)src)[i];
    v.x = rnd(v.x); v.y = rnd(v.y); v.z = rnd(v.z); v.w = rnd(v.w);
    ((float4*)dst)[i] = v;
}

// ---------------- residual add + LayerNorm ----------------------------------
__global__ __launch_bounds__(256)
void add_ln_kernel(const float* __restrict__ fc, const float* __restrict__ res,
                   const float* __restrict__ gamma, const float* __restrict__ beta,
                   float* __restrict__ out)
{
    const long row = blockIdx.x;
    const int tid = threadIdx.x;
    float4 f = ((const float4*)(fc  + row * DQ))[tid];
    float4 r = ((const float4*)(res + row * DQ))[tid];
    float x0 = f.x + r.x, x1 = f.y + r.y, x2 = f.z + r.z, x3 = f.w + r.w;

    float s  = x0 + x1 + x2 + x3;
    float sq = x0 * x0 + x1 * x1 + x2 * x2 + x3 * x3;
#pragma unroll
    for (int off = 16; off > 0; off >>= 1) {
        s  += __shfl_xor_sync(0xffffffffu, s,  off);
        sq += __shfl_xor_sync(0xffffffffu, sq, off);
    }
    __shared__ float rs[8], rq[8];
    const int wid = tid >> 5, lane = tid & 31;
    if (lane == 0) { rs[wid] = s; rq[wid] = sq; }
    __syncthreads();
    float S = 0.f, SQ = 0.f;
#pragma unroll
    for (int w = 0; w < 8; w++) { S += rs[w]; SQ += rq[w]; }

    const float mu  = S * (1.0f / DQ);
    const float var = SQ * (1.0f / DQ) - mu * mu;
    const float rstd = rsqrtf(var + 1e-6f);

    float4 g  = ((const float4*)gamma)[tid];
    float4 be = ((const float4*)beta)[tid];
    float4 o;
    o.x = (x0 - mu) * rstd * g.x + be.x;
    o.y = (x1 - mu) * rstd * g.y + be.y;
    o.z = (x2 - mu) * rstd * g.z + be.z;
    o.w = (x3 - mu) * rstd * g.w + be.w;
    ((float4*)(out + row * DQ))[tid] = o;
}

// ---------------- launcher --------------------------------------------------
extern "C" void kernel_launch(void* const* d_in, const int* in_sizes, int n_in,
                              void* d_out, int out_size)
{
    const float* q    = (const float*)d_in[0];
    const float* k    = (const float*)d_in[1];
    const float* v    = (const float*)d_in[2];
    const float* w_q  = (const float*)d_in[3];
    const float* w_k  = (const float*)d_in[4];
    const float* w_v  = (const float*)d_in[5];
    const float* w_fc = (const float*)d_in[6];
    const float* ga   = (const float*)d_in[7];
    const float* be   = (const float*)d_in[8];
    float* out = (float*)d_out;

    float *qh, *kh, *ctx, *fc, *wfc, *attn_fb;
    __nv_bfloat16* vbh;
    cudaGetSymbolAddress((void**)&qh,      g_qh);
    cudaGetSymbolAddress((void**)&kh,      g_kh);
    cudaGetSymbolAddress((void**)&vbh,     g_vbh);
    cudaGetSymbolAddress((void**)&ctx,     g_ctx);
    cudaGetSymbolAddress((void**)&fc,      g_fc);
    cudaGetSymbolAddress((void**)&wfc,     g_wfc);
    cudaGetSymbolAddress((void**)&attn_fb, g_attn_fb);

    float* attn;
    bool write_out = true;
    if ((long)out_size >= OUT_ELEMS + ATTN_ELEMS) {
        attn = out + OUT_ELEMS;
    } else if ((long)out_size == ATTN_ELEMS) {
        attn = out;
        write_out = false;
    } else {
        attn = attn_fb;
    }

    const int STATS_SMEM = 2 * 64 * KSTR * 4;     // 34,816 B
    const int FUSED_SMEM = 106496;                // Kb+Vb+Pb+Pbh
    const int GEMM_SMEM  = 4 * 128 * GSTR * 4;    // 73,728 B
    static bool attr_done = false;
    if (!attr_done) {
        cudaFuncSetAttribute(attn_stats, cudaFuncAttributeMaxDynamicSharedMemorySize, STATS_SMEM);
        cudaFuncSetAttribute(attn_fused, cudaFuncAttributeMaxDynamicSharedMemorySize, FUSED_SMEM);
        cudaFuncSetAttribute(gemm_fc,    cudaFuncAttributeMaxDynamicSharedMemorySize, GEMM_SMEM);
        cudaFuncSetAttribute(gemm_proj3, cudaFuncAttributeMaxDynamicSharedMemorySize, GEMM_SMEM);
        attr_done = true;
    }

    // pre-round w_fc to tf32
    round_wfc<<<DQ * DQ / 1024, 256>>>(w_fc, wfc);

    // projections (merged): Q,K -> tf32 [z][s][64]; V -> bf16 [z][d][s]
    Proj3 p;
    p.A0 = q;  p.A1 = k;  p.A2 = v;
    p.B0 = w_q; p.B1 = w_k; p.B2 = w_v;
    p.C0 = qh; p.C1 = kh; p.C2 = (float*)vbh;
    gemm_proj3<<<dim3(8, 64, 3), 256, GEMM_SMEM>>>(p, MROWS, DQ, DQ);

    attn_stats<<<dim3(16, 64), 256, STATS_SMEM>>>(qh, kh);
    attn_fused<<<dim3(16, 64), 256, FUSED_SMEM>>>(qh, kh, vbh, attn, ctx);

    if (write_out) {
        gemm_fc<<<dim3(8, 64, 1), 256, GEMM_SMEM>>>(ctx, wfc, fc, MROWS, DQ, DQ, 1.0f);
        add_ln_kernel<<<MROWS, 256>>>(fc, q, ga, be, out);
    }
}

// round 15
// speedup vs baseline: 1.8030x; 1.1748x over previous
#include <cuda_runtime.h>
#include <cuda_bf16.h>
#include <cuda_fp16.h>

// Problem constants
#define NHEAD 16
#define DQ    1024
#define DKEY  64
#define BATCH 4
#define SEQ   2048
#define MROWS (BATCH * SEQ)          // 8192
#define OUT_ELEMS  (8192L * 1024L)           // 8,388,608
#define ATTN_ELEMS (64L * 2048L * 2048L)     // 268,435,456

// ---------------- scratch ---------------------------------------------------
__device__ __half g_qh[MROWS * DQ];          // [z][s][64]  fp16
__device__ __half g_kh[MROWS * DQ];          // [z][s][64]  fp16
__device__ __nv_bfloat16 g_vbh[MROWS * DQ];  // TRANSPOSED [z][d][s], bf16
__device__ float g_ctx[MROWS * DQ];    // [B,S,H*64], tf32-rounded
__device__ float g_fc[MROWS * DQ];
__device__ float g_wfc[DQ * DQ];       // tf32-rounded copy of w_fc
__device__ float g_rowl[64 * SEQ];     // per-row 1/sumexp
__device__ float g_attn_fb[ATTN_ELEMS];

// ---------------- helpers ----------------------------------------------------
__device__ __forceinline__ unsigned f2tf32(float x) {
    unsigned r;
    asm("cvt.rna.tf32.f32 %0, %1;" : "=r"(r) : "f"(x));
    return r;
}
__device__ __forceinline__ float rnd(float x) { return __uint_as_float(f2tf32(x)); }
__device__ __forceinline__ unsigned cvtu(unsigned x) {
    return f2tf32(__uint_as_float(x));
}
__device__ __forceinline__ unsigned pack_bf16(float lo, float hi) {
    unsigned d;
    asm("cvt.rn.bf16x2.f32 %0, %1, %2;" : "=r"(d) : "f"(hi), "f"(lo));
    return d;
}
__device__ __forceinline__ unsigned pack_f16(float lo, float hi) {
    unsigned d;
    asm("cvt.rn.f16x2.f32 %0, %1, %2;" : "=r"(d) : "f"(hi), "f"(lo));
    return d;
}

__device__ __forceinline__ void mma_tf32(float c[4],
                                         unsigned a0, unsigned a1, unsigned a2, unsigned a3,
                                         unsigned b0, unsigned b1) {
    asm volatile(
        "mma.sync.aligned.m16n8k8.row.col.f32.tf32.tf32.f32 "
        "{%0,%1,%2,%3}, {%4,%5,%6,%7}, {%8,%9}, {%0,%1,%2,%3};"
        : "+f"(c[0]), "+f"(c[1]), "+f"(c[2]), "+f"(c[3])
        : "r"(a0), "r"(a1), "r"(a2), "r"(a3), "r"(b0), "r"(b1));
}

__device__ __forceinline__ void mma_f16(float c[4],
                                        unsigned a0, unsigned a1, unsigned a2, unsigned a3,
                                        unsigned b0, unsigned b1) {
    asm volatile(
        "mma.sync.aligned.m16n8k16.row.col.f32.f16.f16.f32 "
        "{%0,%1,%2,%3}, {%4,%5,%6,%7}, {%8,%9}, {%0,%1,%2,%3};"
        : "+f"(c[0]), "+f"(c[1]), "+f"(c[2]), "+f"(c[3])
        : "r"(a0), "r"(a1), "r"(a2), "r"(a3), "r"(b0), "r"(b1));
}

__device__ __forceinline__ void mma_bf16(float c[4],
                                         unsigned a0, unsigned a1, unsigned a2, unsigned a3,
                                         unsigned b0, unsigned b1) {
    asm volatile(
        "mma.sync.aligned.m16n8k16.row.col.f32.bf16.bf16.f32 "
        "{%0,%1,%2,%3}, {%4,%5,%6,%7}, {%8,%9}, {%0,%1,%2,%3};"
        : "+f"(c[0]), "+f"(c[1]), "+f"(c[2]), "+f"(c[3])
        : "r"(a0), "r"(a1), "r"(a2), "r"(a3), "r"(b0), "r"(b1));
}

__device__ __forceinline__ void ldsm4(unsigned& r0, unsigned& r1,
                                      unsigned& r2, unsigned& r3, unsigned addr) {
    asm volatile("ldmatrix.sync.aligned.m8n8.x4.shared.b16 {%0,%1,%2,%3}, [%4];"
                 : "=r"(r0), "=r"(r1), "=r"(r2), "=r"(r3) : "r"(addr));
}

__device__ __forceinline__ void cp16(void* smem_dst, const void* gsrc) {
    unsigned saddr = (unsigned)__cvta_generic_to_shared(smem_dst);
    asm volatile("cp.async.cg.shared.global [%0], [%1], 16;" :: "r"(saddr), "l"(gsrc));
}
#define CP_COMMIT() asm volatile("cp.async.commit_group;")
#define CP_WAIT(n)  asm volatile("cp.async.wait_group %0;" :: "n"(n) : "memory")

#define KSTR 68          // fp32 smem stride (floats) for P tile
#define BSTRB 144        // 16-bit tile smem row stride in BYTES — conflict-free
#define GSTR 36          // gemm smem stride
#define NCH  (SEQ / 64)
#define CHB  (64 * BSTRB)   // bytes per 64-row 16-bit chunk buffer (9216)

// Q fragments for m16n8k16.f16: values in gmem fp16 [s][64]
__device__ __forceinline__ void load_qfrag(unsigned aq[4][4], const __half* Qz,
                                           int row0, int t)
{
    const unsigned* Q0 = (const unsigned*)(Qz + (long)row0 * 64);  // 32 u32/row
    const unsigned* Q1 = Q0 + 8 * 32;
#pragma unroll
    for (int kk = 0; kk < 4; kk++) {
        aq[kk][0] = Q0[kk * 8 + t];
        aq[kk][1] = Q1[kk * 8 + t];
        aq[kk][2] = Q0[kk * 8 + 4 + t];
        aq[kk][3] = Q1[kk * 8 + 4 + t];
    }
}

// 64x64 16-bit chunk (gmem row stride `gstride` elems) -> [64][BSTRB] smem
template <typename T>
__device__ __forceinline__ void cp_chunk_h(char* dst, const T* src,
                                           long gstride, int tid)
{
#pragma unroll
    for (int i = 0; i < 2; i++) {
        const int idx = tid + i * 256;
        const int r = idx >> 3, c8 = (idx & 7);
        cp16(dst + r * BSTRB + c8 * 16, src + (long)r * gstride + c8 * 8);
    }
}

__device__ __forceinline__ unsigned ldsm_lane_off(int lane, int stride)
{
    return (unsigned)((((lane >> 4) * 8 + (lane & 7)) * stride) * 4
                      + 16 * ((lane >> 3) & 1));
}
__device__ __forceinline__ unsigned ldsm_lane_off_bytes(int lane, int strideB)
{
    return (unsigned)(((lane >> 4) * 8 + (lane & 7)) * strideB
                      + 16 * ((lane >> 3) & 1));
}
__device__ __forceinline__ unsigned ldsm_lane_off_A(int lane, int stride)
{
    return (unsigned)((((lane & 7) + 8 * ((lane >> 3) & 1)) * stride) * 4
                      + 16 * (lane >> 4));
}
__device__ __forceinline__ unsigned ldsm_lane_off_A_bytes(int lane, int strideB)
{
    return (unsigned)(((lane & 7) + 8 * ((lane >> 3) & 1)) * strideB
                      + 16 * (lane >> 4));
}

// ---------------- pass 1: softmax row sums (fp16 S) -------------------------
__global__ __launch_bounds__(256, 2)
void attn_stats(const __half* __restrict__ qh, const __half* __restrict__ kh)
{
    extern __shared__ char smemc[];
    char* Kb = smemc;                  // [2][64][BSTRB] fp16

    const int z  = blockIdx.y;
    const int qb = blockIdx.x * 128;
    const __half* Kz = kh + (long)z * SEQ * 64;

    const int tid = threadIdx.x;
    const int warp = tid >> 5, lane = tid & 31;
    const int wm = warp * 16;
    const int g = lane >> 2, t = lane & 3;
    const int row0 = qb + wm + g;

    unsigned aq[4][4];
    load_qfrag(aq, qh + (long)z * SEQ * 64, row0, t);

    const unsigned kLane = (unsigned)__cvta_generic_to_shared(Kb)
                         + ldsm_lane_off_bytes(lane, BSTRB);

    const float scale = 0.125f;
    float l0 = 0.f, l1 = 0.f;

    cp_chunk_h(Kb, Kz, 64, tid);
    CP_COMMIT();

    for (int ch = 0; ch < NCH; ch++) {
        if (ch + 1 < NCH) {
            cp_chunk_h(Kb + ((ch + 1) & 1) * CHB,
                       Kz + (long)(ch + 1) * 64 * 64, 64, tid);
            CP_COMMIT();
            CP_WAIT(1);
        } else {
            CP_WAIT(0);
        }
        __syncthreads();

        const unsigned kBuf = kLane + (unsigned)((ch & 1) * CHB);

        float sacc[8][4];
#pragma unroll
        for (int j = 0; j < 8; j++)
#pragma unroll
            for (int r = 0; r < 4; r++) sacc[j][r] = 0.f;

#pragma unroll
        for (int kk = 0; kk < 4; kk++) {
#pragma unroll
            for (int jp = 0; jp < 4; jp++) {
                unsigned r0, r1, r2, r3;
                ldsm4(r0, r1, r2, r3,
                      kBuf + (unsigned)(jp * 16 * BSTRB + kk * 32));
                mma_f16(sacc[2 * jp],     aq[kk][0], aq[kk][1], aq[kk][2], aq[kk][3], r0, r1);
                mma_f16(sacc[2 * jp + 1], aq[kk][0], aq[kk][1], aq[kk][2], aq[kk][3], r2, r3);
            }
        }

        float s0 = 0.f, s1 = 0.f;
#pragma unroll
        for (int j = 0; j < 8; j++) {
            s0 += __expf(sacc[j][0] * scale) + __expf(sacc[j][1] * scale);
            s1 += __expf(sacc[j][2] * scale) + __expf(sacc[j][3] * scale);
        }
        l0 += s0;
        l1 += s1;
        __syncthreads();
    }

    l0 += __shfl_xor_sync(0xffffffffu, l0, 1);
    l0 += __shfl_xor_sync(0xffffffffu, l0, 2);
    l1 += __shfl_xor_sync(0xffffffffu, l1, 1);
    l1 += __shfl_xor_sync(0xffffffffu, l1, 2);

    if (t == 0) {
        const long base = (long)z * SEQ + qb + wm;
        g_rowl[base + g]     = 1.0f / l0;
        g_rowl[base + g + 8] = 1.0f / l1;
    }
}

// ---------------- pass 2: fused P write + P·V (fp16 S, bf16 PV) -------------
__global__ __launch_bounds__(256, 2)
void attn_fused(const __half* __restrict__ qh, const __half* __restrict__ kh,
                const __nv_bfloat16* __restrict__ vt, float* __restrict__ attn,
                float* __restrict__ ctx)
{
    extern __shared__ char smemc[];
    char*  Kb  = smemc;                     // [2][64][BSTRB] fp16  18,432 B
    char*  Vb  = smemc + 18432;             // [2][64][BSTRB] bf16  18,432 B
    float* Pb  = (float*)(smemc + 36864);   // [128][KSTR] fp32     34,816 B
    char*  Pbh = smemc + 71680;             // [128][BSTRB] bf16    18,432 B

    const int z  = blockIdx.y;
    const int b  = z >> 4, h = z & 15;
    const int qb = blockIdx.x * 128;
    const __half* Kz = kh + (long)z * SEQ * 64;
    const __nv_bfloat16* Vtz = vt + (long)z * SEQ * 64;   // [64 d][2048 s]
    float* attnZ = attn + (long)z * SEQ * SEQ;

    const int tid  = threadIdx.x;
    const int warp = tid >> 5, lane = tid & 31;
    const int wm = warp * 16;
    const int g = lane >> 2, t = lane & 3;
    const int row0 = qb + wm + g, row1 = row0 + 8;

    unsigned aq[4][4];
    load_qfrag(aq, qh + (long)z * SEQ * 64, row0, t);

    const long sbase = (long)z * SEQ;
    const float iv0 = g_rowl[sbase + row0];
    const float iv1 = g_rowl[sbase + row1];
    const float scale = 0.125f;

    const unsigned kLane  = (unsigned)__cvta_generic_to_shared(Kb) + ldsm_lane_off_bytes(lane, BSTRB);
    const unsigned vLane  = (unsigned)__cvta_generic_to_shared(Vb) + ldsm_lane_off_bytes(lane, BSTRB);
    const unsigned pbLane = (unsigned)__cvta_generic_to_shared(Pbh) + ldsm_lane_off_A_bytes(lane, BSTRB);

    // copy-out lane mapping: half-warp per row, full 64 cols (2x128B wavefronts)
    const int cr = lane >> 4;            // 0..1
    const int cc = (lane & 15) * 4;      // 0..60

    float oacc[8][4];
#pragma unroll
    for (int j = 0; j < 8; j++)
#pragma unroll
        for (int r = 0; r < 4; r++) oacc[j][r] = 0.f;

    cp_chunk_h(Kb, Kz, 64, tid);        CP_COMMIT();
    cp_chunk_h(Vb, Vtz, SEQ, tid);      CP_COMMIT();

    for (int ch = 0; ch < NCH; ch++) {
        if (ch + 1 < NCH) {
            const int st = (ch + 1) & 1;
            cp_chunk_h(Kb + st * CHB, Kz + (long)(ch + 1) * 64 * 64, 64, tid);
            CP_COMMIT();
            cp_chunk_h(Vb + st * CHB, Vtz + (long)(ch + 1) * 64, SEQ, tid);
            CP_COMMIT();
            CP_WAIT(2);
        } else {
            CP_WAIT(0);
        }
        __syncthreads();

        const unsigned kBuf = kLane + (unsigned)((ch & 1) * CHB);
        const unsigned vBuf = vLane + (unsigned)((ch & 1) * CHB);

        // ---- S = Q K^T (fp16, fp32 accum) for this 128x64 chunk ----
        float sacc[8][4];
#pragma unroll
        for (int j = 0; j < 8; j++)
#pragma unroll
            for (int r = 0; r < 4; r++) sacc[j][r] = 0.f;

#pragma unroll
        for (int kk = 0; kk < 4; kk++) {
#pragma unroll
            for (int jp = 0; jp < 4; jp++) {
                unsigned r0, r1, r2, r3;
                ldsm4(r0, r1, r2, r3,
                      kBuf + (unsigned)(jp * 16 * BSTRB + kk * 32));
                mma_f16(sacc[2 * jp],     aq[kk][0], aq[kk][1], aq[kk][2], aq[kk][3], r0, r1);
                mma_f16(sacc[2 * jp + 1], aq[kk][0], aq[kk][1], aq[kk][2], aq[kk][3], r2, r3);
            }
        }

        // ---- p = exp(s*scale)*inv_l -> fp32 P (copyout) + bf16 P (PV) ------
#pragma unroll
        for (int j = 0; j < 8; j++) {
            float p0 = __expf(sacc[j][0] * scale) * iv0;
            float p1 = __expf(sacc[j][1] * scale) * iv0;
            float p2 = __expf(sacc[j][2] * scale) * iv1;
            float p3 = __expf(sacc[j][3] * scale) * iv1;
            float2 lo; lo.x = p0; lo.y = p1;
            float2 hi; hi.x = p2; hi.y = p3;
            const int c = j * 8 + 2 * t;
            *(float2*)&Pb[(wm + g) * KSTR + c]     = lo;
            *(float2*)&Pb[(wm + g + 8) * KSTR + c] = hi;
            *(unsigned*)(Pbh + (wm + g) * BSTRB + c * 2)     = pack_bf16(p0, p1);
            *(unsigned*)(Pbh + (wm + g + 8) * BSTRB + c * 2) = pack_bf16(p2, p3);
        }
        __syncwarp();

        // ---- PV (bf16 m16n8k16): A from Pbh, B from V^T ----
#pragma unroll
        for (int j16 = 0; j16 < 4; j16++) {
            unsigned a0, a1, a2, a3;
            ldsm4(a0, a1, a2, a3, pbLane + (unsigned)(wm * BSTRB + j16 * 32));
#pragma unroll
            for (int jdp = 0; jdp < 4; jdp++) {
                unsigned r0, r1, r2, r3;
                ldsm4(r0, r1, r2, r3,
                      vBuf + (unsigned)(jdp * 16 * BSTRB + j16 * 32));
                mma_bf16(oacc[2 * jdp],     a0, a1, a2, a3, r0, r1);
                mma_bf16(oacc[2 * jdp + 1], a0, a1, a2, a3, r2, r3);
            }
        }

        // ---- copy P tile to attn: 8 x (2 rows, full 64 cols) per warp ------
#pragma unroll
        for (int i = 0; i < 8; i++) {
            const int r = wm + cr + i * 2;
            float4 v = *(float4*)&Pb[r * KSTR + cc];
            *(float4*)(attnZ + (long)(qb + r) * SEQ + ch * 64 + cc) = v;
        }
        __syncthreads();
    }

    // ---- write O (tf32-rounded: consumed only by gemm_fc) ----
#pragma unroll
    for (int j = 0; j < 8; j++) {
        const int d = j * 8 + 2 * t;
        float2 lo; lo.x = rnd(oacc[j][0]); lo.y = rnd(oacc[j][1]);
        float2 hi; hi.x = rnd(oacc[j][2]); hi.y = rnd(oacc[j][3]);
        *(float2*)(ctx + ((long)(b * SEQ + row0)) * DQ + h * 64 + d) = lo;
        *(float2*)(ctx + ((long)(b * SEQ + row1)) * DQ + h * 64 + d) = hi;
    }
}

// ---------------- pipelined tensor-core GEMM-NT body ------------------------
// MODE 0: C row-major fp32.  MODE 1: scatter [z][s][64] fp16.  MODE 2: scatter [z][d][s] bf16.
template <int MODE, bool CVT, bool RND>
__device__ __forceinline__
void gemm_body(const float* __restrict__ A, const float* __restrict__ Bm,
               float* __restrict__ C, int M, int N, int K, float alpha,
               unsigned* smem)
{
    constexpr int BM = 128, BN = 128, BK = 32;
    unsigned* As = smem;
    unsigned* Bs = smem + 2 * BM * GSTR;

    const int bm = blockIdx.y * BM;
    const int bn = blockIdx.x * BN;
    const int tid  = threadIdx.x;
    const int warp = tid >> 5, lane = tid & 31;
    const int wm = (warp >> 2) * 64;
    const int wn = (warp & 3) * 32;
    const int g = lane >> 2, t = lane & 3;

    const int lr = tid >> 3;
    const int lc = (tid & 7) * 4;

    const unsigned As_u = (unsigned)__cvta_generic_to_shared(As);
    const unsigned Bs_u = (unsigned)__cvta_generic_to_shared(Bs);
    const unsigned aLane = As_u + ldsm_lane_off_A(lane, GSTR);
    const unsigned bLane = Bs_u + ldsm_lane_off(lane, GSTR);

    float acc[4][4][4];
#pragma unroll
    for (int i = 0; i < 4; i++)
#pragma unroll
        for (int j = 0; j < 4; j++)
#pragma unroll
            for (int r = 0; r < 4; r++) acc[i][j][r] = 0.f;

    const int nt = K / BK;

    {
#pragma unroll
        for (int i = 0; i < 4; i++) {
            const int r = lr + i * 32;
            cp16(&As[r * GSTR + lc], A  + (long)(bm + r) * K + lc);
            cp16(&Bs[r * GSTR + lc], Bm + (long)(bn + r) * K + lc);
        }
        CP_COMMIT();
    }

    for (int kt = 0; kt < nt; kt++) {
        if (kt + 1 < nt) {
            const int st = (kt + 1) & 1;
            const int k0 = (kt + 1) * BK;
            unsigned* Ad = As + st * BM * GSTR;
            unsigned* Bd = Bs + st * BM * GSTR;
#pragma unroll
            for (int i = 0; i < 4; i++) {
                const int r = lr + i * 32;
                cp16(&Ad[r * GSTR + lc], A  + (long)(bm + r) * K + k0 + lc);
                cp16(&Bd[r * GSTR + lc], Bm + (long)(bn + r) * K + k0 + lc);
            }
            CP_COMMIT();
            CP_WAIT(1);
        } else {
            CP_WAIT(0);
        }
        __syncthreads();

        const unsigned bufOff = (unsigned)((kt & 1) * BM * GSTR * 4);
        const unsigned aB = aLane + bufOff;
        const unsigned bB = bLane + bufOff;

#pragma unroll
        for (int kk = 0; kk < BK; kk += 8) {
            unsigned af[4][4], bf[4][2];
#pragma unroll
            for (int i = 0; i < 4; i++) {
                ldsm4(af[i][0], af[i][1], af[i][2], af[i][3],
                      aB + (unsigned)(((wm + i * 16) * GSTR + kk) * 4));
                if (CVT) {
                    af[i][0] = cvtu(af[i][0]); af[i][1] = cvtu(af[i][1]);
                    af[i][2] = cvtu(af[i][2]); af[i][3] = cvtu(af[i][3]);
                }
            }
#pragma unroll
            for (int jp = 0; jp < 2; jp++) {
                unsigned r0, r1, r2, r3;
                ldsm4(r0, r1, r2, r3,
                      bB + (unsigned)(((wn + jp * 16) * GSTR + kk) * 4));
                if (CVT) { r0 = cvtu(r0); r1 = cvtu(r1); r2 = cvtu(r2); r3 = cvtu(r3); }
                bf[2 * jp][0]     = r0;
                bf[2 * jp][1]     = r1;
                bf[2 * jp + 1][0] = r2;
                bf[2 * jp + 1][1] = r3;
            }
#pragma unroll
            for (int i = 0; i < 4; i++)
#pragma unroll
                for (int j = 0; j < 4; j++)
                    mma_tf32(acc[i][j], af[i][0], af[i][1], af[i][2], af[i][3],
                             bf[j][0], bf[j][1]);
        }
        __syncthreads();
    }

#pragma unroll
    for (int i = 0; i < 4; i++) {
#pragma unroll
        for (int j = 0; j < 4; j++) {
            const int mrow = bm + wm + i * 16 + g;
            const int ncol = bn + wn + j * 8 + 2 * t;
            float v0 = alpha * acc[i][j][0], v1 = alpha * acc[i][j][1];
            float v2 = alpha * acc[i][j][2], v3 = alpha * acc[i][j][3];
            if (RND) { v0 = rnd(v0); v1 = rnd(v1); v2 = rnd(v2); v3 = rnd(v3); }
            if (MODE == 0) {
                float2 lo; lo.x = v0; lo.y = v1;
                float2 hi; hi.x = v2; hi.y = v3;
                *(float2*)(C + (long)mrow * N + ncol)       = lo;
                *(float2*)(C + (long)(mrow + 8) * N + ncol) = hi;
            } else if (MODE == 1) {
                // Q/K: fp16 [z][s][64]
                __half* Ch = (__half*)C;
                const int h = ncol >> 6, d = ncol & 63;
                int b0 = mrow >> 11, s0 = mrow & 2047;
                *(unsigned*)(Ch + ((long)((b0 * NHEAD + h) * SEQ + s0)) * 64 + d) = pack_f16(v0, v1);
                int m2 = mrow + 8;
                int b1 = m2 >> 11, s1 = m2 & 2047;
                *(unsigned*)(Ch + ((long)((b1 * NHEAD + h) * SEQ + s1)) * 64 + d) = pack_f16(v2, v3);
            } else {
                // V: bf16 transposed [z][d][s]
                __nv_bfloat16* Cb = (__nv_bfloat16*)C;
                const int h = ncol >> 6, d = ncol & 63;
                int b0 = mrow >> 11, s0 = mrow & 2047;
                __nv_bfloat16* p0 = Cb + ((long)((b0 * NHEAD + h) * 64 + d)) * SEQ + s0;
                p0[0]   = __float2bfloat16(v0);
                p0[SEQ] = __float2bfloat16(v1);
                int m2 = mrow + 8;
                int b1 = m2 >> 11, s1 = m2 & 2047;
                __nv_bfloat16* p1 = Cb + ((long)((b1 * NHEAD + h) * 64 + d)) * SEQ + s1;
                p1[0]   = __float2bfloat16(v2);
                p1[SEQ] = __float2bfloat16(v3);
            }
        }
    }
}

__global__ __launch_bounds__(256, 2)
void gemm_fc(const float* __restrict__ A, const float* __restrict__ Bm,
             float* __restrict__ C, int M, int N, int K, float alpha)
{
    extern __shared__ unsigned smemg[];
    gemm_body<0, false, false>(A, Bm, C, M, N, K, alpha, smemg);
}

struct Proj3 {
    const float *A0, *A1, *A2;
    const float *B0, *B1, *B2;
    float *C0, *C1, *C2;
};

__global__ __launch_bounds__(256, 2)
void gemm_proj3(Proj3 p, int M, int N, int K)
{
    extern __shared__ unsigned smemg[];
    if (blockIdx.z == 0)      gemm_body<1, true, false>(p.A0, p.B0, p.C0, M, N, K, 1.0f, smemg);
    else if (blockIdx.z == 1) gemm_body<1, true, false>(p.A1, p.B1, p.C1, M, N, K, 1.0f, smemg);
    else                      gemm_body<2, true, false>(p.A2, p.B2, p.C2, M, N, K, 1.0f, smemg);
}

// ---------------- w_fc pre-round --------------------------------------------
__global__ __launch_bounds__(256)
void round_wfc(const float* __restrict__ src, float* __restrict__ dst)
{
    const int i = blockIdx.x * 256 + threadIdx.x;
    float4 v = ((const float4*)src)[i];
    v.x = rnd(v.x); v.y = rnd(v.y); v.z = rnd(v.z); v.w = rnd(v.w);
    ((float4*)dst)[i] = v;
}

// ---------------- residual add + LayerNorm ----------------------------------
__global__ __launch_bounds__(256)
void add_ln_kernel(const float* __restrict__ fc, const float* __restrict__ res,
                   const float* __restrict__ gamma, const float* __restrict__ beta,
                   float* __restrict__ out)
{
    const long row = blockIdx.x;
    const int tid = threadIdx.x;
    float4 f = ((const float4*)(fc  + row * DQ))[tid];
    float4 r = ((const float4*)(res + row * DQ))[tid];
    float x0 = f.x + r.x, x1 = f.y + r.y, x2 = f.z + r.z, x3 = f.w + r.w;

    float s  = x0 + x1 + x2 + x3;
    float sq = x0 * x0 + x1 * x1 + x2 * x2 + x3 * x3;
#pragma unroll
    for (int off = 16; off > 0; off >>= 1) {
        s  += __shfl_xor_sync(0xffffffffu, s,  off);
        sq += __shfl_xor_sync(0xffffffffu, sq, off);
    }
    __shared__ float rs[8], rq[8];
    const int wid = tid >> 5, lane = tid & 31;
    if (lane == 0) { rs[wid] = s; rq[wid] = sq; }
    __syncthreads();
    float S = 0.f, SQ = 0.f;
#pragma unroll
    for (int w = 0; w < 8; w++) { S += rs[w]; SQ += rq[w]; }

    const float mu  = S * (1.0f / DQ);
    const float var = SQ * (1.0f / DQ) - mu * mu;
    const float rstd = rsqrtf(var + 1e-6f);

    float4 g  = ((const float4*)gamma)[tid];
    float4 be = ((const float4*)beta)[tid];
    float4 o;
    o.x = (x0 - mu) * rstd * g.x + be.x;
    o.y = (x1 - mu) * rstd * g.y + be.y;
    o.z = (x2 - mu) * rstd * g.z + be.z;
    o.w = (x3 - mu) * rstd * g.w + be.w;
    ((float4*)(out + row * DQ))[tid] = o;
}

// ---------------- launcher --------------------------------------------------
extern "C" void kernel_launch(void* const* d_in, const int* in_sizes, int n_in,
                              void* d_out, int out_size)
{
    const float* q    = (const float*)d_in[0];
    const float* k    = (const float*)d_in[1];
    const float* v    = (const float*)d_in[2];
    const float* w_q  = (const float*)d_in[3];
    const float* w_k  = (const float*)d_in[4];
    const float* w_v  = (const float*)d_in[5];
    const float* w_fc = (const float*)d_in[6];
    const float* ga   = (const float*)d_in[7];
    const float* be   = (const float*)d_in[8];
    float* out = (float*)d_out;

    float *ctx, *fc, *wfc, *attn_fb;
    __half *qh, *kh;
    __nv_bfloat16* vbh;
    cudaGetSymbolAddress((void**)&qh,      g_qh);
    cudaGetSymbolAddress((void**)&kh,      g_kh);
    cudaGetSymbolAddress((void**)&vbh,     g_vbh);
    cudaGetSymbolAddress((void**)&ctx,     g_ctx);
    cudaGetSymbolAddress((void**)&fc,      g_fc);
    cudaGetSymbolAddress((void**)&wfc,     g_wfc);
    cudaGetSymbolAddress((void**)&attn_fb, g_attn_fb);

    float* attn;
    bool write_out = true;
    if ((long)out_size >= OUT_ELEMS + ATTN_ELEMS) {
        attn = out + OUT_ELEMS;
    } else if ((long)out_size == ATTN_ELEMS) {
        attn = out;
        write_out = false;
    } else {
        attn = attn_fb;
    }

    const int STATS_SMEM = 2 * CHB;               // 18,432 B
    const int FUSED_SMEM = 90112;                 // Kb+Vb+Pb+Pbh
    const int GEMM_SMEM  = 4 * 128 * GSTR * 4;    // 73,728 B
    static bool attr_done = false;
    if (!attr_done) {
        cudaFuncSetAttribute(attn_stats, cudaFuncAttributeMaxDynamicSharedMemorySize, STATS_SMEM);
        cudaFuncSetAttribute(attn_fused, cudaFuncAttributeMaxDynamicSharedMemorySize, FUSED_SMEM);
        cudaFuncSetAttribute(gemm_fc,    cudaFuncAttributeMaxDynamicSharedMemorySize, GEMM_SMEM);
        cudaFuncSetAttribute(gemm_proj3, cudaFuncAttributeMaxDynamicSharedMemorySize, GEMM_SMEM);
        attr_done = true;
    }

    // pre-round w_fc to tf32
    round_wfc<<<DQ * DQ / 1024, 256>>>(w_fc, wfc);

    // projections (merged): Q,K -> fp16 [z][s][64]; V -> bf16 [z][d][s]
    Proj3 p;
    p.A0 = q;  p.A1 = k;  p.A2 = v;
    p.B0 = w_q; p.B1 = w_k; p.B2 = w_v;
    p.C0 = (float*)qh; p.C1 = (float*)kh; p.C2 = (float*)vbh;
    gemm_proj3<<<dim3(8, 64, 3), 256, GEMM_SMEM>>>(p, MROWS, DQ, DQ);

    attn_stats<<<dim3(16, 64), 256, STATS_SMEM>>>(qh, kh);
    attn_fused<<<dim3(16, 64), 256, FUSED_SMEM>>>(qh, kh, vbh, attn, ctx);

    if (write_out) {
        gemm_fc<<<dim3(8, 64, 1), 256, GEMM_SMEM>>>(ctx, wfc, fc, MROWS, DQ, DQ, 1.0f);
        add_ln_kernel<<<MROWS, 256>>>(fc, q, ga, be, out);
    }
}